// round 4
// baseline (speedup 1.0000x reference)
#include <cuda_runtime.h>
#include <cuda_bf16.h>
#include <math.h>
#include <stdint.h>

// Problem constants (fixed by this dataset instance)
#define Bsz 2
#define Sq  2048
#define Dm  1024
#define Hn  16
#define Dk  64
#define Mrows (Bsz*Sq)   // 4096

// ---------------- scratch ----------------------------------------------------
__device__ float g_Q[Bsz*Hn*Sq*Dk];   // [B,H,S,Dk]
__device__ float g_K[Bsz*Hn*Sq*Dk];
__device__ float g_V[Bsz*Hn*Sq*Dk];

__device__ __nv_bfloat16 g_xhi[Mrows*Dm], g_xlo[Mrows*Dm];
__device__ __nv_bfloat16 g_wqhi[Dm*Dm], g_wqlo[Dm*Dm];
__device__ __nv_bfloat16 g_wkhi[Dm*Dm], g_wklo[Dm*Dm];
__device__ __nv_bfloat16 g_wvhi[Dm*Dm], g_wvlo[Dm*Dm];
__device__ __nv_bfloat16 g_wohi[Dm*Dm], g_wolo[Dm*Dm];
__device__ __nv_bfloat16 g_Ohi[Mrows*Dm], g_Olo[Mrows*Dm];  // attn out, hi/lo

// ================= small PTX wrappers (portable, compute_103-safe) ===========
__device__ __forceinline__ uint32_t smem_u32(const void* p) {
    uint32_t a;
    asm("{ .reg .u64 t; cvta.to.shared.u64 t, %1; cvt.u32.u64 %0, t; }"
        : "=r"(a) : "l"(p));
    return a;
}
__device__ __forceinline__ void ldsm_x4(uint32_t addr, uint32_t r[4]) {
    asm volatile("ldmatrix.sync.aligned.m8n8.x4.shared.b16 {%0,%1,%2,%3}, [%4];"
                 : "=r"(r[0]), "=r"(r[1]), "=r"(r[2]), "=r"(r[3]) : "r"(addr));
}
__device__ __forceinline__ void ldsm_x2(uint32_t addr, uint32_t r[2]) {
    asm volatile("ldmatrix.sync.aligned.m8n8.x2.shared.b16 {%0,%1}, [%2];"
                 : "=r"(r[0]), "=r"(r[1]) : "r"(addr));
}
__device__ __forceinline__ void mma_bf16(float c[4], const uint32_t a[4],
                                         const uint32_t b[2]) {
    asm volatile(
        "mma.sync.aligned.m16n8k16.row.col.f32.bf16.bf16.f32 "
        "{%0,%1,%2,%3}, {%4,%5,%6,%7}, {%8,%9}, {%0,%1,%2,%3};"
        : "+f"(c[0]), "+f"(c[1]), "+f"(c[2]), "+f"(c[3])
        : "r"(a[0]), "r"(a[1]), "r"(a[2]), "r"(a[3]), "r"(b[0]), "r"(b[1]));
}
__device__ __forceinline__ void cp16(uint32_t smem_addr, const void* gptr) {
    asm volatile("cp.async.cg.shared.global [%0], [%1], 16;"
                 :: "r"(smem_addr), "l"(gptr) : "memory");
}
#define CP_COMMIT() asm volatile("cp.async.commit_group;" ::: "memory")
#define CP_WAIT(n)  asm volatile("cp.async.wait_group %0;" :: "n"(n) : "memory")

__device__ __forceinline__ float bf_round(float x) {
    return __bfloat162float(__float2bfloat16(x));
}

// ================= split pass: fp32 -> bf16 hi/lo =============================
__global__ void __launch_bounds__(256)
split_kernel(const float* __restrict__ src, __nv_bfloat16* __restrict__ hi,
             __nv_bfloat16* __restrict__ lo, int n4)
{
    int i = blockIdx.x * 256 + threadIdx.x;
    if (i >= n4) return;
    float4 v = reinterpret_cast<const float4*>(src)[i];
    __nv_bfloat162 h0 = __floats2bfloat162_rn(v.x, v.y);
    __nv_bfloat162 h1 = __floats2bfloat162_rn(v.z, v.w);
    __nv_bfloat162 l0 = __floats2bfloat162_rn(v.x - bf_round(v.x), v.y - bf_round(v.y));
    __nv_bfloat162 l1 = __floats2bfloat162_rn(v.z - bf_round(v.z), v.w - bf_round(v.w));
    reinterpret_cast<uint2*>(hi)[i] = make_uint2(*(uint32_t*)&h0, *(uint32_t*)&h1);
    reinterpret_cast<uint2*>(lo)[i] = make_uint2(*(uint32_t*)&l0, *(uint32_t*)&l1);
}

// ================= tensor-core GEMM v2: C[m,n] = sum_k A[m,k]*W[n,k] ==========
// Operands pre-split to bf16 hi/lo in gmem. bf16x3: Ahi*Bhi + Alo*Bhi + Ahi*Blo.
#define BM 128
#define BN 128
#define BK 32
#define KT_ITERS (Dm/BK)              // 32
#define TPITCH 80                      // bytes per 32-bf16 row (conflict-free)
#define TILE_BYTES (128*TPITCH)        // 10240
#define STAGE_BYTES (4*TILE_BYTES)     // Ahi|Alo|Bhi|Blo = 40960
#define NSTAGE 3
#define GEMM_SMEM (NSTAGE*STAGE_BYTES) // 122880

template<bool ROPE, bool BHSD>
__global__ void __launch_bounds__(256, 1)
gemm_mma2_kernel(const __nv_bfloat16* __restrict__ Ahi,
                 const __nv_bfloat16* __restrict__ Alo,
                 const __nv_bfloat16* __restrict__ Bhi,
                 const __nv_bfloat16* __restrict__ Blo,
                 float* __restrict__ C, const int* __restrict__ pos)
{
    extern __shared__ char sm[];
    const uint32_t sbase = smem_u32(sm);

    const int tid  = threadIdx.x;
    const int lane = tid & 31;
    const int wid  = tid >> 5;
    const int warp_m = wid & 1;
    const int warp_n = wid >> 1;
    const int n0 = blockIdx.x * BN;
    const int m0 = blockIdx.y * BM;

    // producer mapping: 2 chunks per tile per thread (512 16B-chunks per tile)
    const int r0a = tid >> 2;          // chunk0 row   (c = tid)
    const int c0  = tid & 3;           // chunk0 col16
    const int r1a = (tid + 256) >> 2;  // chunk1 row
    // c1 == c0

    const __nv_bfloat16* gsrc[4] = {Ahi, Alo, Bhi, Blo};

    auto issue_stage = [&](int stage, int kt) {
        const int kc = kt * BK;
        const uint32_t sb = sbase + stage * STAGE_BYTES;
        #pragma unroll
        for (int t = 0; t < 4; t++) {
            const int row0 = (t < 2) ? m0 : n0;
            const __nv_bfloat16* g = gsrc[t];
            cp16(sb + t * TILE_BYTES + (uint32_t)(r0a * TPITCH + c0 * 16),
                 g + (size_t)(row0 + r0a) * Dm + kc + c0 * 8);
            cp16(sb + t * TILE_BYTES + (uint32_t)(r1a * TPITCH + c0 * 16),
                 g + (size_t)(row0 + r1a) * Dm + kc + c0 * 8);
        }
    };

    float acc[4][4][4];
    #pragma unroll
    for (int i = 0; i < 4; i++)
        #pragma unroll
        for (int j = 0; j < 4; j++)
            #pragma unroll
            for (int v = 0; v < 4; v++) acc[i][j][v] = 0.f;

    issue_stage(0, 0); CP_COMMIT();
    issue_stage(1, 1); CP_COMMIT();
    CP_WAIT(1);
    __syncthreads();

    for (int kt = 0; kt < KT_ITERS; kt++) {
        const uint32_t sb = sbase + (kt % NSTAGE) * STAGE_BYTES;
        const uint32_t sAhi = sb;
        const uint32_t sAlo = sb + TILE_BYTES;
        const uint32_t sBhi = sb + 2 * TILE_BYTES;
        const uint32_t sBlo = sb + 3 * TILE_BYTES;

        #pragma unroll
        for (int ks = 0; ks < 2; ks++) {
            const int chunk = ks * 2;
            uint32_t ahi[4][4], alo[4][4], bhi[4][2], blo[4][2];
            #pragma unroll
            for (int mt = 0; mt < 4; mt++) {
                const int arow = warp_m * 64 + mt * 16 + (lane & 15);
                const uint32_t aoff = (uint32_t)(arow * TPITCH + (chunk + (lane >> 4)) * 16);
                ldsm_x4(sAhi + aoff, ahi[mt]);
                ldsm_x4(sAlo + aoff, alo[mt]);
            }
            #pragma unroll
            for (int nt = 0; nt < 4; nt++) {
                const int brow = warp_n * 32 + nt * 8 + (lane & 7);
                const uint32_t boff = (uint32_t)(brow * TPITCH + (chunk + ((lane >> 3) & 1)) * 16);
                ldsm_x2(sBhi + boff, bhi[nt]);
                ldsm_x2(sBlo + boff, blo[nt]);
            }
            #pragma unroll
            for (int mt = 0; mt < 4; mt++)
                #pragma unroll
                for (int nt = 0; nt < 4; nt++) {
                    mma_bf16(acc[mt][nt], ahi[mt], bhi[nt]);
                    mma_bf16(acc[mt][nt], alo[mt], bhi[nt]);
                    mma_bf16(acc[mt][nt], ahi[mt], blo[nt]);
                }
        }
        __syncthreads();   // all warps done reading stage kt%3

        if (kt + 2 < KT_ITERS) { issue_stage((kt + 2) % NSTAGE, kt + 2); CP_COMMIT(); }
        if (kt + 1 < KT_ITERS) {
            if (kt + 2 < KT_ITERS) { CP_WAIT(1); } else { CP_WAIT(0); }
            __syncthreads();
        }
    }

    // ---- epilogue: fused RoPE + layout store ---------------------------------
    #pragma unroll
    for (int mt = 0; mt < 4; mt++) {
        #pragma unroll
        for (int half = 0; half < 2; half++) {
            const int row = m0 + warp_m * 64 + mt * 16 + (lane >> 2) + half * 8;
            const int b = row >> 11;
            const int s = row & (Sq - 1);
            float p = 0.f;
            if (ROPE) p = (float)pos[row];
            #pragma unroll
            for (int nt = 0; nt < 4; nt++) {
                const int col = n0 + warp_n * 32 + nt * 8 + (lane & 3) * 2;  // even
                float e = acc[mt][nt][half * 2];
                float o = acc[mt][nt][half * 2 + 1];
                if (ROPE) {
                    const int dk = col & (Dk - 1);
                    const float inv = exp2f((float)dk * (-13.287712379549449f / 64.0f));
                    float sn, cs;
                    sincosf(p * inv, &sn, &cs);
                    const float re = e * cs - o * sn;
                    const float ro = e * sn + o * cs;
                    e = re; o = ro;
                }
                if (BHSD) {
                    const int h  = col >> 6;
                    const int dk = col & (Dk - 1);
                    float* dst = C + (((size_t)(b * Hn + h) * Sq + s) * Dk + dk);
                    *reinterpret_cast<float2*>(dst) = make_float2(e, o);
                } else {
                    float* dst = C + (size_t)row * Dm + col;
                    *reinterpret_cast<float2*>(dst) = make_float2(e, o);
                }
            }
        }
    }
}

// ---------------- causal flash attention, fp32, 1 query per thread ----------
// Epilogue emits hi/lo bf16 split directly (feeds the Wo GEMM).
__global__ void __launch_bounds__(128)
attn_kernel(const float* __restrict__ Q, const float* __restrict__ K,
            const float* __restrict__ V,
            __nv_bfloat16* __restrict__ Ohi, __nv_bfloat16* __restrict__ Olo)
{
    __shared__ float Ks[16][Dk];
    __shared__ float Vs[16][Dk];

    const int bh  = blockIdx.y;
    const int q0  = blockIdx.x * 128;
    const int tid = threadIdx.x;
    const int i   = q0 + tid;

    const float* __restrict__ Kbase = K + (size_t)bh * Sq * Dk;
    const float* __restrict__ Vbase = V + (size_t)bh * Sq * Dk;
    const float* __restrict__ Qrow  = Q + (size_t)bh * Sq * Dk + (size_t)i * Dk;

    float q[Dk];
    #pragma unroll
    for (int d = 0; d < Dk; d += 4) {
        float4 v = *reinterpret_cast<const float4*>(Qrow + d);
        q[d] = v.x; q[d+1] = v.y; q[d+2] = v.z; q[d+3] = v.w;
    }

    float acc[Dk];
    #pragma unroll
    for (int d = 0; d < Dk; d++) acc[d] = 0.f;
    float mi = -1e30f, li = 0.f;

    const float scale = 0.125f;
    const int ktiles = (q0 + 128) >> 4;

    for (int kt = 0; kt < ktiles; kt++) {
        const int k0 = kt << 4;
        __syncthreads();
        #pragma unroll
        for (int u = 0; u < 2; u++) {
            int e = tid + u * 128;
            int r = e >> 4;
            int c = (e & 15) << 2;
            *reinterpret_cast<float4*>(&Ks[r][c]) =
                *reinterpret_cast<const float4*>(Kbase + (size_t)(k0 + r) * Dk + c);
            *reinterpret_cast<float4*>(&Vs[r][c]) =
                *reinterpret_cast<const float4*>(Vbase + (size_t)(k0 + r) * Dk + c);
        }
        __syncthreads();

        if (k0 > i) continue;

        float s[16];
        #pragma unroll
        for (int jj = 0; jj < 16; jj++) {
            float dp = 0.f;
            #pragma unroll
            for (int d = 0; d < Dk; d++) dp = fmaf(q[d], Ks[jj][d], dp);
            s[jj] = (k0 + jj <= i) ? dp * scale : -1e30f;
        }
        float tmax = -1e30f;
        #pragma unroll
        for (int jj = 0; jj < 16; jj++) tmax = fmaxf(tmax, s[jj]);
        const float mnew = fmaxf(mi, tmax);
        const float corr = __expf(mi - mnew);
        li *= corr;
        #pragma unroll
        for (int d = 0; d < Dk; d++) acc[d] *= corr;
        #pragma unroll
        for (int jj = 0; jj < 16; jj++) {
            const float pj = __expf(s[jj] - mnew);
            li += pj;
            #pragma unroll
            for (int d = 0; d < Dk; d++) acc[d] = fmaf(pj, Vs[jj][d], acc[d]);
        }
        mi = mnew;
    }

    const int b = bh >> 4, h = bh & 15;
    const float inv = 1.0f / li;
    const size_t obase = ((size_t)b * Sq + i) * Dm + h * Dk;
    #pragma unroll
    for (int d = 0; d < Dk; d += 2) {
        const float v0 = acc[d] * inv, v1 = acc[d + 1] * inv;
        __nv_bfloat162 h2 = __floats2bfloat162_rn(v0, v1);
        __nv_bfloat162 l2 = __floats2bfloat162_rn(v0 - bf_round(v0), v1 - bf_round(v1));
        *reinterpret_cast<uint32_t*>(Ohi + obase + d) = *(uint32_t*)&h2;
        *reinterpret_cast<uint32_t*>(Olo + obase + d) = *(uint32_t*)&l2;
    }
}

// ---------------- launch -----------------------------------------------------
extern "C" void kernel_launch(void* const* d_in, const int* in_sizes, int n_in,
                              void* d_out, int out_size)
{
    const float* x   = (const float*)d_in[0];
    const float* Wq  = (const float*)d_in[1];
    const float* Wk  = (const float*)d_in[2];
    const float* Wv  = (const float*)d_in[3];
    const float* Wo  = (const float*)d_in[4];
    const int*   pos = (const int*)d_in[5];
    float* out = (float*)d_out;

    float *Qp, *Kp, *Vp;
    cudaGetSymbolAddress((void**)&Qp, g_Q);
    cudaGetSymbolAddress((void**)&Kp, g_K);
    cudaGetSymbolAddress((void**)&Vp, g_V);

    __nv_bfloat16 *xhi, *xlo, *wqhi, *wqlo, *wkhi, *wklo, *wvhi, *wvlo, *wohi, *wolo, *ohi, *olo;
    cudaGetSymbolAddress((void**)&xhi,  g_xhi);  cudaGetSymbolAddress((void**)&xlo,  g_xlo);
    cudaGetSymbolAddress((void**)&wqhi, g_wqhi); cudaGetSymbolAddress((void**)&wqlo, g_wqlo);
    cudaGetSymbolAddress((void**)&wkhi, g_wkhi); cudaGetSymbolAddress((void**)&wklo, g_wklo);
    cudaGetSymbolAddress((void**)&wvhi, g_wvhi); cudaGetSymbolAddress((void**)&wvlo, g_wvlo);
    cudaGetSymbolAddress((void**)&wohi, g_wohi); cudaGetSymbolAddress((void**)&wolo, g_wolo);
    cudaGetSymbolAddress((void**)&ohi,  g_Ohi);  cudaGetSymbolAddress((void**)&olo,  g_Olo);

    cudaFuncSetAttribute(gemm_mma2_kernel<true,  true >,
                         cudaFuncAttributeMaxDynamicSharedMemorySize, GEMM_SMEM);
    cudaFuncSetAttribute(gemm_mma2_kernel<false, true >,
                         cudaFuncAttributeMaxDynamicSharedMemorySize, GEMM_SMEM);
    cudaFuncSetAttribute(gemm_mma2_kernel<false, false>,
                         cudaFuncAttributeMaxDynamicSharedMemorySize, GEMM_SMEM);

    // split passes
    const int nx4 = Mrows * Dm / 4;   // 1048576
    const int nw4 = Dm * Dm / 4;      // 262144
    split_kernel<<<nx4 / 256, 256>>>(x,  xhi,  xlo,  nx4);
    split_kernel<<<nw4 / 256, 256>>>(Wq, wqhi, wqlo, nw4);
    split_kernel<<<nw4 / 256, 256>>>(Wk, wkhi, wklo, nw4);
    split_kernel<<<nw4 / 256, 256>>>(Wv, wvhi, wvlo, nw4);
    split_kernel<<<nw4 / 256, 256>>>(Wo, wohi, wolo, nw4);

    dim3 ggrid(Dm / BN, Mrows / BM);   // (8, 32)
    gemm_mma2_kernel<true,  true ><<<ggrid, 256, GEMM_SMEM>>>(xhi, xlo, wqhi, wqlo, Qp, pos);
    gemm_mma2_kernel<true,  true ><<<ggrid, 256, GEMM_SMEM>>>(xhi, xlo, wkhi, wklo, Kp, pos);
    gemm_mma2_kernel<false, true ><<<ggrid, 256, GEMM_SMEM>>>(xhi, xlo, wvhi, wvlo, Vp, pos);

    dim3 agrid(Sq / 128, Bsz * Hn);    // (16, 32)
    attn_kernel<<<agrid, 128>>>(Qp, Kp, Vp, ohi, olo);

    gemm_mma2_kernel<false, false><<<ggrid, 256, GEMM_SMEM>>>(ohi, olo, wohi, wolo, out, pos);
}

// round 5
// speedup vs baseline: 2.7747x; 2.7747x over previous
#include <cuda_runtime.h>
#include <cuda_bf16.h>
#include <math.h>
#include <stdint.h>

// Problem constants (fixed by this dataset instance)
#define Bsz 2
#define Sq  2048
#define Dm  1024
#define Hn  16
#define Dk  64
#define Mrows (Bsz*Sq)   // 4096

// ---------------- scratch ----------------------------------------------------
__device__ __nv_bfloat16 g_xhi[Mrows*Dm], g_xlo[Mrows*Dm];
__device__ __nv_bfloat16 g_wqhi[Dm*Dm], g_wqlo[Dm*Dm];
__device__ __nv_bfloat16 g_wkhi[Dm*Dm], g_wklo[Dm*Dm];
__device__ __nv_bfloat16 g_wvhi[Dm*Dm], g_wvlo[Dm*Dm];
__device__ __nv_bfloat16 g_wohi[Dm*Dm], g_wolo[Dm*Dm];
__device__ __nv_bfloat16 g_Qhi[Mrows*Dm], g_Qlo[Mrows*Dm];   // [B,H,S,Dk]
__device__ __nv_bfloat16 g_Khi[Mrows*Dm], g_Klo[Mrows*Dm];
__device__ __nv_bfloat16 g_Vhi[Mrows*Dm], g_Vlo[Mrows*Dm];
__device__ __nv_bfloat16 g_Ohi[Mrows*Dm], g_Olo[Mrows*Dm];   // [B,S,D]

// ================= small PTX wrappers (portable, compute_103-safe) ===========
__device__ __forceinline__ uint32_t smem_u32(const void* p) {
    uint32_t a;
    asm("{ .reg .u64 t; cvta.to.shared.u64 t, %1; cvt.u32.u64 %0, t; }"
        : "=r"(a) : "l"(p));
    return a;
}
__device__ __forceinline__ void ldsm_x4(uint32_t addr, uint32_t r[4]) {
    asm volatile("ldmatrix.sync.aligned.m8n8.x4.shared.b16 {%0,%1,%2,%3}, [%4];"
                 : "=r"(r[0]), "=r"(r[1]), "=r"(r[2]), "=r"(r[3]) : "r"(addr));
}
__device__ __forceinline__ void ldsm_x2(uint32_t addr, uint32_t r[2]) {
    asm volatile("ldmatrix.sync.aligned.m8n8.x2.shared.b16 {%0,%1}, [%2];"
                 : "=r"(r[0]), "=r"(r[1]) : "r"(addr));
}
__device__ __forceinline__ void ldsm_x2t(uint32_t addr, uint32_t r[2]) {
    asm volatile("ldmatrix.sync.aligned.m8n8.x2.trans.shared.b16 {%0,%1}, [%2];"
                 : "=r"(r[0]), "=r"(r[1]) : "r"(addr));
}
__device__ __forceinline__ void mma_bf16(float c[4], const uint32_t a[4],
                                         const uint32_t b[2]) {
    asm volatile(
        "mma.sync.aligned.m16n8k16.row.col.f32.bf16.bf16.f32 "
        "{%0,%1,%2,%3}, {%4,%5,%6,%7}, {%8,%9}, {%0,%1,%2,%3};"
        : "+f"(c[0]), "+f"(c[1]), "+f"(c[2]), "+f"(c[3])
        : "r"(a[0]), "r"(a[1]), "r"(a[2]), "r"(a[3]), "r"(b[0]), "r"(b[1]));
}
__device__ __forceinline__ void cp16(uint32_t smem_addr, const void* gptr) {
    asm volatile("cp.async.cg.shared.global [%0], [%1], 16;"
                 :: "r"(smem_addr), "l"(gptr) : "memory");
}
#define CP_COMMIT() asm volatile("cp.async.commit_group;" ::: "memory")
#define CP_WAIT(n)  asm volatile("cp.async.wait_group %0;" :: "n"(n) : "memory")

__device__ __forceinline__ float bf_round(float x) {
    return __bfloat162float(__float2bfloat16(x));
}
__device__ __forceinline__ uint32_t pack_bf2(float x, float y) {
    __nv_bfloat162 t = __floats2bfloat162_rn(x, y);
    return *reinterpret_cast<uint32_t*>(&t);
}

// ================= split pass: fp32 -> bf16 hi/lo =============================
__global__ void __launch_bounds__(256)
split_kernel(const float* __restrict__ src, __nv_bfloat16* __restrict__ hi,
             __nv_bfloat16* __restrict__ lo, int n4)
{
    int i = blockIdx.x * 256 + threadIdx.x;
    if (i >= n4) return;
    float4 v = reinterpret_cast<const float4*>(src)[i];
    uint2 h = make_uint2(pack_bf2(v.x, v.y), pack_bf2(v.z, v.w));
    uint2 l = make_uint2(pack_bf2(v.x - bf_round(v.x), v.y - bf_round(v.y)),
                         pack_bf2(v.z - bf_round(v.z), v.w - bf_round(v.w)));
    reinterpret_cast<uint2*>(hi)[i] = h;
    reinterpret_cast<uint2*>(lo)[i] = l;
}

// ================= tensor-core GEMM: C[m,n] = sum_k A[m,k]*W[n,k] =============
#define BM 128
#define BN 128
#define BK 32
#define KT_ITERS (Dm/BK)              // 32
#define TPITCH 80
#define TILE_BYTES (128*TPITCH)        // 10240
#define STAGE_BYTES (4*TILE_BYTES)     // 40960
#define NSTAGE 3
#define GEMM_SMEM (NSTAGE*STAGE_BYTES) // 122880

template<bool ROPE, bool BHSD>
__global__ void __launch_bounds__(256, 1)
gemm_mma2_kernel(const __nv_bfloat16* __restrict__ Ahi,
                 const __nv_bfloat16* __restrict__ Alo,
                 const __nv_bfloat16* __restrict__ Bhi,
                 const __nv_bfloat16* __restrict__ Blo,
                 float* __restrict__ C,
                 __nv_bfloat16* __restrict__ Chi, __nv_bfloat16* __restrict__ Clo,
                 const int* __restrict__ pos)
{
    extern __shared__ char sm[];
    const uint32_t sbase = smem_u32(sm);

    const int tid  = threadIdx.x;
    const int lane = tid & 31;
    const int wid  = tid >> 5;
    const int warp_m = wid & 1;
    const int warp_n = wid >> 1;
    const int n0 = blockIdx.x * BN;
    const int m0 = blockIdx.y * BM;

    const int r0a = tid >> 2;
    const int c0  = tid & 3;
    const int r1a = (tid + 256) >> 2;

    const __nv_bfloat16* gsrc[4] = {Ahi, Alo, Bhi, Blo};

    auto issue_stage = [&](int stage, int kt) {
        const int kc = kt * BK;
        const uint32_t sb = sbase + stage * STAGE_BYTES;
        #pragma unroll
        for (int t = 0; t < 4; t++) {
            const int row0 = (t < 2) ? m0 : n0;
            const __nv_bfloat16* g = gsrc[t];
            cp16(sb + t * TILE_BYTES + (uint32_t)(r0a * TPITCH + c0 * 16),
                 g + (size_t)(row0 + r0a) * Dm + kc + c0 * 8);
            cp16(sb + t * TILE_BYTES + (uint32_t)(r1a * TPITCH + c0 * 16),
                 g + (size_t)(row0 + r1a) * Dm + kc + c0 * 8);
        }
    };

    float acc[4][4][4];
    #pragma unroll
    for (int i = 0; i < 4; i++)
        #pragma unroll
        for (int j = 0; j < 4; j++)
            #pragma unroll
            for (int v = 0; v < 4; v++) acc[i][j][v] = 0.f;

    issue_stage(0, 0); CP_COMMIT();
    issue_stage(1, 1); CP_COMMIT();
    CP_WAIT(1);
    __syncthreads();

    for (int kt = 0; kt < KT_ITERS; kt++) {
        const uint32_t sb = sbase + (kt % NSTAGE) * STAGE_BYTES;
        const uint32_t sAhi = sb;
        const uint32_t sAlo = sb + TILE_BYTES;
        const uint32_t sBhi = sb + 2 * TILE_BYTES;
        const uint32_t sBlo = sb + 3 * TILE_BYTES;

        #pragma unroll
        for (int ks = 0; ks < 2; ks++) {
            const int chunk = ks * 2;
            uint32_t ahi[4][4], alo[4][4], bhi[4][2], blo[4][2];
            #pragma unroll
            for (int mt = 0; mt < 4; mt++) {
                const int arow = warp_m * 64 + mt * 16 + (lane & 15);
                const uint32_t aoff = (uint32_t)(arow * TPITCH + (chunk + (lane >> 4)) * 16);
                ldsm_x4(sAhi + aoff, ahi[mt]);
                ldsm_x4(sAlo + aoff, alo[mt]);
            }
            #pragma unroll
            for (int nt = 0; nt < 4; nt++) {
                const int brow = warp_n * 32 + nt * 8 + (lane & 7);
                const uint32_t boff = (uint32_t)(brow * TPITCH + (chunk + ((lane >> 3) & 1)) * 16);
                ldsm_x2(sBhi + boff, bhi[nt]);
                ldsm_x2(sBlo + boff, blo[nt]);
            }
            #pragma unroll
            for (int mt = 0; mt < 4; mt++)
                #pragma unroll
                for (int nt = 0; nt < 4; nt++) {
                    mma_bf16(acc[mt][nt], ahi[mt], bhi[nt]);
                    mma_bf16(acc[mt][nt], alo[mt], bhi[nt]);
                    mma_bf16(acc[mt][nt], ahi[mt], blo[nt]);
                }
        }
        __syncthreads();

        if (kt + 2 < KT_ITERS) { issue_stage((kt + 2) % NSTAGE, kt + 2); CP_COMMIT(); }
        if (kt + 1 < KT_ITERS) {
            if (kt + 2 < KT_ITERS) { CP_WAIT(1); } else { CP_WAIT(0); }
            __syncthreads();
        }
    }

    // ---- epilogue: fused RoPE + store (bf16 hi/lo if BHSD, else fp32) --------
    #pragma unroll
    for (int mt = 0; mt < 4; mt++) {
        #pragma unroll
        for (int half = 0; half < 2; half++) {
            const int row = m0 + warp_m * 64 + mt * 16 + (lane >> 2) + half * 8;
            const int b = row >> 11;
            const int s = row & (Sq - 1);
            float p = 0.f;
            if (ROPE) p = (float)pos[row];
            #pragma unroll
            for (int nt = 0; nt < 4; nt++) {
                const int col = n0 + warp_n * 32 + nt * 8 + (lane & 3) * 2;  // even
                float e = acc[mt][nt][half * 2];
                float o = acc[mt][nt][half * 2 + 1];
                if (ROPE) {
                    const int dk = col & (Dk - 1);
                    const float inv = exp2f((float)dk * (-13.287712379549449f / 64.0f));
                    float sn, cs;
                    sincosf(p * inv, &sn, &cs);
                    const float re = e * cs - o * sn;
                    const float ro = e * sn + o * cs;
                    e = re; o = ro;
                }
                if (BHSD) {
                    const int h  = col >> 6;
                    const int dk = col & (Dk - 1);
                    const size_t idx = ((size_t)(b * Hn + h) * Sq + s) * Dk + dk;
                    *reinterpret_cast<uint32_t*>(Chi + idx) = pack_bf2(e, o);
                    *reinterpret_cast<uint32_t*>(Clo + idx) =
                        pack_bf2(e - bf_round(e), o - bf_round(o));
                } else {
                    float* dst = C + (size_t)row * Dm + col;
                    *reinterpret_cast<float2*>(dst) = make_float2(e, o);
                }
            }
        }
    }
}

// ================= tensor-core causal flash attention =========================
// CTA: 128 queries of one (b,h); 8 warps x 16 rows; key tiles of 64.
// QK^T and P*V via m16n8k16 bf16 with 3-term compensation.
#define ATPITCH 144
#define AT_TILE (64*ATPITCH)          // 9216
#define AT_STAGE (4*AT_TILE)          // Khi|Klo|Vhi|Vlo = 36864
#define ATT_SMEM (2*AT_STAGE)         // 73728

__global__ void __launch_bounds__(256, 1)
attn_mma_kernel(const __nv_bfloat16* __restrict__ Qhi, const __nv_bfloat16* __restrict__ Qlo,
                const __nv_bfloat16* __restrict__ Khi, const __nv_bfloat16* __restrict__ Klo,
                const __nv_bfloat16* __restrict__ Vhi, const __nv_bfloat16* __restrict__ Vlo,
                __nv_bfloat16* __restrict__ Ohi, __nv_bfloat16* __restrict__ Olo)
{
    extern __shared__ char sm[];
    const uint32_t sbase = smem_u32(sm);

    const int tid  = threadIdx.x;
    const int lane = tid & 31;
    const int w    = tid >> 5;
    const int bh   = blockIdx.y;
    const int qt   = (int)gridDim.x - 1 - (int)blockIdx.x;   // big tiles first
    const int q0   = qt * 128;
    const int NT   = 2 * qt + 2;                             // key tiles (64 each)

    const size_t kvbase = (size_t)bh * Sq;   // row base in [B*H, S] space

    // --- Q fragments (direct gmem gather, once) ------------------------------
    const int r  = q0 + w * 16 + (lane >> 2);
    const int dc = 2 * (lane & 3);
    uint32_t qh[4][4], ql[4][4];
    #pragma unroll
    for (int c = 0; c < 4; c++) {
        const int d = c * 16 + dc;
        const size_t i00 = (kvbase + r) * Dk + d;
        const size_t i10 = (kvbase + r + 8) * Dk + d;
        qh[c][0] = *reinterpret_cast<const uint32_t*>(Qhi + i00);
        qh[c][1] = *reinterpret_cast<const uint32_t*>(Qhi + i10);
        qh[c][2] = *reinterpret_cast<const uint32_t*>(Qhi + i00 + 8);
        qh[c][3] = *reinterpret_cast<const uint32_t*>(Qhi + i10 + 8);
        ql[c][0] = *reinterpret_cast<const uint32_t*>(Qlo + i00);
        ql[c][1] = *reinterpret_cast<const uint32_t*>(Qlo + i10);
        ql[c][2] = *reinterpret_cast<const uint32_t*>(Qlo + i00 + 8);
        ql[c][3] = *reinterpret_cast<const uint32_t*>(Qlo + i10 + 8);
    }

    const __nv_bfloat16* gkv[4] = {Khi, Klo, Vhi, Vlo};
    auto issue_kv = [&](int stage, int it) {
        const int k0 = it * 64;
        const uint32_t sb = sbase + stage * AT_STAGE;
        #pragma unroll
        for (int i = 0; i < 8; i++) {
            const int c = tid + i * 256;          // 0..2047
            const int t = c >> 9;                 // tile 0..3
            const int rr = (c >> 3) & 63;         // row 0..63
            const int cl = c & 7;                 // 16B chunk 0..7
            cp16(sb + t * AT_TILE + (uint32_t)(rr * ATPITCH + cl * 16),
                 gkv[t] + (kvbase + k0 + rr) * Dk + cl * 8);
        }
    };

    float o[8][4];
    #pragma unroll
    for (int nt = 0; nt < 8; nt++)
        #pragma unroll
        for (int j = 0; j < 4; j++) o[nt][j] = 0.f;
    float m0 = -1e30f, m1 = -1e30f, l0 = 0.f, l1 = 0.f;

    issue_kv(0, 0); CP_COMMIT();
    issue_kv(1, 1); CP_COMMIT();
    CP_WAIT(1);
    __syncthreads();

    const float SCL = 0.125f * 1.4426950408889634f;  // scale * log2(e)

    for (int it = 0; it < NT; it++) {
        const uint32_t sb  = sbase + (it & 1) * AT_STAGE;
        const uint32_t sKh = sb;
        const uint32_t sKl = sb + AT_TILE;
        const uint32_t sVh = sb + 2 * AT_TILE;
        const uint32_t sVl = sb + 3 * AT_TILE;
        const int k0 = it * 64;

        // ---- S = Q K^T (compensated) ----------------------------------------
        float s[8][4];
        #pragma unroll
        for (int nt = 0; nt < 8; nt++)
            #pragma unroll
            for (int j = 0; j < 4; j++) s[nt][j] = 0.f;

        #pragma unroll
        for (int c = 0; c < 4; c++) {
            #pragma unroll
            for (int nt = 0; nt < 8; nt++) {
                const uint32_t boff =
                    (uint32_t)((nt * 8 + (lane & 7)) * ATPITCH + c * 32 + ((lane >> 3) & 1) * 16);
                uint32_t kh[2], kl[2];
                ldsm_x2(sKh + boff, kh);
                ldsm_x2(sKl + boff, kl);
                mma_bf16(s[nt], qh[c], kh);
                mma_bf16(s[nt], ql[c], kh);
                mma_bf16(s[nt], qh[c], kl);
            }
        }

        // ---- online softmax (exp2 domain) ------------------------------------
        const bool need_mask = (k0 + 63 > q0);
        float t0 = -1e30f, t1 = -1e30f;
        #pragma unroll
        for (int nt = 0; nt < 8; nt++) {
            #pragma unroll
            for (int j = 0; j < 4; j++) {
                float t = s[nt][j] * SCL;
                if (need_mask) {
                    const int col = k0 + nt * 8 + dc + (j & 1);
                    const int row = (j < 2) ? r : r + 8;
                    if (col > row) t = -1e30f;
                }
                s[nt][j] = t;
                if (j < 2) t0 = fmaxf(t0, t); else t1 = fmaxf(t1, t);
            }
        }
        t0 = fmaxf(t0, __shfl_xor_sync(0xffffffffu, t0, 1));
        t0 = fmaxf(t0, __shfl_xor_sync(0xffffffffu, t0, 2));
        t1 = fmaxf(t1, __shfl_xor_sync(0xffffffffu, t1, 1));
        t1 = fmaxf(t1, __shfl_xor_sync(0xffffffffu, t1, 2));
        const float mn0 = fmaxf(m0, t0), mn1 = fmaxf(m1, t1);
        const float corr0 = exp2f(m0 - mn0), corr1 = exp2f(m1 - mn1);
        m0 = mn0; m1 = mn1;

        float ps0 = 0.f, ps1 = 0.f;
        #pragma unroll
        for (int nt = 0; nt < 8; nt++) {
            s[nt][0] = exp2f(s[nt][0] - m0);
            s[nt][1] = exp2f(s[nt][1] - m0);
            s[nt][2] = exp2f(s[nt][2] - m1);
            s[nt][3] = exp2f(s[nt][3] - m1);
            ps0 += s[nt][0] + s[nt][1];
            ps1 += s[nt][2] + s[nt][3];
        }
        ps0 += __shfl_xor_sync(0xffffffffu, ps0, 1);
        ps0 += __shfl_xor_sync(0xffffffffu, ps0, 2);
        ps1 += __shfl_xor_sync(0xffffffffu, ps1, 1);
        ps1 += __shfl_xor_sync(0xffffffffu, ps1, 2);
        l0 = l0 * corr0 + ps0;
        l1 = l1 * corr1 + ps1;

        #pragma unroll
        for (int nt = 0; nt < 8; nt++) {
            o[nt][0] *= corr0; o[nt][1] *= corr0;
            o[nt][2] *= corr1; o[nt][3] *= corr1;
        }

        // ---- O += P V (compensated) ------------------------------------------
        #pragma unroll
        for (int u = 0; u < 4; u++) {
            uint32_t aph[4], apl[4];
            {
                const float p00 = s[2*u][0],   p01 = s[2*u][1];
                const float p02 = s[2*u][2],   p03 = s[2*u][3];
                const float p10 = s[2*u+1][0], p11 = s[2*u+1][1];
                const float p12 = s[2*u+1][2], p13 = s[2*u+1][3];
                aph[0] = pack_bf2(p00, p01);
                aph[1] = pack_bf2(p02, p03);
                aph[2] = pack_bf2(p10, p11);
                aph[3] = pack_bf2(p12, p13);
                apl[0] = pack_bf2(p00 - bf_round(p00), p01 - bf_round(p01));
                apl[1] = pack_bf2(p02 - bf_round(p02), p03 - bf_round(p03));
                apl[2] = pack_bf2(p10 - bf_round(p10), p11 - bf_round(p11));
                apl[3] = pack_bf2(p12 - bf_round(p12), p13 - bf_round(p13));
            }
            #pragma unroll
            for (int nt = 0; nt < 8; nt++) {
                const uint32_t voff =
                    (uint32_t)((u * 16 + (lane & 15)) * ATPITCH + nt * 16);
                uint32_t vh[2], vl[2];
                ldsm_x2t(sVh + voff, vh);
                ldsm_x2t(sVl + voff, vl);
                mma_bf16(o[nt], aph, vh);
                mma_bf16(o[nt], apl, vh);
                mma_bf16(o[nt], aph, vl);
            }
        }

        __syncthreads();
        if (it + 2 < NT) { issue_kv(it & 1, it + 2); CP_COMMIT(); }
        if (it + 1 < NT) {
            if (it + 2 < NT) { CP_WAIT(1); } else { CP_WAIT(0); }
            __syncthreads();
        }
    }

    // ---- epilogue: normalize, split hi/lo, write [B,S,D] ---------------------
    const float inv0 = 1.0f / l0, inv1 = 1.0f / l1;
    const int b = bh >> 4, h = bh & 15;
    const size_t base0 = ((size_t)b * Sq + r) * Dm + h * Dk;
    const size_t base1 = ((size_t)b * Sq + r + 8) * Dm + h * Dk;
    #pragma unroll
    for (int nt = 0; nt < 8; nt++) {
        const int col = nt * 8 + dc;
        const float v0 = o[nt][0] * inv0, v1 = o[nt][1] * inv0;
        const float v2 = o[nt][2] * inv1, v3 = o[nt][3] * inv1;
        *reinterpret_cast<uint32_t*>(Ohi + base0 + col) = pack_bf2(v0, v1);
        *reinterpret_cast<uint32_t*>(Olo + base0 + col) =
            pack_bf2(v0 - bf_round(v0), v1 - bf_round(v1));
        *reinterpret_cast<uint32_t*>(Ohi + base1 + col) = pack_bf2(v2, v3);
        *reinterpret_cast<uint32_t*>(Olo + base1 + col) =
            pack_bf2(v2 - bf_round(v2), v3 - bf_round(v3));
    }
}

// ---------------- launch -----------------------------------------------------
extern "C" void kernel_launch(void* const* d_in, const int* in_sizes, int n_in,
                              void* d_out, int out_size)
{
    const float* x   = (const float*)d_in[0];
    const float* Wq  = (const float*)d_in[1];
    const float* Wk  = (const float*)d_in[2];
    const float* Wv  = (const float*)d_in[3];
    const float* Wo  = (const float*)d_in[4];
    const int*   pos = (const int*)d_in[5];
    float* out = (float*)d_out;

    __nv_bfloat16 *xhi, *xlo, *wqhi, *wqlo, *wkhi, *wklo, *wvhi, *wvlo, *wohi, *wolo;
    __nv_bfloat16 *qhi, *qlo, *khi, *klo, *vhi, *vlo, *ohi, *olo;
    cudaGetSymbolAddress((void**)&xhi,  g_xhi);  cudaGetSymbolAddress((void**)&xlo,  g_xlo);
    cudaGetSymbolAddress((void**)&wqhi, g_wqhi); cudaGetSymbolAddress((void**)&wqlo, g_wqlo);
    cudaGetSymbolAddress((void**)&wkhi, g_wkhi); cudaGetSymbolAddress((void**)&wklo, g_wklo);
    cudaGetSymbolAddress((void**)&wvhi, g_wvhi); cudaGetSymbolAddress((void**)&wvlo, g_wvlo);
    cudaGetSymbolAddress((void**)&wohi, g_wohi); cudaGetSymbolAddress((void**)&wolo, g_wolo);
    cudaGetSymbolAddress((void**)&qhi,  g_Qhi);  cudaGetSymbolAddress((void**)&qlo,  g_Qlo);
    cudaGetSymbolAddress((void**)&khi,  g_Khi);  cudaGetSymbolAddress((void**)&klo,  g_Klo);
    cudaGetSymbolAddress((void**)&vhi,  g_Vhi);  cudaGetSymbolAddress((void**)&vlo,  g_Vlo);
    cudaGetSymbolAddress((void**)&ohi,  g_Ohi);  cudaGetSymbolAddress((void**)&olo,  g_Olo);

    cudaFuncSetAttribute(gemm_mma2_kernel<true,  true >,
                         cudaFuncAttributeMaxDynamicSharedMemorySize, GEMM_SMEM);
    cudaFuncSetAttribute(gemm_mma2_kernel<false, true >,
                         cudaFuncAttributeMaxDynamicSharedMemorySize, GEMM_SMEM);
    cudaFuncSetAttribute(gemm_mma2_kernel<false, false>,
                         cudaFuncAttributeMaxDynamicSharedMemorySize, GEMM_SMEM);
    cudaFuncSetAttribute(attn_mma_kernel,
                         cudaFuncAttributeMaxDynamicSharedMemorySize, ATT_SMEM);

    const int nx4 = Mrows * Dm / 4;
    const int nw4 = Dm * Dm / 4;
    split_kernel<<<nx4 / 256, 256>>>(x,  xhi,  xlo,  nx4);
    split_kernel<<<nw4 / 256, 256>>>(Wq, wqhi, wqlo, nw4);
    split_kernel<<<nw4 / 256, 256>>>(Wk, wkhi, wklo, nw4);
    split_kernel<<<nw4 / 256, 256>>>(Wv, wvhi, wvlo, nw4);
    split_kernel<<<nw4 / 256, 256>>>(Wo, wohi, wolo, nw4);

    dim3 ggrid(Dm / BN, Mrows / BM);   // (8, 32)
    gemm_mma2_kernel<true,  true ><<<ggrid, 256, GEMM_SMEM>>>(xhi, xlo, wqhi, wqlo, nullptr, qhi, qlo, pos);
    gemm_mma2_kernel<true,  true ><<<ggrid, 256, GEMM_SMEM>>>(xhi, xlo, wkhi, wklo, nullptr, khi, klo, pos);
    gemm_mma2_kernel<false, true ><<<ggrid, 256, GEMM_SMEM>>>(xhi, xlo, wvhi, wvlo, nullptr, vhi, vlo, pos);

    dim3 agrid(Sq / 128, Bsz * Hn);    // (16, 32)
    attn_mma_kernel<<<agrid, 256, ATT_SMEM>>>(qhi, qlo, khi, klo, vhi, vlo, ohi, olo);

    gemm_mma2_kernel<false, false><<<ggrid, 256, GEMM_SMEM>>>(ohi, olo, wohi, wolo, out, nullptr, nullptr, pos);
}

// round 6
// speedup vs baseline: 2.8912x; 1.0420x over previous
#include <cuda_runtime.h>
#include <cuda_bf16.h>
#include <math.h>
#include <stdint.h>

// Problem constants (fixed by this dataset instance)
#define Bsz 2
#define Sq  2048
#define Dm  1024
#define Hn  16
#define Dk  64
#define Mrows (Bsz*Sq)   // 4096

// ---------------- scratch ----------------------------------------------------
__device__ __nv_bfloat16 g_xhi[Mrows*Dm], g_xlo[Mrows*Dm];
__device__ __nv_bfloat16 g_wqhi[Dm*Dm], g_wqlo[Dm*Dm];
__device__ __nv_bfloat16 g_wkhi[Dm*Dm], g_wklo[Dm*Dm];
__device__ __nv_bfloat16 g_wvhi[Dm*Dm], g_wvlo[Dm*Dm];
__device__ __nv_bfloat16 g_wohi[Dm*Dm], g_wolo[Dm*Dm];
__device__ __nv_bfloat16 g_Qhi[Mrows*Dm], g_Qlo[Mrows*Dm];   // [B,H,S,Dk]
__device__ __nv_bfloat16 g_Khi[Mrows*Dm], g_Klo[Mrows*Dm];
__device__ __nv_bfloat16 g_Vhi[Mrows*Dm], g_Vlo[Mrows*Dm];
__device__ __nv_bfloat16 g_Ohi[Mrows*Dm], g_Olo[Mrows*Dm];   // [B,S,D]

// ================= small PTX wrappers (portable, compute_103-safe) ===========
__device__ __forceinline__ uint32_t smem_u32(const void* p) {
    uint32_t a;
    asm("{ .reg .u64 t; cvta.to.shared.u64 t, %1; cvt.u32.u64 %0, t; }"
        : "=r"(a) : "l"(p));
    return a;
}
__device__ __forceinline__ void ldsm_x4(uint32_t addr, uint32_t r[4]) {
    asm volatile("ldmatrix.sync.aligned.m8n8.x4.shared.b16 {%0,%1,%2,%3}, [%4];"
                 : "=r"(r[0]), "=r"(r[1]), "=r"(r[2]), "=r"(r[3]) : "r"(addr));
}
__device__ __forceinline__ void ldsm_x2(uint32_t addr, uint32_t r[2]) {
    asm volatile("ldmatrix.sync.aligned.m8n8.x2.shared.b16 {%0,%1}, [%2];"
                 : "=r"(r[0]), "=r"(r[1]) : "r"(addr));
}
__device__ __forceinline__ void ldsm_x2t(uint32_t addr, uint32_t r[2]) {
    asm volatile("ldmatrix.sync.aligned.m8n8.x2.trans.shared.b16 {%0,%1}, [%2];"
                 : "=r"(r[0]), "=r"(r[1]) : "r"(addr));
}
__device__ __forceinline__ void mma_bf16(float c[4], const uint32_t a[4],
                                         const uint32_t b[2]) {
    asm volatile(
        "mma.sync.aligned.m16n8k16.row.col.f32.bf16.bf16.f32 "
        "{%0,%1,%2,%3}, {%4,%5,%6,%7}, {%8,%9}, {%0,%1,%2,%3};"
        : "+f"(c[0]), "+f"(c[1]), "+f"(c[2]), "+f"(c[3])
        : "r"(a[0]), "r"(a[1]), "r"(a[2]), "r"(a[3]), "r"(b[0]), "r"(b[1]));
}
__device__ __forceinline__ void cp16(uint32_t smem_addr, const void* gptr) {
    asm volatile("cp.async.cg.shared.global [%0], [%1], 16;"
                 :: "r"(smem_addr), "l"(gptr) : "memory");
}
#define CP_COMMIT() asm volatile("cp.async.commit_group;" ::: "memory")
#define CP_WAIT(n)  asm volatile("cp.async.wait_group %0;" :: "n"(n) : "memory")

__device__ __forceinline__ float bf_round(float x) {
    return __bfloat162float(__float2bfloat16(x));
}
__device__ __forceinline__ uint32_t pack_bf2(float x, float y) {
    __nv_bfloat162 t = __floats2bfloat162_rn(x, y);
    return *reinterpret_cast<uint32_t*>(&t);
}

// ================= fused split pass: fp32 -> bf16 hi/lo (all 5 tensors) ======
#define NX4 (Mrows*Dm/4)    // 1048576
#define NW4 (Dm*Dm/4)       // 262144
__global__ void __launch_bounds__(256)
split_all_kernel(const float* __restrict__ x,  const float* __restrict__ Wq,
                 const float* __restrict__ Wk, const float* __restrict__ Wv,
                 const float* __restrict__ Wo,
                 __nv_bfloat16* __restrict__ xhi,  __nv_bfloat16* __restrict__ xlo,
                 __nv_bfloat16* __restrict__ wqhi, __nv_bfloat16* __restrict__ wqlo,
                 __nv_bfloat16* __restrict__ wkhi, __nv_bfloat16* __restrict__ wklo,
                 __nv_bfloat16* __restrict__ wvhi, __nv_bfloat16* __restrict__ wvlo,
                 __nv_bfloat16* __restrict__ wohi, __nv_bfloat16* __restrict__ wolo)
{
    int i = blockIdx.x * 256 + threadIdx.x;
    const float* src; __nv_bfloat16 *hi, *lo; int j;
    if (i < NX4) { src = x; hi = xhi; lo = xlo; j = i; }
    else {
        int t = (i - NX4) >> 18;            // which weight (NW4 = 2^18)
        j = (i - NX4) & (NW4 - 1);
        if      (t == 0) { src = Wq; hi = wqhi; lo = wqlo; }
        else if (t == 1) { src = Wk; hi = wkhi; lo = wklo; }
        else if (t == 2) { src = Wv; hi = wvhi; lo = wvlo; }
        else             { src = Wo; hi = wohi; lo = wolo; }
    }
    float4 v = reinterpret_cast<const float4*>(src)[j];
    uint2 h = make_uint2(pack_bf2(v.x, v.y), pack_bf2(v.z, v.w));
    uint2 l = make_uint2(pack_bf2(v.x - bf_round(v.x), v.y - bf_round(v.y)),
                         pack_bf2(v.z - bf_round(v.z), v.w - bf_round(v.w)));
    reinterpret_cast<uint2*>(hi)[j] = h;
    reinterpret_cast<uint2*>(lo)[j] = l;
}

// ================= shared GEMM machinery ======================================
#define BM 128
#define BN 128
#define BK 32
#define KT_ITERS (Dm/BK)              // 32
#define TPITCH 80
#define TILE_BYTES (128*TPITCH)        // 10240
#define STAGE_BYTES (4*TILE_BYTES)     // 40960
#define NSTAGE 3
#define GEMM_SMEM (NSTAGE*STAGE_BYTES) // 122880

struct GemmCore {
    uint32_t sbase;
    int tid, lane, warp_m, warp_n, m0, n0;
    const __nv_bfloat16 *Ahi, *Alo, *Bhi, *Blo;
    int r0a, c0, r1a;

    __device__ __forceinline__ void issue_stage(int stage, int kt) {
        const int kc = kt * BK;
        const uint32_t sb = sbase + stage * STAGE_BYTES;
        const __nv_bfloat16* gsrc[4] = {Ahi, Alo, Bhi, Blo};
        #pragma unroll
        for (int t = 0; t < 4; t++) {
            const int row0 = (t < 2) ? m0 : n0;
            const __nv_bfloat16* g = gsrc[t];
            cp16(sb + t * TILE_BYTES + (uint32_t)(r0a * TPITCH + c0 * 16),
                 g + (size_t)(row0 + r0a) * Dm + kc + c0 * 8);
            cp16(sb + t * TILE_BYTES + (uint32_t)(r1a * TPITCH + c0 * 16),
                 g + (size_t)(row0 + r1a) * Dm + kc + c0 * 8);
        }
        CP_COMMIT();
    }

    __device__ __forceinline__ void mainloop(float acc[4][4][4]) {
        issue_stage(0, 0);
        issue_stage(1, 1);
        for (int kt = 0; kt < KT_ITERS; kt++) {
            if (kt + 1 < KT_ITERS) { CP_WAIT(1); } else { CP_WAIT(0); }
            __syncthreads();
            if (kt + 2 < KT_ITERS) issue_stage((kt + 2) % NSTAGE, kt + 2);

            const uint32_t sb = sbase + (kt % NSTAGE) * STAGE_BYTES;
            const uint32_t sAhi = sb;
            const uint32_t sAlo = sb + TILE_BYTES;
            const uint32_t sBhi = sb + 2 * TILE_BYTES;
            const uint32_t sBlo = sb + 3 * TILE_BYTES;

            #pragma unroll
            for (int ks = 0; ks < 2; ks++) {
                const int chunk = ks * 2;
                uint32_t ahi[4][4], alo[4][4], bhi[4][2], blo[4][2];
                #pragma unroll
                for (int mt = 0; mt < 4; mt++) {
                    const int arow = warp_m * 64 + mt * 16 + (lane & 15);
                    const uint32_t aoff = (uint32_t)(arow * TPITCH + (chunk + (lane >> 4)) * 16);
                    ldsm_x4(sAhi + aoff, ahi[mt]);
                    ldsm_x4(sAlo + aoff, alo[mt]);
                }
                #pragma unroll
                for (int nt = 0; nt < 4; nt++) {
                    const int brow = warp_n * 32 + nt * 8 + (lane & 7);
                    const uint32_t boff = (uint32_t)(brow * TPITCH + (chunk + ((lane >> 3) & 1)) * 16);
                    ldsm_x2(sBhi + boff, bhi[nt]);
                    ldsm_x2(sBlo + boff, blo[nt]);
                }
                #pragma unroll
                for (int mt = 0; mt < 4; mt++)
                    #pragma unroll
                    for (int nt = 0; nt < 4; nt++) {
                        mma_bf16(acc[mt][nt], ahi[mt], bhi[nt]);
                        mma_bf16(acc[mt][nt], alo[mt], bhi[nt]);
                        mma_bf16(acc[mt][nt], ahi[mt], blo[nt]);
                    }
            }
        }
    }
};

// ---- fused QKV GEMM: one launch computes Q, K, V projections -----------------
__global__ void __launch_bounds__(256, 1)
qkv_gemm_kernel(const __nv_bfloat16* __restrict__ xhi, const __nv_bfloat16* __restrict__ xlo,
                const __nv_bfloat16* __restrict__ wqhi, const __nv_bfloat16* __restrict__ wqlo,
                const __nv_bfloat16* __restrict__ wkhi, const __nv_bfloat16* __restrict__ wklo,
                const __nv_bfloat16* __restrict__ wvhi, const __nv_bfloat16* __restrict__ wvlo,
                __nv_bfloat16* __restrict__ qhi, __nv_bfloat16* __restrict__ qlo,
                __nv_bfloat16* __restrict__ khi, __nv_bfloat16* __restrict__ klo,
                __nv_bfloat16* __restrict__ vhi, __nv_bfloat16* __restrict__ vlo,
                const int* __restrict__ pos)
{
    extern __shared__ char sm[];
    const int tid  = threadIdx.x;
    const int wsel = blockIdx.x >> 3;

    GemmCore gc;
    gc.sbase = smem_u32(sm);
    gc.tid = tid; gc.lane = tid & 31;
    gc.warp_m = (tid >> 5) & 1; gc.warp_n = tid >> 6;
    gc.n0 = (blockIdx.x & 7) * BN;
    gc.m0 = blockIdx.y * BM;
    gc.Ahi = xhi; gc.Alo = xlo;
    gc.r0a = tid >> 2; gc.c0 = tid & 3; gc.r1a = (tid + 256) >> 2;

    __nv_bfloat16 *Chi, *Clo;
    bool rope;
    if (wsel == 0)      { gc.Bhi = wqhi; gc.Blo = wqlo; Chi = qhi; Clo = qlo; rope = true;  }
    else if (wsel == 1) { gc.Bhi = wkhi; gc.Blo = wklo; Chi = khi; Clo = klo; rope = true;  }
    else                { gc.Bhi = wvhi; gc.Blo = wvlo; Chi = vhi; Clo = vlo; rope = false; }

    float acc[4][4][4];
    #pragma unroll
    for (int i = 0; i < 4; i++)
        #pragma unroll
        for (int j = 0; j < 4; j++)
            #pragma unroll
            for (int v = 0; v < 4; v++) acc[i][j][v] = 0.f;

    gc.mainloop(acc);

    // epilogue: fused RoPE + hi/lo bf16 store to [B,H,S,Dk]
    const int lane = gc.lane;
    #pragma unroll
    for (int mt = 0; mt < 4; mt++) {
        #pragma unroll
        for (int half = 0; half < 2; half++) {
            const int row = gc.m0 + gc.warp_m * 64 + mt * 16 + (lane >> 2) + half * 8;
            const int b = row >> 11;
            const int s = row & (Sq - 1);
            float p = rope ? (float)pos[row] : 0.f;
            #pragma unroll
            for (int nt = 0; nt < 4; nt++) {
                const int col = gc.n0 + gc.warp_n * 32 + nt * 8 + (lane & 3) * 2;  // even
                float e = acc[mt][nt][half * 2];
                float o = acc[mt][nt][half * 2 + 1];
                if (rope) {
                    const int dk = col & (Dk - 1);
                    const float inv = exp2f((float)dk * (-13.287712379549449f / 64.0f));
                    float sn, cs;
                    sincosf(p * inv, &sn, &cs);
                    const float re = e * cs - o * sn;
                    const float ro = e * sn + o * cs;
                    e = re; o = ro;
                }
                const int h  = col >> 6;
                const int dk = col & (Dk - 1);
                const size_t idx = ((size_t)(b * Hn + h) * Sq + s) * Dk + dk;
                *reinterpret_cast<uint32_t*>(Chi + idx) = pack_bf2(e, o);
                *reinterpret_cast<uint32_t*>(Clo + idx) =
                    pack_bf2(e - bf_round(e), o - bf_round(o));
            }
        }
    }
}

// ---- output projection GEMM: fp32 out ----------------------------------------
__global__ void __launch_bounds__(256, 1)
wo_gemm_kernel(const __nv_bfloat16* __restrict__ Ahi, const __nv_bfloat16* __restrict__ Alo,
               const __nv_bfloat16* __restrict__ Bhi, const __nv_bfloat16* __restrict__ Blo,
               float* __restrict__ C)
{
    extern __shared__ char sm[];
    const int tid = threadIdx.x;

    GemmCore gc;
    gc.sbase = smem_u32(sm);
    gc.tid = tid; gc.lane = tid & 31;
    gc.warp_m = (tid >> 5) & 1; gc.warp_n = tid >> 6;
    gc.n0 = blockIdx.x * BN;
    gc.m0 = blockIdx.y * BM;
    gc.Ahi = Ahi; gc.Alo = Alo; gc.Bhi = Bhi; gc.Blo = Blo;
    gc.r0a = tid >> 2; gc.c0 = tid & 3; gc.r1a = (tid + 256) >> 2;

    float acc[4][4][4];
    #pragma unroll
    for (int i = 0; i < 4; i++)
        #pragma unroll
        for (int j = 0; j < 4; j++)
            #pragma unroll
            for (int v = 0; v < 4; v++) acc[i][j][v] = 0.f;

    gc.mainloop(acc);

    const int lane = gc.lane;
    #pragma unroll
    for (int mt = 0; mt < 4; mt++) {
        #pragma unroll
        for (int half = 0; half < 2; half++) {
            const int row = gc.m0 + gc.warp_m * 64 + mt * 16 + (lane >> 2) + half * 8;
            #pragma unroll
            for (int nt = 0; nt < 4; nt++) {
                const int col = gc.n0 + gc.warp_n * 32 + nt * 8 + (lane & 3) * 2;
                float* dst = C + (size_t)row * Dm + col;
                *reinterpret_cast<float2*>(dst) =
                    make_float2(acc[mt][nt][half * 2], acc[mt][nt][half * 2 + 1]);
            }
        }
    }
}

// ================= tensor-core causal flash attention =========================
#define ATPITCH 144
#define AT_TILE (64*ATPITCH)          // 9216
#define AT_STAGE (4*AT_TILE)          // Khi|Klo|Vhi|Vlo = 36864
#define AT_NSTAGE 3
#define ATT_SMEM (AT_NSTAGE*AT_STAGE) // 110592

__global__ void __launch_bounds__(256, 1)
attn_mma_kernel(const __nv_bfloat16* __restrict__ Qhi, const __nv_bfloat16* __restrict__ Qlo,
                const __nv_bfloat16* __restrict__ Khi, const __nv_bfloat16* __restrict__ Klo,
                const __nv_bfloat16* __restrict__ Vhi, const __nv_bfloat16* __restrict__ Vlo,
                __nv_bfloat16* __restrict__ Ohi, __nv_bfloat16* __restrict__ Olo)
{
    extern __shared__ char sm[];
    const uint32_t sbase = smem_u32(sm);

    const int tid  = threadIdx.x;
    const int lane = tid & 31;
    const int w    = tid >> 5;
    const int bh   = blockIdx.y;
    const int qt   = (int)gridDim.x - 1 - (int)blockIdx.x;   // big tiles first
    const int q0   = qt * 128;
    const int NT   = 2 * qt + 2;                             // key tiles (64 each)

    const size_t kvbase = (size_t)bh * Sq;

    // --- Q fragments (direct gmem gather, once) ------------------------------
    const int r  = q0 + w * 16 + (lane >> 2);
    const int dc = 2 * (lane & 3);
    uint32_t qh[4][4], ql[4][4];
    #pragma unroll
    for (int c = 0; c < 4; c++) {
        const int d = c * 16 + dc;
        const size_t i00 = (kvbase + r) * Dk + d;
        const size_t i10 = (kvbase + r + 8) * Dk + d;
        qh[c][0] = *reinterpret_cast<const uint32_t*>(Qhi + i00);
        qh[c][1] = *reinterpret_cast<const uint32_t*>(Qhi + i10);
        qh[c][2] = *reinterpret_cast<const uint32_t*>(Qhi + i00 + 8);
        qh[c][3] = *reinterpret_cast<const uint32_t*>(Qhi + i10 + 8);
        ql[c][0] = *reinterpret_cast<const uint32_t*>(Qlo + i00);
        ql[c][1] = *reinterpret_cast<const uint32_t*>(Qlo + i10);
        ql[c][2] = *reinterpret_cast<const uint32_t*>(Qlo + i00 + 8);
        ql[c][3] = *reinterpret_cast<const uint32_t*>(Qlo + i10 + 8);
    }

    const __nv_bfloat16* gkv[4] = {Khi, Klo, Vhi, Vlo};
    auto issue_kv = [&](int stage, int it) {
        const int k0 = it * 64;
        const uint32_t sb = sbase + stage * AT_STAGE;
        #pragma unroll
        for (int i = 0; i < 8; i++) {
            const int c = tid + i * 256;
            const int t = c >> 9;
            const int rr = (c >> 3) & 63;
            const int cl = c & 7;
            cp16(sb + t * AT_TILE + (uint32_t)(rr * ATPITCH + cl * 16),
                 gkv[t] + (kvbase + k0 + rr) * Dk + cl * 8);
        }
        CP_COMMIT();
    };

    float o[8][4];
    #pragma unroll
    for (int nt = 0; nt < 8; nt++)
        #pragma unroll
        for (int j = 0; j < 4; j++) o[nt][j] = 0.f;
    float m0 = -1e30f, m1 = -1e30f, l0 = 0.f, l1 = 0.f;

    issue_kv(0, 0);
    issue_kv(1, 1);

    const float SCL = 0.125f * 1.4426950408889634f;  // scale * log2(e)

    for (int it = 0; it < NT; it++) {
        if (it + 1 < NT) { CP_WAIT(1); } else { CP_WAIT(0); }
        __syncthreads();
        if (it + 2 < NT) issue_kv((it + 2) % AT_NSTAGE, it + 2);

        const uint32_t sb  = sbase + (it % AT_NSTAGE) * AT_STAGE;
        const uint32_t sKh = sb;
        const uint32_t sKl = sb + AT_TILE;
        const uint32_t sVh = sb + 2 * AT_TILE;
        const uint32_t sVl = sb + 3 * AT_TILE;
        const int k0 = it * 64;

        // ---- S = Q K^T (compensated) ----------------------------------------
        float s[8][4];
        #pragma unroll
        for (int nt = 0; nt < 8; nt++)
            #pragma unroll
            for (int j = 0; j < 4; j++) s[nt][j] = 0.f;

        #pragma unroll
        for (int c = 0; c < 4; c++) {
            #pragma unroll
            for (int nt = 0; nt < 8; nt++) {
                const uint32_t boff =
                    (uint32_t)((nt * 8 + (lane & 7)) * ATPITCH + c * 32 + ((lane >> 3) & 1) * 16);
                uint32_t kh[2], kl[2];
                ldsm_x2(sKh + boff, kh);
                ldsm_x2(sKl + boff, kl);
                mma_bf16(s[nt], qh[c], kh);
                mma_bf16(s[nt], ql[c], kh);
                mma_bf16(s[nt], qh[c], kl);
            }
        }

        // ---- online softmax (exp2 domain) ------------------------------------
        const bool need_mask = (k0 + 63 > q0);
        float t0 = -1e30f, t1 = -1e30f;
        #pragma unroll
        for (int nt = 0; nt < 8; nt++) {
            #pragma unroll
            for (int j = 0; j < 4; j++) {
                float t = s[nt][j] * SCL;
                if (need_mask) {
                    const int col = k0 + nt * 8 + dc + (j & 1);
                    const int row = (j < 2) ? r : r + 8;
                    if (col > row) t = -1e30f;
                }
                s[nt][j] = t;
                if (j < 2) t0 = fmaxf(t0, t); else t1 = fmaxf(t1, t);
            }
        }
        t0 = fmaxf(t0, __shfl_xor_sync(0xffffffffu, t0, 1));
        t0 = fmaxf(t0, __shfl_xor_sync(0xffffffffu, t0, 2));
        t1 = fmaxf(t1, __shfl_xor_sync(0xffffffffu, t1, 1));
        t1 = fmaxf(t1, __shfl_xor_sync(0xffffffffu, t1, 2));
        const float mn0 = fmaxf(m0, t0), mn1 = fmaxf(m1, t1);
        const float corr0 = exp2f(m0 - mn0), corr1 = exp2f(m1 - mn1);
        m0 = mn0; m1 = mn1;

        float ps0 = 0.f, ps1 = 0.f;
        #pragma unroll
        for (int nt = 0; nt < 8; nt++) {
            s[nt][0] = exp2f(s[nt][0] - m0);
            s[nt][1] = exp2f(s[nt][1] - m0);
            s[nt][2] = exp2f(s[nt][2] - m1);
            s[nt][3] = exp2f(s[nt][3] - m1);
            ps0 += s[nt][0] + s[nt][1];
            ps1 += s[nt][2] + s[nt][3];
        }
        ps0 += __shfl_xor_sync(0xffffffffu, ps0, 1);
        ps0 += __shfl_xor_sync(0xffffffffu, ps0, 2);
        ps1 += __shfl_xor_sync(0xffffffffu, ps1, 1);
        ps1 += __shfl_xor_sync(0xffffffffu, ps1, 2);
        l0 = l0 * corr0 + ps0;
        l1 = l1 * corr1 + ps1;

        #pragma unroll
        for (int nt = 0; nt < 8; nt++) {
            o[nt][0] *= corr0; o[nt][1] *= corr0;
            o[nt][2] *= corr1; o[nt][3] *= corr1;
        }

        // ---- O += P V (compensated) ------------------------------------------
        #pragma unroll
        for (int u = 0; u < 4; u++) {
            uint32_t aph[4], apl[4];
            {
                const float p00 = s[2*u][0],   p01 = s[2*u][1];
                const float p02 = s[2*u][2],   p03 = s[2*u][3];
                const float p10 = s[2*u+1][0], p11 = s[2*u+1][1];
                const float p12 = s[2*u+1][2], p13 = s[2*u+1][3];
                aph[0] = pack_bf2(p00, p01);
                aph[1] = pack_bf2(p02, p03);
                aph[2] = pack_bf2(p10, p11);
                aph[3] = pack_bf2(p12, p13);
                apl[0] = pack_bf2(p00 - bf_round(p00), p01 - bf_round(p01));
                apl[1] = pack_bf2(p02 - bf_round(p02), p03 - bf_round(p03));
                apl[2] = pack_bf2(p10 - bf_round(p10), p11 - bf_round(p11));
                apl[3] = pack_bf2(p12 - bf_round(p12), p13 - bf_round(p13));
            }
            #pragma unroll
            for (int nt = 0; nt < 8; nt++) {
                const uint32_t voff =
                    (uint32_t)((u * 16 + (lane & 15)) * ATPITCH + nt * 16);
                uint32_t vh[2], vl[2];
                ldsm_x2t(sVh + voff, vh);
                ldsm_x2t(sVl + voff, vl);
                mma_bf16(o[nt], aph, vh);
                mma_bf16(o[nt], apl, vh);
                mma_bf16(o[nt], aph, vl);
            }
        }
    }

    // ---- epilogue: normalize, split hi/lo, write [B,S,D] ---------------------
    const float inv0 = 1.0f / l0, inv1 = 1.0f / l1;
    const int b = bh >> 4, h = bh & 15;
    const size_t base0 = ((size_t)b * Sq + r) * Dm + h * Dk;
    const size_t base1 = ((size_t)b * Sq + r + 8) * Dm + h * Dk;
    #pragma unroll
    for (int nt = 0; nt < 8; nt++) {
        const int col = nt * 8 + dc;
        const float v0 = o[nt][0] * inv0, v1 = o[nt][1] * inv0;
        const float v2 = o[nt][2] * inv1, v3 = o[nt][3] * inv1;
        *reinterpret_cast<uint32_t*>(Ohi + base0 + col) = pack_bf2(v0, v1);
        *reinterpret_cast<uint32_t*>(Olo + base0 + col) =
            pack_bf2(v0 - bf_round(v0), v1 - bf_round(v1));
        *reinterpret_cast<uint32_t*>(Ohi + base1 + col) = pack_bf2(v2, v3);
        *reinterpret_cast<uint32_t*>(Olo + base1 + col) =
            pack_bf2(v2 - bf_round(v2), v3 - bf_round(v3));
    }
}

// ---------------- launch -----------------------------------------------------
extern "C" void kernel_launch(void* const* d_in, const int* in_sizes, int n_in,
                              void* d_out, int out_size)
{
    const float* x   = (const float*)d_in[0];
    const float* Wq  = (const float*)d_in[1];
    const float* Wk  = (const float*)d_in[2];
    const float* Wv  = (const float*)d_in[3];
    const float* Wo  = (const float*)d_in[4];
    const int*   pos = (const int*)d_in[5];
    float* out = (float*)d_out;

    __nv_bfloat16 *xhi, *xlo, *wqhi, *wqlo, *wkhi, *wklo, *wvhi, *wvlo, *wohi, *wolo;
    __nv_bfloat16 *qhi, *qlo, *khi, *klo, *vhi, *vlo, *ohi, *olo;
    cudaGetSymbolAddress((void**)&xhi,  g_xhi);  cudaGetSymbolAddress((void**)&xlo,  g_xlo);
    cudaGetSymbolAddress((void**)&wqhi, g_wqhi); cudaGetSymbolAddress((void**)&wqlo, g_wqlo);
    cudaGetSymbolAddress((void**)&wkhi, g_wkhi); cudaGetSymbolAddress((void**)&wklo, g_wklo);
    cudaGetSymbolAddress((void**)&wvhi, g_wvhi); cudaGetSymbolAddress((void**)&wvlo, g_wvlo);
    cudaGetSymbolAddress((void**)&wohi, g_wohi); cudaGetSymbolAddress((void**)&wolo, g_wolo);
    cudaGetSymbolAddress((void**)&qhi,  g_Qhi);  cudaGetSymbolAddress((void**)&qlo,  g_Qlo);
    cudaGetSymbolAddress((void**)&khi,  g_Khi);  cudaGetSymbolAddress((void**)&klo,  g_Klo);
    cudaGetSymbolAddress((void**)&vhi,  g_Vhi);  cudaGetSymbolAddress((void**)&vlo,  g_Vlo);
    cudaGetSymbolAddress((void**)&ohi,  g_Ohi);  cudaGetSymbolAddress((void**)&olo,  g_Olo);

    cudaFuncSetAttribute(qkv_gemm_kernel,
                         cudaFuncAttributeMaxDynamicSharedMemorySize, GEMM_SMEM);
    cudaFuncSetAttribute(wo_gemm_kernel,
                         cudaFuncAttributeMaxDynamicSharedMemorySize, GEMM_SMEM);
    cudaFuncSetAttribute(attn_mma_kernel,
                         cudaFuncAttributeMaxDynamicSharedMemorySize, ATT_SMEM);

    // 1) one fused split pass (x + 4 weights)
    const int ntot4 = NX4 + 4 * NW4;   // 2097152
    split_all_kernel<<<ntot4 / 256, 256>>>(x, Wq, Wk, Wv, Wo,
                                           xhi, xlo, wqhi, wqlo, wkhi, wklo,
                                           wvhi, wvlo, wohi, wolo);

    // 2) fused QKV projection (+RoPE on Q,K)
    dim3 qkvgrid(3 * (Dm / BN), Mrows / BM);   // (24, 32)
    qkv_gemm_kernel<<<qkvgrid, 256, GEMM_SMEM>>>(xhi, xlo, wqhi, wqlo, wkhi, wklo,
                                                 wvhi, wvlo, qhi, qlo, khi, klo,
                                                 vhi, vlo, pos);

    // 3) causal flash attention
    dim3 agrid(Sq / 128, Bsz * Hn);            // (16, 32)
    attn_mma_kernel<<<agrid, 256, ATT_SMEM>>>(qhi, qlo, khi, klo, vhi, vlo, ohi, olo);

    // 4) output projection
    dim3 wogrid(Dm / BN, Mrows / BM);          // (8, 32)
    wo_gemm_kernel<<<wogrid, 256, GEMM_SMEM>>>(ohi, olo, wohi, wolo, out);
}

// round 7
// speedup vs baseline: 3.0003x; 1.0377x over previous
#include <cuda_runtime.h>
#include <cuda_bf16.h>
#include <math.h>
#include <stdint.h>

// Problem constants (fixed by this dataset instance)
#define Bsz 2
#define Sq  2048
#define Dm  1024
#define Hn  16
#define Dk  64
#define Mrows (Bsz*Sq)   // 4096

// ---------------- scratch ----------------------------------------------------
__device__ __nv_bfloat16 g_xhi[Mrows*Dm], g_xlo[Mrows*Dm];
__device__ __nv_bfloat16 g_wqhi[Dm*Dm], g_wqlo[Dm*Dm];
__device__ __nv_bfloat16 g_wkhi[Dm*Dm], g_wklo[Dm*Dm];
__device__ __nv_bfloat16 g_wvhi[Dm*Dm], g_wvlo[Dm*Dm];
__device__ __nv_bfloat16 g_wohi[Dm*Dm], g_wolo[Dm*Dm];
__device__ __nv_bfloat16 g_Qhi[Mrows*Dm], g_Qlo[Mrows*Dm];   // [B,H,S,Dk]
__device__ __nv_bfloat16 g_Khi[Mrows*Dm], g_Klo[Mrows*Dm];
__device__ __nv_bfloat16 g_Vhi[Mrows*Dm], g_Vlo[Mrows*Dm];
__device__ __nv_bfloat16 g_Ohi[Mrows*Dm], g_Olo[Mrows*Dm];   // [B,S,D]

// ================= small PTX wrappers (portable, compute_103-safe) ===========
__device__ __forceinline__ uint32_t smem_u32(const void* p) {
    uint32_t a;
    asm("{ .reg .u64 t; cvta.to.shared.u64 t, %1; cvt.u32.u64 %0, t; }"
        : "=r"(a) : "l"(p));
    return a;
}
__device__ __forceinline__ void ldsm_x4(uint32_t addr, uint32_t r[4]) {
    asm volatile("ldmatrix.sync.aligned.m8n8.x4.shared.b16 {%0,%1,%2,%3}, [%4];"
                 : "=r"(r[0]), "=r"(r[1]), "=r"(r[2]), "=r"(r[3]) : "r"(addr));
}
__device__ __forceinline__ void ldsm_x2(uint32_t addr, uint32_t r[2]) {
    asm volatile("ldmatrix.sync.aligned.m8n8.x2.shared.b16 {%0,%1}, [%2];"
                 : "=r"(r[0]), "=r"(r[1]) : "r"(addr));
}
__device__ __forceinline__ void ldsm_x2t(uint32_t addr, uint32_t r[2]) {
    asm volatile("ldmatrix.sync.aligned.m8n8.x2.trans.shared.b16 {%0,%1}, [%2];"
                 : "=r"(r[0]), "=r"(r[1]) : "r"(addr));
}
__device__ __forceinline__ void mma_bf16(float c[4], const uint32_t a[4],
                                         const uint32_t b[2]) {
    asm volatile(
        "mma.sync.aligned.m16n8k16.row.col.f32.bf16.bf16.f32 "
        "{%0,%1,%2,%3}, {%4,%5,%6,%7}, {%8,%9}, {%0,%1,%2,%3};"
        : "+f"(c[0]), "+f"(c[1]), "+f"(c[2]), "+f"(c[3])
        : "r"(a[0]), "r"(a[1]), "r"(a[2]), "r"(a[3]), "r"(b[0]), "r"(b[1]));
}
__device__ __forceinline__ void cp16(uint32_t smem_addr, const void* gptr) {
    asm volatile("cp.async.cg.shared.global [%0], [%1], 16;"
                 :: "r"(smem_addr), "l"(gptr) : "memory");
}
#define CP_COMMIT() asm volatile("cp.async.commit_group;" ::: "memory")
#define CP_WAIT(n)  asm volatile("cp.async.wait_group %0;" :: "n"(n) : "memory")

__device__ __forceinline__ float bf_round(float x) {
    return __bfloat162float(__float2bfloat16(x));
}
__device__ __forceinline__ uint32_t pack_bf2(float x, float y) {
    __nv_bfloat162 t = __floats2bfloat162_rn(x, y);
    return *reinterpret_cast<uint32_t*>(&t);
}

// ================= fused split pass: fp32 -> bf16 hi/lo (all 5 tensors) ======
#define NX4 (Mrows*Dm/4)    // 1048576
#define NW4 (Dm*Dm/4)       // 262144
__global__ void __launch_bounds__(256)
split_all_kernel(const float* __restrict__ x,  const float* __restrict__ Wq,
                 const float* __restrict__ Wk, const float* __restrict__ Wv,
                 const float* __restrict__ Wo,
                 __nv_bfloat16* __restrict__ xhi,  __nv_bfloat16* __restrict__ xlo,
                 __nv_bfloat16* __restrict__ wqhi, __nv_bfloat16* __restrict__ wqlo,
                 __nv_bfloat16* __restrict__ wkhi, __nv_bfloat16* __restrict__ wklo,
                 __nv_bfloat16* __restrict__ wvhi, __nv_bfloat16* __restrict__ wvlo,
                 __nv_bfloat16* __restrict__ wohi, __nv_bfloat16* __restrict__ wolo)
{
    int i = blockIdx.x * 256 + threadIdx.x;
    const float* src; __nv_bfloat16 *hi, *lo; int j;
    if (i < NX4) { src = x; hi = xhi; lo = xlo; j = i; }
    else {
        int t = (i - NX4) >> 18;            // which weight (NW4 = 2^18)
        j = (i - NX4) & (NW4 - 1);
        if      (t == 0) { src = Wq; hi = wqhi; lo = wqlo; }
        else if (t == 1) { src = Wk; hi = wkhi; lo = wklo; }
        else if (t == 2) { src = Wv; hi = wvhi; lo = wvlo; }
        else             { src = Wo; hi = wohi; lo = wolo; }
    }
    float4 v = reinterpret_cast<const float4*>(src)[j];
    uint2 h = make_uint2(pack_bf2(v.x, v.y), pack_bf2(v.z, v.w));
    uint2 l = make_uint2(pack_bf2(v.x - bf_round(v.x), v.y - bf_round(v.y)),
                         pack_bf2(v.z - bf_round(v.z), v.w - bf_round(v.w)));
    reinterpret_cast<uint2*>(hi)[j] = h;
    reinterpret_cast<uint2*>(lo)[j] = l;
}

// ================= shared GEMM machinery ======================================
#define BM 128
#define BN 128
#define BK 32
#define KT_ITERS (Dm/BK)              // 32
#define TPITCH 80
#define TILE_BYTES (128*TPITCH)        // 10240
#define STAGE_BYTES (4*TILE_BYTES)     // 40960
#define NSTAGE 2
#define GEMM_SMEM (NSTAGE*STAGE_BYTES) // 81920  (2 CTAs/SM fit)

struct GemmCore {
    uint32_t sbase;
    int tid, lane, warp_m, warp_n, m0, n0;
    const __nv_bfloat16 *Ahi, *Alo, *Bhi, *Blo;
    int r0a, c0, r1a;

    __device__ __forceinline__ void issue_stage(int stage, int kt) {
        const int kc = kt * BK;
        const uint32_t sb = sbase + stage * STAGE_BYTES;
        const __nv_bfloat16* gsrc[4] = {Ahi, Alo, Bhi, Blo};
        #pragma unroll
        for (int t = 0; t < 4; t++) {
            const int row0 = (t < 2) ? m0 : n0;
            const __nv_bfloat16* g = gsrc[t];
            cp16(sb + t * TILE_BYTES + (uint32_t)(r0a * TPITCH + c0 * 16),
                 g + (size_t)(row0 + r0a) * Dm + kc + c0 * 8);
            cp16(sb + t * TILE_BYTES + (uint32_t)(r1a * TPITCH + c0 * 16),
                 g + (size_t)(row0 + r1a) * Dm + kc + c0 * 8);
        }
        CP_COMMIT();
    }

    // register-lean mainloop: B fragments resident per k16 step, A per-mt
    __device__ __forceinline__ void mainloop(float acc[4][4][4]) {
        issue_stage(0, 0);
        issue_stage(1, 1);
        for (int kt = 0; kt < KT_ITERS; kt++) {
            if (kt + 1 < KT_ITERS) { CP_WAIT(1); } else { CP_WAIT(0); }
            __syncthreads();

            const uint32_t sb = sbase + (kt & 1) * STAGE_BYTES;
            const uint32_t sAhi = sb;
            const uint32_t sAlo = sb + TILE_BYTES;
            const uint32_t sBhi = sb + 2 * TILE_BYTES;
            const uint32_t sBlo = sb + 3 * TILE_BYTES;

            #pragma unroll
            for (int ks = 0; ks < 2; ks++) {
                const int chunk = ks * 2;
                uint32_t bhi[4][2], blo[4][2];
                #pragma unroll
                for (int nt = 0; nt < 4; nt++) {
                    const int brow = warp_n * 32 + nt * 8 + (lane & 7);
                    const uint32_t boff = (uint32_t)(brow * TPITCH + (chunk + ((lane >> 3) & 1)) * 16);
                    ldsm_x2(sBhi + boff, bhi[nt]);
                    ldsm_x2(sBlo + boff, blo[nt]);
                }
                #pragma unroll
                for (int mt = 0; mt < 4; mt++) {
                    uint32_t ahi[4], alo[4];
                    const int arow = warp_m * 64 + mt * 16 + (lane & 15);
                    const uint32_t aoff = (uint32_t)(arow * TPITCH + (chunk + (lane >> 4)) * 16);
                    ldsm_x4(sAhi + aoff, ahi);
                    ldsm_x4(sAlo + aoff, alo);
                    #pragma unroll
                    for (int nt = 0; nt < 4; nt++) {
                        mma_bf16(acc[mt][nt], ahi, bhi[nt]);
                        mma_bf16(acc[mt][nt], alo, bhi[nt]);
                        mma_bf16(acc[mt][nt], ahi, blo[nt]);
                    }
                }
            }

            if (kt + 2 < KT_ITERS) {
                __syncthreads();                  // stage (kt&1) fully consumed
                issue_stage(kt & 1, kt + 2);      // lands during compute(kt+1)
            }
        }
    }
};

// ---- fused QKV GEMM: one launch computes Q, K, V projections -----------------
__global__ void __launch_bounds__(256, 2)
qkv_gemm_kernel(const __nv_bfloat16* __restrict__ xhi, const __nv_bfloat16* __restrict__ xlo,
                const __nv_bfloat16* __restrict__ wqhi, const __nv_bfloat16* __restrict__ wqlo,
                const __nv_bfloat16* __restrict__ wkhi, const __nv_bfloat16* __restrict__ wklo,
                const __nv_bfloat16* __restrict__ wvhi, const __nv_bfloat16* __restrict__ wvlo,
                __nv_bfloat16* __restrict__ qhi, __nv_bfloat16* __restrict__ qlo,
                __nv_bfloat16* __restrict__ khi, __nv_bfloat16* __restrict__ klo,
                __nv_bfloat16* __restrict__ vhi, __nv_bfloat16* __restrict__ vlo,
                const int* __restrict__ pos)
{
    extern __shared__ char sm[];
    const int tid  = threadIdx.x;
    const int wsel = blockIdx.x >> 3;

    GemmCore gc;
    gc.sbase = smem_u32(sm);
    gc.tid = tid; gc.lane = tid & 31;
    gc.warp_m = (tid >> 5) & 1; gc.warp_n = tid >> 6;
    gc.n0 = (blockIdx.x & 7) * BN;
    gc.m0 = blockIdx.y * BM;
    gc.Ahi = xhi; gc.Alo = xlo;
    gc.r0a = tid >> 2; gc.c0 = tid & 3; gc.r1a = (tid + 256) >> 2;

    __nv_bfloat16 *Chi, *Clo;
    bool rope;
    if (wsel == 0)      { gc.Bhi = wqhi; gc.Blo = wqlo; Chi = qhi; Clo = qlo; rope = true;  }
    else if (wsel == 1) { gc.Bhi = wkhi; gc.Blo = wklo; Chi = khi; Clo = klo; rope = true;  }
    else                { gc.Bhi = wvhi; gc.Blo = wvlo; Chi = vhi; Clo = vlo; rope = false; }

    float acc[4][4][4];
    #pragma unroll
    for (int i = 0; i < 4; i++)
        #pragma unroll
        for (int j = 0; j < 4; j++)
            #pragma unroll
            for (int v = 0; v < 4; v++) acc[i][j][v] = 0.f;

    gc.mainloop(acc);

    // epilogue: fused RoPE + hi/lo bf16 store to [B,H,S,Dk]
    const int lane = gc.lane;
    #pragma unroll
    for (int mt = 0; mt < 4; mt++) {
        #pragma unroll
        for (int half = 0; half < 2; half++) {
            const int row = gc.m0 + gc.warp_m * 64 + mt * 16 + (lane >> 2) + half * 8;
            const int b = row >> 11;
            const int s = row & (Sq - 1);
            float p = rope ? (float)pos[row] : 0.f;
            #pragma unroll
            for (int nt = 0; nt < 4; nt++) {
                const int col = gc.n0 + gc.warp_n * 32 + nt * 8 + (lane & 3) * 2;  // even
                float e = acc[mt][nt][half * 2];
                float o = acc[mt][nt][half * 2 + 1];
                if (rope) {
                    const int dk = col & (Dk - 1);
                    const float inv = exp2f((float)dk * (-13.287712379549449f / 64.0f));
                    float sn, cs;
                    sincosf(p * inv, &sn, &cs);
                    const float re = e * cs - o * sn;
                    const float ro = e * sn + o * cs;
                    e = re; o = ro;
                }
                const int h  = col >> 6;
                const int dk = col & (Dk - 1);
                const size_t idx = ((size_t)(b * Hn + h) * Sq + s) * Dk + dk;
                *reinterpret_cast<uint32_t*>(Chi + idx) = pack_bf2(e, o);
                *reinterpret_cast<uint32_t*>(Clo + idx) =
                    pack_bf2(e - bf_round(e), o - bf_round(o));
            }
        }
    }
}

// ---- output projection GEMM: fp32 out ----------------------------------------
__global__ void __launch_bounds__(256, 2)
wo_gemm_kernel(const __nv_bfloat16* __restrict__ Ahi, const __nv_bfloat16* __restrict__ Alo,
               const __nv_bfloat16* __restrict__ Bhi, const __nv_bfloat16* __restrict__ Blo,
               float* __restrict__ C)
{
    extern __shared__ char sm[];
    const int tid = threadIdx.x;

    GemmCore gc;
    gc.sbase = smem_u32(sm);
    gc.tid = tid; gc.lane = tid & 31;
    gc.warp_m = (tid >> 5) & 1; gc.warp_n = tid >> 6;
    gc.n0 = blockIdx.x * BN;
    gc.m0 = blockIdx.y * BM;
    gc.Ahi = Ahi; gc.Alo = Alo; gc.Bhi = Bhi; gc.Blo = Blo;
    gc.r0a = tid >> 2; gc.c0 = tid & 3; gc.r1a = (tid + 256) >> 2;

    float acc[4][4][4];
    #pragma unroll
    for (int i = 0; i < 4; i++)
        #pragma unroll
        for (int j = 0; j < 4; j++)
            #pragma unroll
            for (int v = 0; v < 4; v++) acc[i][j][v] = 0.f;

    gc.mainloop(acc);

    const int lane = gc.lane;
    #pragma unroll
    for (int mt = 0; mt < 4; mt++) {
        #pragma unroll
        for (int half = 0; half < 2; half++) {
            const int row = gc.m0 + gc.warp_m * 64 + mt * 16 + (lane >> 2) + half * 8;
            #pragma unroll
            for (int nt = 0; nt < 4; nt++) {
                const int col = gc.n0 + gc.warp_n * 32 + nt * 8 + (lane & 3) * 2;
                float* dst = C + (size_t)row * Dm + col;
                *reinterpret_cast<float2*>(dst) =
                    make_float2(acc[mt][nt][half * 2], acc[mt][nt][half * 2 + 1]);
            }
        }
    }
}

// ================= tensor-core causal flash attention =========================
#define ATPITCH 144
#define AT_TILE (64*ATPITCH)          // 9216
#define AT_STAGE (4*AT_TILE)          // Khi|Klo|Vhi|Vlo = 36864
#define AT_NSTAGE 2
#define ATT_SMEM (AT_NSTAGE*AT_STAGE) // 73728  (2 CTAs/SM fit)

__global__ void __launch_bounds__(256, 2)
attn_mma_kernel(const __nv_bfloat16* __restrict__ Qhi, const __nv_bfloat16* __restrict__ Qlo,
                const __nv_bfloat16* __restrict__ Khi, const __nv_bfloat16* __restrict__ Klo,
                const __nv_bfloat16* __restrict__ Vhi, const __nv_bfloat16* __restrict__ Vlo,
                __nv_bfloat16* __restrict__ Ohi, __nv_bfloat16* __restrict__ Olo)
{
    extern __shared__ char sm[];
    const uint32_t sbase = smem_u32(sm);

    const int tid  = threadIdx.x;
    const int lane = tid & 31;
    const int w    = tid >> 5;
    const int bh   = blockIdx.y;
    const int qt   = (int)gridDim.x - 1 - (int)blockIdx.x;   // big tiles first
    const int q0   = qt * 128;
    const int NT   = 2 * qt + 2;                             // key tiles (64 each)

    const size_t kvbase = (size_t)bh * Sq;

    // --- Q fragments (direct gmem gather, once) ------------------------------
    const int r  = q0 + w * 16 + (lane >> 2);
    const int dc = 2 * (lane & 3);
    uint32_t qh[4][4], ql[4][4];
    #pragma unroll
    for (int c = 0; c < 4; c++) {
        const int d = c * 16 + dc;
        const size_t i00 = (kvbase + r) * Dk + d;
        const size_t i10 = (kvbase + r + 8) * Dk + d;
        qh[c][0] = *reinterpret_cast<const uint32_t*>(Qhi + i00);
        qh[c][1] = *reinterpret_cast<const uint32_t*>(Qhi + i10);
        qh[c][2] = *reinterpret_cast<const uint32_t*>(Qhi + i00 + 8);
        qh[c][3] = *reinterpret_cast<const uint32_t*>(Qhi + i10 + 8);
        ql[c][0] = *reinterpret_cast<const uint32_t*>(Qlo + i00);
        ql[c][1] = *reinterpret_cast<const uint32_t*>(Qlo + i10);
        ql[c][2] = *reinterpret_cast<const uint32_t*>(Qlo + i00 + 8);
        ql[c][3] = *reinterpret_cast<const uint32_t*>(Qlo + i10 + 8);
    }

    const __nv_bfloat16* gkv[4] = {Khi, Klo, Vhi, Vlo};
    auto issue_kv = [&](int stage, int it) {
        const int k0 = it * 64;
        const uint32_t sb = sbase + stage * AT_STAGE;
        #pragma unroll
        for (int i = 0; i < 8; i++) {
            const int c = tid + i * 256;
            const int t = c >> 9;
            const int rr = (c >> 3) & 63;
            const int cl = c & 7;
            cp16(sb + t * AT_TILE + (uint32_t)(rr * ATPITCH + cl * 16),
                 gkv[t] + (kvbase + k0 + rr) * Dk + cl * 8);
        }
        CP_COMMIT();
    };

    float o[8][4];
    #pragma unroll
    for (int nt = 0; nt < 8; nt++)
        #pragma unroll
        for (int j = 0; j < 4; j++) o[nt][j] = 0.f;
    float m0 = -1e30f, m1 = -1e30f, l0 = 0.f, l1 = 0.f;

    issue_kv(0, 0);
    issue_kv(1, 1);

    const float SCL = 0.125f * 1.4426950408889634f;  // scale * log2(e)

    for (int it = 0; it < NT; it++) {
        if (it + 1 < NT) { CP_WAIT(1); } else { CP_WAIT(0); }
        __syncthreads();

        const uint32_t sb  = sbase + (it & 1) * AT_STAGE;
        const uint32_t sKh = sb;
        const uint32_t sKl = sb + AT_TILE;
        const uint32_t sVh = sb + 2 * AT_TILE;
        const uint32_t sVl = sb + 3 * AT_TILE;
        const int k0 = it * 64;

        // ---- S = Q K^T (compensated) ----------------------------------------
        float s[8][4];
        #pragma unroll
        for (int nt = 0; nt < 8; nt++)
            #pragma unroll
            for (int j = 0; j < 4; j++) s[nt][j] = 0.f;

        #pragma unroll
        for (int c = 0; c < 4; c++) {
            #pragma unroll
            for (int nt = 0; nt < 8; nt++) {
                const uint32_t boff =
                    (uint32_t)((nt * 8 + (lane & 7)) * ATPITCH + c * 32 + ((lane >> 3) & 1) * 16);
                uint32_t kh[2], kl[2];
                ldsm_x2(sKh + boff, kh);
                ldsm_x2(sKl + boff, kl);
                mma_bf16(s[nt], qh[c], kh);
                mma_bf16(s[nt], ql[c], kh);
                mma_bf16(s[nt], qh[c], kl);
            }
        }

        // ---- online softmax (exp2 domain) ------------------------------------
        const bool need_mask = (k0 + 63 > q0);
        float t0 = -1e30f, t1 = -1e30f;
        #pragma unroll
        for (int nt = 0; nt < 8; nt++) {
            #pragma unroll
            for (int j = 0; j < 4; j++) {
                float t = s[nt][j] * SCL;
                if (need_mask) {
                    const int col = k0 + nt * 8 + dc + (j & 1);
                    const int row = (j < 2) ? r : r + 8;
                    if (col > row) t = -1e30f;
                }
                s[nt][j] = t;
                if (j < 2) t0 = fmaxf(t0, t); else t1 = fmaxf(t1, t);
            }
        }
        t0 = fmaxf(t0, __shfl_xor_sync(0xffffffffu, t0, 1));
        t0 = fmaxf(t0, __shfl_xor_sync(0xffffffffu, t0, 2));
        t1 = fmaxf(t1, __shfl_xor_sync(0xffffffffu, t1, 1));
        t1 = fmaxf(t1, __shfl_xor_sync(0xffffffffu, t1, 2));
        const float mn0 = fmaxf(m0, t0), mn1 = fmaxf(m1, t1);
        const float corr0 = exp2f(m0 - mn0), corr1 = exp2f(m1 - mn1);
        m0 = mn0; m1 = mn1;

        float ps0 = 0.f, ps1 = 0.f;
        #pragma unroll
        for (int nt = 0; nt < 8; nt++) {
            s[nt][0] = exp2f(s[nt][0] - m0);
            s[nt][1] = exp2f(s[nt][1] - m0);
            s[nt][2] = exp2f(s[nt][2] - m1);
            s[nt][3] = exp2f(s[nt][3] - m1);
            ps0 += s[nt][0] + s[nt][1];
            ps1 += s[nt][2] + s[nt][3];
        }
        ps0 += __shfl_xor_sync(0xffffffffu, ps0, 1);
        ps0 += __shfl_xor_sync(0xffffffffu, ps0, 2);
        ps1 += __shfl_xor_sync(0xffffffffu, ps1, 1);
        ps1 += __shfl_xor_sync(0xffffffffu, ps1, 2);
        l0 = l0 * corr0 + ps0;
        l1 = l1 * corr1 + ps1;

        #pragma unroll
        for (int nt = 0; nt < 8; nt++) {
            o[nt][0] *= corr0; o[nt][1] *= corr0;
            o[nt][2] *= corr1; o[nt][3] *= corr1;
        }

        // ---- O += P V (compensated) ------------------------------------------
        #pragma unroll
        for (int u = 0; u < 4; u++) {
            uint32_t aph[4], apl[4];
            {
                const float p00 = s[2*u][0],   p01 = s[2*u][1];
                const float p02 = s[2*u][2],   p03 = s[2*u][3];
                const float p10 = s[2*u+1][0], p11 = s[2*u+1][1];
                const float p12 = s[2*u+1][2], p13 = s[2*u+1][3];
                aph[0] = pack_bf2(p00, p01);
                aph[1] = pack_bf2(p02, p03);
                aph[2] = pack_bf2(p10, p11);
                aph[3] = pack_bf2(p12, p13);
                apl[0] = pack_bf2(p00 - bf_round(p00), p01 - bf_round(p01));
                apl[1] = pack_bf2(p02 - bf_round(p02), p03 - bf_round(p03));
                apl[2] = pack_bf2(p10 - bf_round(p10), p11 - bf_round(p11));
                apl[3] = pack_bf2(p12 - bf_round(p12), p13 - bf_round(p13));
            }
            #pragma unroll
            for (int nt = 0; nt < 8; nt++) {
                const uint32_t voff =
                    (uint32_t)((u * 16 + (lane & 15)) * ATPITCH + nt * 16);
                uint32_t vh[2], vl[2];
                ldsm_x2t(sVh + voff, vh);
                ldsm_x2t(sVl + voff, vl);
                mma_bf16(o[nt], aph, vh);
                mma_bf16(o[nt], apl, vh);
                mma_bf16(o[nt], aph, vl);
            }
        }

        if (it + 2 < NT) {
            __syncthreads();          // stage (it&1) fully consumed
            issue_kv(it & 1, it + 2); // lands during compute(it+1)
        }
    }

    // ---- epilogue: normalize, split hi/lo, write [B,S,D] ---------------------
    const float inv0 = 1.0f / l0, inv1 = 1.0f / l1;
    const int b = bh >> 4, h = bh & 15;
    const size_t base0 = ((size_t)b * Sq + r) * Dm + h * Dk;
    const size_t base1 = ((size_t)b * Sq + r + 8) * Dm + h * Dk;
    #pragma unroll
    for (int nt = 0; nt < 8; nt++) {
        const int col = nt * 8 + dc;
        const float v0 = o[nt][0] * inv0, v1 = o[nt][1] * inv0;
        const float v2 = o[nt][2] * inv1, v3 = o[nt][3] * inv1;
        *reinterpret_cast<uint32_t*>(Ohi + base0 + col) = pack_bf2(v0, v1);
        *reinterpret_cast<uint32_t*>(Olo + base0 + col) =
            pack_bf2(v0 - bf_round(v0), v1 - bf_round(v1));
        *reinterpret_cast<uint32_t*>(Ohi + base1 + col) = pack_bf2(v2, v3);
        *reinterpret_cast<uint32_t*>(Olo + base1 + col) =
            pack_bf2(v2 - bf_round(v2), v3 - bf_round(v3));
    }
}

// ---------------- launch -----------------------------------------------------
extern "C" void kernel_launch(void* const* d_in, const int* in_sizes, int n_in,
                              void* d_out, int out_size)
{
    const float* x   = (const float*)d_in[0];
    const float* Wq  = (const float*)d_in[1];
    const float* Wk  = (const float*)d_in[2];
    const float* Wv  = (const float*)d_in[3];
    const float* Wo  = (const float*)d_in[4];
    const int*   pos = (const int*)d_in[5];
    float* out = (float*)d_out;

    __nv_bfloat16 *xhi, *xlo, *wqhi, *wqlo, *wkhi, *wklo, *wvhi, *wvlo, *wohi, *wolo;
    __nv_bfloat16 *qhi, *qlo, *khi, *klo, *vhi, *vlo, *ohi, *olo;
    cudaGetSymbolAddress((void**)&xhi,  g_xhi);  cudaGetSymbolAddress((void**)&xlo,  g_xlo);
    cudaGetSymbolAddress((void**)&wqhi, g_wqhi); cudaGetSymbolAddress((void**)&wqlo, g_wqlo);
    cudaGetSymbolAddress((void**)&wkhi, g_wkhi); cudaGetSymbolAddress((void**)&wklo, g_wklo);
    cudaGetSymbolAddress((void**)&wvhi, g_wvhi); cudaGetSymbolAddress((void**)&wvlo, g_wvlo);
    cudaGetSymbolAddress((void**)&wohi, g_wohi); cudaGetSymbolAddress((void**)&wolo, g_wolo);
    cudaGetSymbolAddress((void**)&qhi,  g_Qhi);  cudaGetSymbolAddress((void**)&qlo,  g_Qlo);
    cudaGetSymbolAddress((void**)&khi,  g_Khi);  cudaGetSymbolAddress((void**)&klo,  g_Klo);
    cudaGetSymbolAddress((void**)&vhi,  g_Vhi);  cudaGetSymbolAddress((void**)&vlo,  g_Vlo);
    cudaGetSymbolAddress((void**)&ohi,  g_Ohi);  cudaGetSymbolAddress((void**)&olo,  g_Olo);

    cudaFuncSetAttribute(qkv_gemm_kernel,
                         cudaFuncAttributeMaxDynamicSharedMemorySize, GEMM_SMEM);
    cudaFuncSetAttribute(wo_gemm_kernel,
                         cudaFuncAttributeMaxDynamicSharedMemorySize, GEMM_SMEM);
    cudaFuncSetAttribute(attn_mma_kernel,
                         cudaFuncAttributeMaxDynamicSharedMemorySize, ATT_SMEM);

    // 1) one fused split pass (x + 4 weights)
    const int ntot4 = NX4 + 4 * NW4;   // 2097152
    split_all_kernel<<<ntot4 / 256, 256>>>(x, Wq, Wk, Wv, Wo,
                                           xhi, xlo, wqhi, wqlo, wkhi, wklo,
                                           wvhi, wvlo, wohi, wolo);

    // 2) fused QKV projection (+RoPE on Q,K)
    dim3 qkvgrid(3 * (Dm / BN), Mrows / BM);   // (24, 32)
    qkv_gemm_kernel<<<qkvgrid, 256, GEMM_SMEM>>>(xhi, xlo, wqhi, wqlo, wkhi, wklo,
                                                 wvhi, wvlo, qhi, qlo, khi, klo,
                                                 vhi, vlo, pos);

    // 3) causal flash attention
    dim3 agrid(Sq / 128, Bsz * Hn);            // (16, 32)
    attn_mma_kernel<<<agrid, 256, ATT_SMEM>>>(qhi, qlo, khi, klo, vhi, vlo, ohi, olo);

    // 4) output projection
    dim3 wogrid(Dm / BN, Mrows / BM);          // (8, 32)
    wo_gemm_kernel<<<wogrid, 256, GEMM_SMEM>>>(ohi, olo, wohi, wolo, out);
}

// round 8
// speedup vs baseline: 3.6245x; 1.2080x over previous
#include <cuda_runtime.h>
#include <cuda_bf16.h>
#include <cuda_fp16.h>
#include <math.h>
#include <stdint.h>

// Problem constants (fixed by this dataset instance)
#define Bsz 2
#define Sq  2048
#define Dm  1024
#define Hn  16
#define Dk  64
#define Mrows (Bsz*Sq)   // 4096

// ---------------- scratch ----------------------------------------------------
__device__ __half g_xhi[Mrows*Dm], g_xlo[Mrows*Dm];        // x: fp16 hi/lo
__device__ __half g_wqhi[Dm*Dm];                            // weights: fp16 hi only
__device__ __half g_wkhi[Dm*Dm];
__device__ __half g_wvhi[Dm*Dm];
__device__ __half g_wohi[Dm*Dm];
__device__ __nv_bfloat16 g_Qhi[Mrows*Dm], g_Qlo[Mrows*Dm]; // [B,H,S,Dk] bf16 hi/lo
__device__ __nv_bfloat16 g_Khi[Mrows*Dm], g_Klo[Mrows*Dm];
__device__ __nv_bfloat16 g_Vhi[Mrows*Dm], g_Vlo[Mrows*Dm];
__device__ __half g_Ohi[Mrows*Dm], g_Olo[Mrows*Dm];        // [B,S,D] fp16 hi/lo

// ================= small PTX wrappers (portable, compute_103-safe) ===========
__device__ __forceinline__ uint32_t smem_u32(const void* p) {
    uint32_t a;
    asm("{ .reg .u64 t; cvta.to.shared.u64 t, %1; cvt.u32.u64 %0, t; }"
        : "=r"(a) : "l"(p));
    return a;
}
__device__ __forceinline__ void ldsm_x4(uint32_t addr, uint32_t r[4]) {
    asm volatile("ldmatrix.sync.aligned.m8n8.x4.shared.b16 {%0,%1,%2,%3}, [%4];"
                 : "=r"(r[0]), "=r"(r[1]), "=r"(r[2]), "=r"(r[3]) : "r"(addr));
}
__device__ __forceinline__ void ldsm_x2(uint32_t addr, uint32_t r[2]) {
    asm volatile("ldmatrix.sync.aligned.m8n8.x2.shared.b16 {%0,%1}, [%2];"
                 : "=r"(r[0]), "=r"(r[1]) : "r"(addr));
}
__device__ __forceinline__ void ldsm_x2t(uint32_t addr, uint32_t r[2]) {
    asm volatile("ldmatrix.sync.aligned.m8n8.x2.trans.shared.b16 {%0,%1}, [%2];"
                 : "=r"(r[0]), "=r"(r[1]) : "r"(addr));
}
__device__ __forceinline__ void mma_bf16(float c[4], const uint32_t a[4],
                                         const uint32_t b[2]) {
    asm volatile(
        "mma.sync.aligned.m16n8k16.row.col.f32.bf16.bf16.f32 "
        "{%0,%1,%2,%3}, {%4,%5,%6,%7}, {%8,%9}, {%0,%1,%2,%3};"
        : "+f"(c[0]), "+f"(c[1]), "+f"(c[2]), "+f"(c[3])
        : "r"(a[0]), "r"(a[1]), "r"(a[2]), "r"(a[3]), "r"(b[0]), "r"(b[1]));
}
__device__ __forceinline__ void mma_f16(float c[4], const uint32_t a[4],
                                        const uint32_t b[2]) {
    asm volatile(
        "mma.sync.aligned.m16n8k16.row.col.f32.f16.f16.f32 "
        "{%0,%1,%2,%3}, {%4,%5,%6,%7}, {%8,%9}, {%0,%1,%2,%3};"
        : "+f"(c[0]), "+f"(c[1]), "+f"(c[2]), "+f"(c[3])
        : "r"(a[0]), "r"(a[1]), "r"(a[2]), "r"(a[3]), "r"(b[0]), "r"(b[1]));
}
__device__ __forceinline__ void cp16(uint32_t smem_addr, const void* gptr) {
    asm volatile("cp.async.cg.shared.global [%0], [%1], 16;"
                 :: "r"(smem_addr), "l"(gptr) : "memory");
}
#define CP_COMMIT() asm volatile("cp.async.commit_group;" ::: "memory")
#define CP_WAIT(n)  asm volatile("cp.async.wait_group %0;" :: "n"(n) : "memory")

__device__ __forceinline__ float bf_round(float x) {
    return __bfloat162float(__float2bfloat16(x));
}
__device__ __forceinline__ uint32_t pack_bf2(float x, float y) {
    __nv_bfloat162 t = __floats2bfloat162_rn(x, y);
    return *reinterpret_cast<uint32_t*>(&t);
}
__device__ __forceinline__ float hf_round(float x) {
    return __half2float(__float2half_rn(x));
}
__device__ __forceinline__ uint32_t pack_hf2(float x, float y) {
    __half2 t = __floats2half2_rn(x, y);
    return *reinterpret_cast<uint32_t*>(&t);
}

// ================= fused split pass ==========================================
// x -> fp16 hi/lo ; weights -> fp16 hi only
#define NX4 (Mrows*Dm/4)    // 1048576
#define NW4 (Dm*Dm/4)       // 262144
__global__ void __launch_bounds__(256)
split_all_kernel(const float* __restrict__ x,  const float* __restrict__ Wq,
                 const float* __restrict__ Wk, const float* __restrict__ Wv,
                 const float* __restrict__ Wo,
                 __half* __restrict__ xhi,  __half* __restrict__ xlo,
                 __half* __restrict__ wqhi, __half* __restrict__ wkhi,
                 __half* __restrict__ wvhi, __half* __restrict__ wohi)
{
    int i = blockIdx.x * 256 + threadIdx.x;
    if (i < NX4) {
        float4 v = reinterpret_cast<const float4*>(x)[i];
        uint2 h = make_uint2(pack_hf2(v.x, v.y), pack_hf2(v.z, v.w));
        uint2 l = make_uint2(pack_hf2(v.x - hf_round(v.x), v.y - hf_round(v.y)),
                             pack_hf2(v.z - hf_round(v.z), v.w - hf_round(v.w)));
        reinterpret_cast<uint2*>(xhi)[i] = h;
        reinterpret_cast<uint2*>(xlo)[i] = l;
    } else {
        int t = (i - NX4) >> 18;            // which weight (NW4 = 2^18)
        int j = (i - NX4) & (NW4 - 1);
        const float* src; __half* hi;
        if      (t == 0) { src = Wq; hi = wqhi; }
        else if (t == 1) { src = Wk; hi = wkhi; }
        else if (t == 2) { src = Wv; hi = wvhi; }
        else             { src = Wo; hi = wohi; }
        float4 v = reinterpret_cast<const float4*>(src)[j];
        reinterpret_cast<uint2*>(hi)[j] =
            make_uint2(pack_hf2(v.x, v.y), pack_hf2(v.z, v.w));
    }
}

// ================= shared GEMM machinery (fp16 2-term) ========================
// C = A*B^T with A = Ahi+Alo (fp16 pair), B = Bhi (fp16).  D = Ahi*Bhi + Alo*Bhi
#define BM 128
#define BN 128
#define BK 32
#define KT_ITERS (Dm/BK)              // 32
#define TPITCH 80
#define TILE_BYTES (128*TPITCH)        // 10240
#define STAGE_BYTES (3*TILE_BYTES)     // Ahi|Alo|Bhi = 30720
#define NSTAGE 3
#define GEMM_SMEM (NSTAGE*STAGE_BYTES) // 92160  (2 CTAs/SM fit)

struct GemmCore {
    uint32_t sbase;
    int lane, warp_m, warp_n, m0, n0;
    const __half *Ahi, *Alo, *Bhi;
    int r0a, c0, r1a;

    __device__ __forceinline__ void issue_stage(int stage, int kt) {
        const int kc = kt * BK;
        const uint32_t sb = sbase + stage * STAGE_BYTES;
        const __half* gsrc[3] = {Ahi, Alo, Bhi};
        #pragma unroll
        for (int t = 0; t < 3; t++) {
            const int row0 = (t < 2) ? m0 : n0;
            const __half* g = gsrc[t];
            cp16(sb + t * TILE_BYTES + (uint32_t)(r0a * TPITCH + c0 * 16),
                 g + (size_t)(row0 + r0a) * Dm + kc + c0 * 8);
            cp16(sb + t * TILE_BYTES + (uint32_t)(r1a * TPITCH + c0 * 16),
                 g + (size_t)(row0 + r1a) * Dm + kc + c0 * 8);
        }
        CP_COMMIT();
    }

    __device__ __forceinline__ void mainloop(float acc[4][4][4]) {
        issue_stage(0, 0);
        issue_stage(1, 1);
        for (int kt = 0; kt < KT_ITERS; kt++) {
            if (kt + 1 < KT_ITERS) { CP_WAIT(1); } else { CP_WAIT(0); }
            __syncthreads();
            if (kt + 2 < KT_ITERS) issue_stage((kt + 2) % NSTAGE, kt + 2);

            const uint32_t sb = sbase + (kt % NSTAGE) * STAGE_BYTES;
            const uint32_t sAhi = sb;
            const uint32_t sAlo = sb + TILE_BYTES;
            const uint32_t sBhi = sb + 2 * TILE_BYTES;

            #pragma unroll
            for (int ks = 0; ks < 2; ks++) {
                const int chunk = ks * 2;
                uint32_t bhi[4][2];
                #pragma unroll
                for (int nt = 0; nt < 4; nt++) {
                    const int brow = warp_n * 32 + nt * 8 + (lane & 7);
                    const uint32_t boff = (uint32_t)(brow * TPITCH + (chunk + ((lane >> 3) & 1)) * 16);
                    ldsm_x2(sBhi + boff, bhi[nt]);
                }
                #pragma unroll
                for (int mt = 0; mt < 4; mt++) {
                    uint32_t ahi[4], alo[4];
                    const int arow = warp_m * 64 + mt * 16 + (lane & 15);
                    const uint32_t aoff = (uint32_t)(arow * TPITCH + (chunk + (lane >> 4)) * 16);
                    ldsm_x4(sAhi + aoff, ahi);
                    ldsm_x4(sAlo + aoff, alo);
                    #pragma unroll
                    for (int nt = 0; nt < 4; nt++) {
                        mma_f16(acc[mt][nt], ahi, bhi[nt]);
                        mma_f16(acc[mt][nt], alo, bhi[nt]);
                    }
                }
            }
        }
    }
};

// ---- fused QKV GEMM: one launch computes Q, K, V projections -----------------
__global__ void __launch_bounds__(256, 2)
qkv_gemm_kernel(const __half* __restrict__ xhi, const __half* __restrict__ xlo,
                const __half* __restrict__ wqhi, const __half* __restrict__ wkhi,
                const __half* __restrict__ wvhi,
                __nv_bfloat16* __restrict__ qhi, __nv_bfloat16* __restrict__ qlo,
                __nv_bfloat16* __restrict__ khi, __nv_bfloat16* __restrict__ klo,
                __nv_bfloat16* __restrict__ vhi, __nv_bfloat16* __restrict__ vlo,
                const int* __restrict__ pos)
{
    extern __shared__ char sm[];
    const int tid  = threadIdx.x;
    const int wsel = blockIdx.x >> 3;

    GemmCore gc;
    gc.sbase = smem_u32(sm);
    gc.lane = tid & 31;
    gc.warp_m = (tid >> 5) & 1; gc.warp_n = tid >> 6;
    gc.n0 = (blockIdx.x & 7) * BN;
    gc.m0 = blockIdx.y * BM;
    gc.Ahi = xhi; gc.Alo = xlo;
    gc.r0a = tid >> 2; gc.c0 = tid & 3; gc.r1a = (tid + 256) >> 2;

    __nv_bfloat16 *Chi, *Clo;
    bool rope;
    if (wsel == 0)      { gc.Bhi = wqhi; Chi = qhi; Clo = qlo; rope = true;  }
    else if (wsel == 1) { gc.Bhi = wkhi; Chi = khi; Clo = klo; rope = true;  }
    else                { gc.Bhi = wvhi; Chi = vhi; Clo = vlo; rope = false; }

    float acc[4][4][4];
    #pragma unroll
    for (int i = 0; i < 4; i++)
        #pragma unroll
        for (int j = 0; j < 4; j++)
            #pragma unroll
            for (int v = 0; v < 4; v++) acc[i][j][v] = 0.f;

    gc.mainloop(acc);

    // epilogue: fused RoPE + hi/lo bf16 store to [B,H,S,Dk]
    const int lane = gc.lane;
    #pragma unroll
    for (int mt = 0; mt < 4; mt++) {
        #pragma unroll
        for (int half = 0; half < 2; half++) {
            const int row = gc.m0 + gc.warp_m * 64 + mt * 16 + (lane >> 2) + half * 8;
            const int b = row >> 11;
            const int s = row & (Sq - 1);
            float p = rope ? (float)pos[row] : 0.f;
            #pragma unroll
            for (int nt = 0; nt < 4; nt++) {
                const int col = gc.n0 + gc.warp_n * 32 + nt * 8 + (lane & 3) * 2;  // even
                float e = acc[mt][nt][half * 2];
                float o = acc[mt][nt][half * 2 + 1];
                if (rope) {
                    const int dk = col & (Dk - 1);
                    const float inv = exp2f((float)dk * (-13.287712379549449f / 64.0f));
                    float sn, cs;
                    sincosf(p * inv, &sn, &cs);
                    const float re = e * cs - o * sn;
                    const float ro = e * sn + o * cs;
                    e = re; o = ro;
                }
                const int h  = col >> 6;
                const int dk = col & (Dk - 1);
                const size_t idx = ((size_t)(b * Hn + h) * Sq + s) * Dk + dk;
                *reinterpret_cast<uint32_t*>(Chi + idx) = pack_bf2(e, o);
                *reinterpret_cast<uint32_t*>(Clo + idx) =
                    pack_bf2(e - bf_round(e), o - bf_round(o));
            }
        }
    }
}

// ---- output projection GEMM: fp32 out ----------------------------------------
__global__ void __launch_bounds__(256, 2)
wo_gemm_kernel(const __half* __restrict__ Ahi, const __half* __restrict__ Alo,
               const __half* __restrict__ Bhi, float* __restrict__ C)
{
    extern __shared__ char sm[];
    const int tid = threadIdx.x;

    GemmCore gc;
    gc.sbase = smem_u32(sm);
    gc.lane = tid & 31;
    gc.warp_m = (tid >> 5) & 1; gc.warp_n = tid >> 6;
    gc.n0 = blockIdx.x * BN;
    gc.m0 = blockIdx.y * BM;
    gc.Ahi = Ahi; gc.Alo = Alo; gc.Bhi = Bhi;
    gc.r0a = tid >> 2; gc.c0 = tid & 3; gc.r1a = (tid + 256) >> 2;

    float acc[4][4][4];
    #pragma unroll
    for (int i = 0; i < 4; i++)
        #pragma unroll
        for (int j = 0; j < 4; j++)
            #pragma unroll
            for (int v = 0; v < 4; v++) acc[i][j][v] = 0.f;

    gc.mainloop(acc);

    const int lane = gc.lane;
    #pragma unroll
    for (int mt = 0; mt < 4; mt++) {
        #pragma unroll
        for (int half = 0; half < 2; half++) {
            const int row = gc.m0 + gc.warp_m * 64 + mt * 16 + (lane >> 2) + half * 8;
            #pragma unroll
            for (int nt = 0; nt < 4; nt++) {
                const int col = gc.n0 + gc.warp_n * 32 + nt * 8 + (lane & 3) * 2;
                float* dst = C + (size_t)row * Dm + col;
                *reinterpret_cast<float2*>(dst) =
                    make_float2(acc[mt][nt][half * 2], acc[mt][nt][half * 2 + 1]);
            }
        }
    }
}

// ================= tensor-core causal flash attention (bf16x3, unchanged) =====
#define ATPITCH 144
#define AT_TILE (64*ATPITCH)          // 9216
#define AT_STAGE (4*AT_TILE)          // Khi|Klo|Vhi|Vlo = 36864
#define AT_NSTAGE 2
#define ATT_SMEM (AT_NSTAGE*AT_STAGE) // 73728  (2 CTAs/SM fit)

__global__ void __launch_bounds__(256, 2)
attn_mma_kernel(const __nv_bfloat16* __restrict__ Qhi, const __nv_bfloat16* __restrict__ Qlo,
                const __nv_bfloat16* __restrict__ Khi, const __nv_bfloat16* __restrict__ Klo,
                const __nv_bfloat16* __restrict__ Vhi, const __nv_bfloat16* __restrict__ Vlo,
                __half* __restrict__ Ohi, __half* __restrict__ Olo)
{
    extern __shared__ char sm[];
    const uint32_t sbase = smem_u32(sm);

    const int tid  = threadIdx.x;
    const int lane = tid & 31;
    const int w    = tid >> 5;
    const int bh   = blockIdx.y;
    const int qt   = (int)gridDim.x - 1 - (int)blockIdx.x;   // big tiles first
    const int q0   = qt * 128;
    const int NT   = 2 * qt + 2;                             // key tiles (64 each)

    const size_t kvbase = (size_t)bh * Sq;

    // --- Q fragments (direct gmem gather, once) ------------------------------
    const int r  = q0 + w * 16 + (lane >> 2);
    const int dc = 2 * (lane & 3);
    uint32_t qh[4][4], ql[4][4];
    #pragma unroll
    for (int c = 0; c < 4; c++) {
        const int d = c * 16 + dc;
        const size_t i00 = (kvbase + r) * Dk + d;
        const size_t i10 = (kvbase + r + 8) * Dk + d;
        qh[c][0] = *reinterpret_cast<const uint32_t*>(Qhi + i00);
        qh[c][1] = *reinterpret_cast<const uint32_t*>(Qhi + i10);
        qh[c][2] = *reinterpret_cast<const uint32_t*>(Qhi + i00 + 8);
        qh[c][3] = *reinterpret_cast<const uint32_t*>(Qhi + i10 + 8);
        ql[c][0] = *reinterpret_cast<const uint32_t*>(Qlo + i00);
        ql[c][1] = *reinterpret_cast<const uint32_t*>(Qlo + i10);
        ql[c][2] = *reinterpret_cast<const uint32_t*>(Qlo + i00 + 8);
        ql[c][3] = *reinterpret_cast<const uint32_t*>(Qlo + i10 + 8);
    }

    const __nv_bfloat16* gkv[4] = {Khi, Klo, Vhi, Vlo};
    auto issue_kv = [&](int stage, int it) {
        const int k0 = it * 64;
        const uint32_t sb = sbase + stage * AT_STAGE;
        #pragma unroll
        for (int i = 0; i < 8; i++) {
            const int c = tid + i * 256;
            const int t = c >> 9;
            const int rr = (c >> 3) & 63;
            const int cl = c & 7;
            cp16(sb + t * AT_TILE + (uint32_t)(rr * ATPITCH + cl * 16),
                 gkv[t] + (kvbase + k0 + rr) * Dk + cl * 8);
        }
        CP_COMMIT();
    };

    float o[8][4];
    #pragma unroll
    for (int nt = 0; nt < 8; nt++)
        #pragma unroll
        for (int j = 0; j < 4; j++) o[nt][j] = 0.f;
    float m0 = -1e30f, m1 = -1e30f, l0 = 0.f, l1 = 0.f;

    issue_kv(0, 0);
    issue_kv(1, 1);

    const float SCL = 0.125f * 1.4426950408889634f;  // scale * log2(e)

    for (int it = 0; it < NT; it++) {
        if (it + 1 < NT) { CP_WAIT(1); } else { CP_WAIT(0); }
        __syncthreads();

        const uint32_t sb  = sbase + (it & 1) * AT_STAGE;
        const uint32_t sKh = sb;
        const uint32_t sKl = sb + AT_TILE;
        const uint32_t sVh = sb + 2 * AT_TILE;
        const uint32_t sVl = sb + 3 * AT_TILE;
        const int k0 = it * 64;

        // ---- S = Q K^T (compensated) ----------------------------------------
        float s[8][4];
        #pragma unroll
        for (int nt = 0; nt < 8; nt++)
            #pragma unroll
            for (int j = 0; j < 4; j++) s[nt][j] = 0.f;

        #pragma unroll
        for (int c = 0; c < 4; c++) {
            #pragma unroll
            for (int nt = 0; nt < 8; nt++) {
                const uint32_t boff =
                    (uint32_t)((nt * 8 + (lane & 7)) * ATPITCH + c * 32 + ((lane >> 3) & 1) * 16);
                uint32_t kh[2], kl[2];
                ldsm_x2(sKh + boff, kh);
                ldsm_x2(sKl + boff, kl);
                mma_bf16(s[nt], qh[c], kh);
                mma_bf16(s[nt], ql[c], kh);
                mma_bf16(s[nt], qh[c], kl);
            }
        }

        // ---- online softmax (exp2 domain) ------------------------------------
        const bool need_mask = (k0 + 63 > q0);
        float t0 = -1e30f, t1 = -1e30f;
        #pragma unroll
        for (int nt = 0; nt < 8; nt++) {
            #pragma unroll
            for (int j = 0; j < 4; j++) {
                float t = s[nt][j] * SCL;
                if (need_mask) {
                    const int col = k0 + nt * 8 + dc + (j & 1);
                    const int row = (j < 2) ? r : r + 8;
                    if (col > row) t = -1e30f;
                }
                s[nt][j] = t;
                if (j < 2) t0 = fmaxf(t0, t); else t1 = fmaxf(t1, t);
            }
        }
        t0 = fmaxf(t0, __shfl_xor_sync(0xffffffffu, t0, 1));
        t0 = fmaxf(t0, __shfl_xor_sync(0xffffffffu, t0, 2));
        t1 = fmaxf(t1, __shfl_xor_sync(0xffffffffu, t1, 1));
        t1 = fmaxf(t1, __shfl_xor_sync(0xffffffffu, t1, 2));
        const float mn0 = fmaxf(m0, t0), mn1 = fmaxf(m1, t1);
        const float corr0 = exp2f(m0 - mn0), corr1 = exp2f(m1 - mn1);
        m0 = mn0; m1 = mn1;

        float ps0 = 0.f, ps1 = 0.f;
        #pragma unroll
        for (int nt = 0; nt < 8; nt++) {
            s[nt][0] = exp2f(s[nt][0] - m0);
            s[nt][1] = exp2f(s[nt][1] - m0);
            s[nt][2] = exp2f(s[nt][2] - m1);
            s[nt][3] = exp2f(s[nt][3] - m1);
            ps0 += s[nt][0] + s[nt][1];
            ps1 += s[nt][2] + s[nt][3];
        }
        ps0 += __shfl_xor_sync(0xffffffffu, ps0, 1);
        ps0 += __shfl_xor_sync(0xffffffffu, ps0, 2);
        ps1 += __shfl_xor_sync(0xffffffffu, ps1, 1);
        ps1 += __shfl_xor_sync(0xffffffffu, ps1, 2);
        l0 = l0 * corr0 + ps0;
        l1 = l1 * corr1 + ps1;

        #pragma unroll
        for (int nt = 0; nt < 8; nt++) {
            o[nt][0] *= corr0; o[nt][1] *= corr0;
            o[nt][2] *= corr1; o[nt][3] *= corr1;
        }

        // ---- O += P V (compensated) ------------------------------------------
        #pragma unroll
        for (int u = 0; u < 4; u++) {
            uint32_t aph[4], apl[4];
            {
                const float p00 = s[2*u][0],   p01 = s[2*u][1];
                const float p02 = s[2*u][2],   p03 = s[2*u][3];
                const float p10 = s[2*u+1][0], p11 = s[2*u+1][1];
                const float p12 = s[2*u+1][2], p13 = s[2*u+1][3];
                aph[0] = pack_bf2(p00, p01);
                aph[1] = pack_bf2(p02, p03);
                aph[2] = pack_bf2(p10, p11);
                aph[3] = pack_bf2(p12, p13);
                apl[0] = pack_bf2(p00 - bf_round(p00), p01 - bf_round(p01));
                apl[1] = pack_bf2(p02 - bf_round(p02), p03 - bf_round(p03));
                apl[2] = pack_bf2(p10 - bf_round(p10), p11 - bf_round(p11));
                apl[3] = pack_bf2(p12 - bf_round(p12), p13 - bf_round(p13));
            }
            #pragma unroll
            for (int nt = 0; nt < 8; nt++) {
                const uint32_t voff =
                    (uint32_t)((u * 16 + (lane & 15)) * ATPITCH + nt * 16);
                uint32_t vh[2], vl[2];
                ldsm_x2t(sVh + voff, vh);
                ldsm_x2t(sVl + voff, vl);
                mma_bf16(o[nt], aph, vh);
                mma_bf16(o[nt], apl, vh);
                mma_bf16(o[nt], aph, vl);
            }
        }

        if (it + 2 < NT) {
            __syncthreads();          // stage (it&1) fully consumed
            issue_kv(it & 1, it + 2); // lands during compute(it+1)
        }
    }

    // ---- epilogue: normalize, split fp16 hi/lo, write [B,S,D] ----------------
    const float inv0 = 1.0f / l0, inv1 = 1.0f / l1;
    const int b = bh >> 4, h = bh & 15;
    const size_t base0 = ((size_t)b * Sq + r) * Dm + h * Dk;
    const size_t base1 = ((size_t)b * Sq + r + 8) * Dm + h * Dk;
    #pragma unroll
    for (int nt = 0; nt < 8; nt++) {
        const int col = nt * 8 + dc;
        const float v0 = o[nt][0] * inv0, v1 = o[nt][1] * inv0;
        const float v2 = o[nt][2] * inv1, v3 = o[nt][3] * inv1;
        *reinterpret_cast<uint32_t*>(Ohi + base0 + col) = pack_hf2(v0, v1);
        *reinterpret_cast<uint32_t*>(Olo + base0 + col) =
            pack_hf2(v0 - hf_round(v0), v1 - hf_round(v1));
        *reinterpret_cast<uint32_t*>(Ohi + base1 + col) = pack_hf2(v2, v3);
        *reinterpret_cast<uint32_t*>(Olo + base1 + col) =
            pack_hf2(v2 - hf_round(v2), v3 - hf_round(v3));
    }
}

// ---------------- launch -----------------------------------------------------
extern "C" void kernel_launch(void* const* d_in, const int* in_sizes, int n_in,
                              void* d_out, int out_size)
{
    const float* x   = (const float*)d_in[0];
    const float* Wq  = (const float*)d_in[1];
    const float* Wk  = (const float*)d_in[2];
    const float* Wv  = (const float*)d_in[3];
    const float* Wo  = (const float*)d_in[4];
    const int*   pos = (const int*)d_in[5];
    float* out = (float*)d_out;

    __half *xhi, *xlo, *wqhi, *wkhi, *wvhi, *wohi, *ohi, *olo;
    __nv_bfloat16 *qhi, *qlo, *khi, *klo, *vhi, *vlo;
    cudaGetSymbolAddress((void**)&xhi,  g_xhi);  cudaGetSymbolAddress((void**)&xlo,  g_xlo);
    cudaGetSymbolAddress((void**)&wqhi, g_wqhi);
    cudaGetSymbolAddress((void**)&wkhi, g_wkhi);
    cudaGetSymbolAddress((void**)&wvhi, g_wvhi);
    cudaGetSymbolAddress((void**)&wohi, g_wohi);
    cudaGetSymbolAddress((void**)&qhi,  g_Qhi);  cudaGetSymbolAddress((void**)&qlo,  g_Qlo);
    cudaGetSymbolAddress((void**)&khi,  g_Khi);  cudaGetSymbolAddress((void**)&klo,  g_Klo);
    cudaGetSymbolAddress((void**)&vhi,  g_Vhi);  cudaGetSymbolAddress((void**)&vlo,  g_Vlo);
    cudaGetSymbolAddress((void**)&ohi,  g_Ohi);  cudaGetSymbolAddress((void**)&olo,  g_Olo);

    cudaFuncSetAttribute(qkv_gemm_kernel,
                         cudaFuncAttributeMaxDynamicSharedMemorySize, GEMM_SMEM);
    cudaFuncSetAttribute(wo_gemm_kernel,
                         cudaFuncAttributeMaxDynamicSharedMemorySize, GEMM_SMEM);
    cudaFuncSetAttribute(attn_mma_kernel,
                         cudaFuncAttributeMaxDynamicSharedMemorySize, ATT_SMEM);

    // 1) one fused split pass (x hi/lo fp16 + 4 weights fp16 hi)
    const int ntot4 = NX4 + 4 * NW4;   // 2097152
    split_all_kernel<<<ntot4 / 256, 256>>>(x, Wq, Wk, Wv, Wo,
                                           xhi, xlo, wqhi, wkhi, wvhi, wohi);

    // 2) fused QKV projection (+RoPE on Q,K)
    dim3 qkvgrid(3 * (Dm / BN), Mrows / BM);   // (24, 32)
    qkv_gemm_kernel<<<qkvgrid, 256, GEMM_SMEM>>>(xhi, xlo, wqhi, wkhi, wvhi,
                                                 qhi, qlo, khi, klo, vhi, vlo, pos);

    // 3) causal flash attention
    dim3 agrid(Sq / 128, Bsz * Hn);            // (16, 32)
    attn_mma_kernel<<<agrid, 256, ATT_SMEM>>>(qhi, qlo, khi, klo, vhi, vlo, ohi, olo);

    // 4) output projection
    dim3 wogrid(Dm / BN, Mrows / BM);          // (8, 32)
    wo_gemm_kernel<<<wogrid, 256, GEMM_SMEM>>>(ohi, olo, wohi, out);
}

// round 9
// speedup vs baseline: 3.8620x; 1.0655x over previous
#include <cuda_runtime.h>
#include <cuda_bf16.h>
#include <cuda_fp16.h>
#include <math.h>
#include <stdint.h>

// Problem constants (fixed by this dataset instance)
#define Bsz 2
#define Sq  2048
#define Dm  1024
#define Hn  16
#define Dk  64
#define Mrows (Bsz*Sq)   // 4096

// ---------------- scratch ----------------------------------------------------
__device__ __half g_xhi[Mrows*Dm], g_xlo[Mrows*Dm];        // x: fp16 hi/lo
__device__ __half g_wqhi[Dm*Dm];                            // weights: fp16 hi only
__device__ __half g_wkhi[Dm*Dm];
__device__ __half g_wvhi[Dm*Dm];
__device__ __half g_wohi[Dm*Dm];
__device__ __half g_Qhi[Mrows*Dm], g_Qlo[Mrows*Dm];        // [B,H,S,Dk] fp16 hi/lo
__device__ __half g_Khi[Mrows*Dm];                          // K: fp16 hi only
__device__ __half g_Vhi[Mrows*Dm];                          // V: fp16 hi only
__device__ __half g_Ohi[Mrows*Dm], g_Olo[Mrows*Dm];        // [B,S,D] fp16 hi/lo

// ================= small PTX wrappers (portable, compute_103-safe) ===========
__device__ __forceinline__ uint32_t smem_u32(const void* p) {
    uint32_t a;
    asm("{ .reg .u64 t; cvta.to.shared.u64 t, %1; cvt.u32.u64 %0, t; }"
        : "=r"(a) : "l"(p));
    return a;
}
__device__ __forceinline__ void ldsm_x4(uint32_t addr, uint32_t r[4]) {
    asm volatile("ldmatrix.sync.aligned.m8n8.x4.shared.b16 {%0,%1,%2,%3}, [%4];"
                 : "=r"(r[0]), "=r"(r[1]), "=r"(r[2]), "=r"(r[3]) : "r"(addr));
}
__device__ __forceinline__ void ldsm_x4t(uint32_t addr, uint32_t r[4]) {
    asm volatile("ldmatrix.sync.aligned.m8n8.x4.trans.shared.b16 {%0,%1,%2,%3}, [%4];"
                 : "=r"(r[0]), "=r"(r[1]), "=r"(r[2]), "=r"(r[3]) : "r"(addr));
}
__device__ __forceinline__ void mma_f16(float c[4], const uint32_t a[4],
                                        const uint32_t b[2]) {
    asm volatile(
        "mma.sync.aligned.m16n8k16.row.col.f32.f16.f16.f32 "
        "{%0,%1,%2,%3}, {%4,%5,%6,%7}, {%8,%9}, {%0,%1,%2,%3};"
        : "+f"(c[0]), "+f"(c[1]), "+f"(c[2]), "+f"(c[3])
        : "r"(a[0]), "r"(a[1]), "r"(a[2]), "r"(a[3]), "r"(b[0]), "r"(b[1]));
}
__device__ __forceinline__ void cp16(uint32_t smem_addr, const void* gptr) {
    asm volatile("cp.async.cg.shared.global [%0], [%1], 16;"
                 :: "r"(smem_addr), "l"(gptr) : "memory");
}
#define CP_COMMIT() asm volatile("cp.async.commit_group;" ::: "memory")
#define CP_WAIT(n)  asm volatile("cp.async.wait_group %0;" :: "n"(n) : "memory")

__device__ __forceinline__ float hf_round(float x) {
    return __half2float(__float2half_rn(x));
}
__device__ __forceinline__ uint32_t pack_hf2(float x, float y) {
    __half2 t = __floats2half2_rn(x, y);
    return *reinterpret_cast<uint32_t*>(&t);
}

// ================= fused split pass ==========================================
// x -> fp16 hi/lo ; weights -> fp16 hi only
#define NX4 (Mrows*Dm/4)    // 1048576
#define NW4 (Dm*Dm/4)       // 262144
__global__ void __launch_bounds__(256)
split_all_kernel(const float* __restrict__ x,  const float* __restrict__ Wq,
                 const float* __restrict__ Wk, const float* __restrict__ Wv,
                 const float* __restrict__ Wo,
                 __half* __restrict__ xhi,  __half* __restrict__ xlo,
                 __half* __restrict__ wqhi, __half* __restrict__ wkhi,
                 __half* __restrict__ wvhi, __half* __restrict__ wohi)
{
    int i = blockIdx.x * 256 + threadIdx.x;
    if (i < NX4) {
        float4 v = reinterpret_cast<const float4*>(x)[i];
        uint2 h = make_uint2(pack_hf2(v.x, v.y), pack_hf2(v.z, v.w));
        uint2 l = make_uint2(pack_hf2(v.x - hf_round(v.x), v.y - hf_round(v.y)),
                             pack_hf2(v.z - hf_round(v.z), v.w - hf_round(v.w)));
        reinterpret_cast<uint2*>(xhi)[i] = h;
        reinterpret_cast<uint2*>(xlo)[i] = l;
    } else {
        int t = (i - NX4) >> 18;            // which weight (NW4 = 2^18)
        int j = (i - NX4) & (NW4 - 1);
        const float* src; __half* hi;
        if      (t == 0) { src = Wq; hi = wqhi; }
        else if (t == 1) { src = Wk; hi = wkhi; }
        else if (t == 2) { src = Wv; hi = wvhi; }
        else             { src = Wo; hi = wohi; }
        float4 v = reinterpret_cast<const float4*>(src)[j];
        reinterpret_cast<uint2*>(hi)[j] =
            make_uint2(pack_hf2(v.x, v.y), pack_hf2(v.z, v.w));
    }
}

// ================= shared GEMM machinery (fp16 2-term) ========================
// C = A*B^T with A = Ahi+Alo (fp16 pair), B = Bhi (fp16).  D = Ahi*Bhi + Alo*Bhi
#define BM 128
#define BN 128
#define BK 32
#define KT_ITERS (Dm/BK)              // 32
#define TPITCH 80
#define TILE_BYTES (128*TPITCH)        // 10240
#define STAGE_BYTES (3*TILE_BYTES)     // Ahi|Alo|Bhi = 30720
#define NSTAGE 3
#define GEMM_SMEM (NSTAGE*STAGE_BYTES) // 92160  (2 CTAs/SM fit)

struct GemmCore {
    uint32_t sbase;
    int lane, warp_m, warp_n, m0, n0;
    const __half *Ahi, *Alo, *Bhi;
    int r0a, c0, r1a;

    __device__ __forceinline__ void issue_stage(int stage, int kt) {
        const int kc = kt * BK;
        const uint32_t sb = sbase + stage * STAGE_BYTES;
        const __half* gsrc[3] = {Ahi, Alo, Bhi};
        #pragma unroll
        for (int t = 0; t < 3; t++) {
            const int row0 = (t < 2) ? m0 : n0;
            const __half* g = gsrc[t];
            cp16(sb + t * TILE_BYTES + (uint32_t)(r0a * TPITCH + c0 * 16),
                 g + (size_t)(row0 + r0a) * Dm + kc + c0 * 8);
            cp16(sb + t * TILE_BYTES + (uint32_t)(r1a * TPITCH + c0 * 16),
                 g + (size_t)(row0 + r1a) * Dm + kc + c0 * 8);
        }
        CP_COMMIT();
    }

    __device__ __forceinline__ void mainloop(float acc[4][4][4]) {
        issue_stage(0, 0);
        issue_stage(1, 1);
        for (int kt = 0; kt < KT_ITERS; kt++) {
            if (kt + 1 < KT_ITERS) { CP_WAIT(1); } else { CP_WAIT(0); }
            __syncthreads();
            if (kt + 2 < KT_ITERS) issue_stage((kt + 2) % NSTAGE, kt + 2);

            const uint32_t sb = sbase + (kt % NSTAGE) * STAGE_BYTES;
            const uint32_t sAhi = sb;
            const uint32_t sAlo = sb + TILE_BYTES;
            const uint32_t sBhi = sb + 2 * TILE_BYTES;

            #pragma unroll
            for (int ks = 0; ks < 2; ks++) {
                const int chunk = ks * 2;
                uint32_t bhi[4][2];
                #pragma unroll
                for (int pr = 0; pr < 2; pr++) {     // paired x4: 2 n-tiles per ld
                    uint32_t tmp[4];
                    const int brow = warp_n * 32 + pr * 16 + (lane & 15);
                    const uint32_t boff = (uint32_t)(brow * TPITCH + (chunk + (lane >> 4)) * 16);
                    ldsm_x4(sBhi + boff, tmp);
                    bhi[2*pr  ][0] = tmp[0]; bhi[2*pr+1][0] = tmp[1];
                    bhi[2*pr  ][1] = tmp[2]; bhi[2*pr+1][1] = tmp[3];
                }
                #pragma unroll
                for (int mt = 0; mt < 4; mt++) {
                    uint32_t ahi[4], alo[4];
                    const int arow = warp_m * 64 + mt * 16 + (lane & 15);
                    const uint32_t aoff = (uint32_t)(arow * TPITCH + (chunk + (lane >> 4)) * 16);
                    ldsm_x4(sAhi + aoff, ahi);
                    ldsm_x4(sAlo + aoff, alo);
                    #pragma unroll
                    for (int nt = 0; nt < 4; nt++) {
                        mma_f16(acc[mt][nt], ahi, bhi[nt]);
                        mma_f16(acc[mt][nt], alo, bhi[nt]);
                    }
                }
            }
        }
    }
};

// ---- fused QKV GEMM: one launch computes Q, K, V projections -----------------
__global__ void __launch_bounds__(256, 2)
qkv_gemm_kernel(const __half* __restrict__ xhi, const __half* __restrict__ xlo,
                const __half* __restrict__ wqhi, const __half* __restrict__ wkhi,
                const __half* __restrict__ wvhi,
                __half* __restrict__ qhi, __half* __restrict__ qlo,
                __half* __restrict__ khi, __half* __restrict__ vhi,
                const int* __restrict__ pos)
{
    extern __shared__ char sm[];
    const int tid  = threadIdx.x;
    const int wsel = blockIdx.x >> 3;

    GemmCore gc;
    gc.sbase = smem_u32(sm);
    gc.lane = tid & 31;
    gc.warp_m = (tid >> 5) & 1; gc.warp_n = tid >> 6;
    gc.n0 = (blockIdx.x & 7) * BN;
    gc.m0 = blockIdx.y * BM;
    gc.Ahi = xhi; gc.Alo = xlo;
    gc.r0a = tid >> 2; gc.c0 = tid & 3; gc.r1a = (tid + 256) >> 2;

    __half *Chi, *Clo;
    bool rope, storelo;
    if (wsel == 0)      { gc.Bhi = wqhi; Chi = qhi; Clo = qlo; rope = true;  storelo = true;  }
    else if (wsel == 1) { gc.Bhi = wkhi; Chi = khi; Clo = qlo; rope = true;  storelo = false; }
    else                { gc.Bhi = wvhi; Chi = vhi; Clo = qlo; rope = false; storelo = false; }

    float acc[4][4][4];
    #pragma unroll
    for (int i = 0; i < 4; i++)
        #pragma unroll
        for (int j = 0; j < 4; j++)
            #pragma unroll
            for (int v = 0; v < 4; v++) acc[i][j][v] = 0.f;

    gc.mainloop(acc);

    // epilogue: fused RoPE + fp16 store to [B,H,S,Dk] (hi always, lo for Q only)
    const int lane = gc.lane;
    #pragma unroll
    for (int mt = 0; mt < 4; mt++) {
        #pragma unroll
        for (int half = 0; half < 2; half++) {
            const int row = gc.m0 + gc.warp_m * 64 + mt * 16 + (lane >> 2) + half * 8;
            const int b = row >> 11;
            const int s = row & (Sq - 1);
            float p = rope ? (float)pos[row] : 0.f;
            #pragma unroll
            for (int nt = 0; nt < 4; nt++) {
                const int col = gc.n0 + gc.warp_n * 32 + nt * 8 + (lane & 3) * 2;  // even
                float e = acc[mt][nt][half * 2];
                float o = acc[mt][nt][half * 2 + 1];
                if (rope) {
                    const int dk = col & (Dk - 1);
                    const float inv = exp2f((float)dk * (-13.287712379549449f / 64.0f));
                    float sn, cs;
                    sincosf(p * inv, &sn, &cs);
                    const float re = e * cs - o * sn;
                    const float ro = e * sn + o * cs;
                    e = re; o = ro;
                }
                const int h  = col >> 6;
                const int dk = col & (Dk - 1);
                const size_t idx = ((size_t)(b * Hn + h) * Sq + s) * Dk + dk;
                *reinterpret_cast<uint32_t*>(Chi + idx) = pack_hf2(e, o);
                if (storelo)
                    *reinterpret_cast<uint32_t*>(Clo + idx) =
                        pack_hf2(e - hf_round(e), o - hf_round(o));
            }
        }
    }
}

// ---- output projection GEMM: fp32 out ----------------------------------------
__global__ void __launch_bounds__(256, 2)
wo_gemm_kernel(const __half* __restrict__ Ahi, const __half* __restrict__ Alo,
               const __half* __restrict__ Bhi, float* __restrict__ C)
{
    extern __shared__ char sm[];
    const int tid = threadIdx.x;

    GemmCore gc;
    gc.sbase = smem_u32(sm);
    gc.lane = tid & 31;
    gc.warp_m = (tid >> 5) & 1; gc.warp_n = tid >> 6;
    gc.n0 = blockIdx.x * BN;
    gc.m0 = blockIdx.y * BM;
    gc.Ahi = Ahi; gc.Alo = Alo; gc.Bhi = Bhi;
    gc.r0a = tid >> 2; gc.c0 = tid & 3; gc.r1a = (tid + 256) >> 2;

    float acc[4][4][4];
    #pragma unroll
    for (int i = 0; i < 4; i++)
        #pragma unroll
        for (int j = 0; j < 4; j++)
            #pragma unroll
            for (int v = 0; v < 4; v++) acc[i][j][v] = 0.f;

    gc.mainloop(acc);

    const int lane = gc.lane;
    #pragma unroll
    for (int mt = 0; mt < 4; mt++) {
        #pragma unroll
        for (int half = 0; half < 2; half++) {
            const int row = gc.m0 + gc.warp_m * 64 + mt * 16 + (lane >> 2) + half * 8;
            #pragma unroll
            for (int nt = 0; nt < 4; nt++) {
                const int col = gc.n0 + gc.warp_n * 32 + nt * 8 + (lane & 3) * 2;
                float* dst = C + (size_t)row * Dm + col;
                *reinterpret_cast<float2*>(dst) =
                    make_float2(acc[mt][nt][half * 2], acc[mt][nt][half * 2 + 1]);
            }
        }
    }
}

// ================= tensor-core causal flash attention (fp16 2-term) ===========
// S = (Qhi+Qlo)*Khi   (K fp16-rounded);  O += (Phi+Plo)*Vhi  (V fp16-rounded)
#define ATPITCH 144
#define AT_TILE (64*ATPITCH)          // 9216
#define AT_STAGE (2*AT_TILE)          // Khi|Vhi = 18432
#define ATT_SMEM (2*AT_STAGE)         // 36864  (2 stages; 2 CTAs/SM easily)

__global__ void __launch_bounds__(256, 2)
attn_mma_kernel(const __half* __restrict__ Qhi, const __half* __restrict__ Qlo,
                const __half* __restrict__ Khi, const __half* __restrict__ Vhi,
                __half* __restrict__ Ohi, __half* __restrict__ Olo)
{
    extern __shared__ char sm[];
    const uint32_t sbase = smem_u32(sm);

    const int tid  = threadIdx.x;
    const int lane = tid & 31;
    const int w    = tid >> 5;
    const int bh   = blockIdx.y;
    const int qt   = (int)gridDim.x - 1 - (int)blockIdx.x;   // big tiles first
    const int q0   = qt * 128;
    const int NT   = 2 * qt + 2;                             // key tiles (64 each)

    const size_t kvbase = (size_t)bh * Sq;

    // --- Q fragments (direct gmem gather, once) ------------------------------
    const int r  = q0 + w * 16 + (lane >> 2);
    const int dc = 2 * (lane & 3);
    uint32_t qh[4][4], ql[4][4];
    #pragma unroll
    for (int c = 0; c < 4; c++) {
        const int d = c * 16 + dc;
        const size_t i00 = (kvbase + r) * Dk + d;
        const size_t i10 = (kvbase + r + 8) * Dk + d;
        qh[c][0] = *reinterpret_cast<const uint32_t*>(Qhi + i00);
        qh[c][1] = *reinterpret_cast<const uint32_t*>(Qhi + i10);
        qh[c][2] = *reinterpret_cast<const uint32_t*>(Qhi + i00 + 8);
        qh[c][3] = *reinterpret_cast<const uint32_t*>(Qhi + i10 + 8);
        ql[c][0] = *reinterpret_cast<const uint32_t*>(Qlo + i00);
        ql[c][1] = *reinterpret_cast<const uint32_t*>(Qlo + i10);
        ql[c][2] = *reinterpret_cast<const uint32_t*>(Qlo + i00 + 8);
        ql[c][3] = *reinterpret_cast<const uint32_t*>(Qlo + i10 + 8);
    }

    const __half* gkv[2] = {Khi, Vhi};
    auto issue_kv = [&](int stage, int it) {
        const int k0 = it * 64;
        const uint32_t sb = sbase + stage * AT_STAGE;
        #pragma unroll
        for (int i = 0; i < 4; i++) {
            const int c = tid + i * 256;          // 0..1023
            const int t = c >> 9;                 // tile 0..1
            const int rr = (c >> 3) & 63;         // row 0..63
            const int cl = c & 7;                 // 16B chunk 0..7
            cp16(sb + t * AT_TILE + (uint32_t)(rr * ATPITCH + cl * 16),
                 gkv[t] + (kvbase + k0 + rr) * Dk + cl * 8);
        }
        CP_COMMIT();
    };

    float o[8][4];
    #pragma unroll
    for (int nt = 0; nt < 8; nt++)
        #pragma unroll
        for (int j = 0; j < 4; j++) o[nt][j] = 0.f;
    float m0 = -1e30f, m1 = -1e30f, l0 = 0.f, l1 = 0.f;

    issue_kv(0, 0);
    issue_kv(1, 1);

    const float SCL = 0.125f * 1.4426950408889634f;  // scale * log2(e)

    for (int it = 0; it < NT; it++) {
        if (it + 1 < NT) { CP_WAIT(1); } else { CP_WAIT(0); }
        __syncthreads();

        const uint32_t sb  = sbase + (it & 1) * AT_STAGE;
        const uint32_t sKh = sb;
        const uint32_t sVh = sb + AT_TILE;
        const int k0 = it * 64;

        // ---- S = Q K^T (Q exact, K fp16) -------------------------------------
        float s[8][4];
        #pragma unroll
        for (int nt = 0; nt < 8; nt++)
            #pragma unroll
            for (int j = 0; j < 4; j++) s[nt][j] = 0.f;

        #pragma unroll
        for (int c = 0; c < 4; c++) {
            uint32_t kh[8][2];
            #pragma unroll
            for (int pr = 0; pr < 4; pr++) {     // paired x4: 2 n-tiles per ld
                uint32_t tmp[4];
                const uint32_t boff =
                    (uint32_t)((pr * 16 + (lane & 15)) * ATPITCH + (c * 2 + (lane >> 4)) * 16);
                ldsm_x4(sKh + boff, tmp);
                kh[2*pr  ][0] = tmp[0]; kh[2*pr+1][0] = tmp[1];
                kh[2*pr  ][1] = tmp[2]; kh[2*pr+1][1] = tmp[3];
            }
            #pragma unroll
            for (int nt = 0; nt < 8; nt++) {
                mma_f16(s[nt], qh[c], kh[nt]);
                mma_f16(s[nt], ql[c], kh[nt]);
            }
        }

        // ---- online softmax (exp2 domain) ------------------------------------
        const bool need_mask = (k0 + 63 > q0);
        float t0 = -1e30f, t1 = -1e30f;
        #pragma unroll
        for (int nt = 0; nt < 8; nt++) {
            #pragma unroll
            for (int j = 0; j < 4; j++) {
                float t = s[nt][j] * SCL;
                if (need_mask) {
                    const int col = k0 + nt * 8 + dc + (j & 1);
                    const int row = (j < 2) ? r : r + 8;
                    if (col > row) t = -1e30f;
                }
                s[nt][j] = t;
                if (j < 2) t0 = fmaxf(t0, t); else t1 = fmaxf(t1, t);
            }
        }
        t0 = fmaxf(t0, __shfl_xor_sync(0xffffffffu, t0, 1));
        t0 = fmaxf(t0, __shfl_xor_sync(0xffffffffu, t0, 2));
        t1 = fmaxf(t1, __shfl_xor_sync(0xffffffffu, t1, 1));
        t1 = fmaxf(t1, __shfl_xor_sync(0xffffffffu, t1, 2));
        const float mn0 = fmaxf(m0, t0), mn1 = fmaxf(m1, t1);
        const float corr0 = exp2f(m0 - mn0), corr1 = exp2f(m1 - mn1);
        m0 = mn0; m1 = mn1;

        float ps0 = 0.f, ps1 = 0.f;
        #pragma unroll
        for (int nt = 0; nt < 8; nt++) {
            s[nt][0] = exp2f(s[nt][0] - m0);
            s[nt][1] = exp2f(s[nt][1] - m0);
            s[nt][2] = exp2f(s[nt][2] - m1);
            s[nt][3] = exp2f(s[nt][3] - m1);
            ps0 += s[nt][0] + s[nt][1];
            ps1 += s[nt][2] + s[nt][3];
        }
        ps0 += __shfl_xor_sync(0xffffffffu, ps0, 1);
        ps0 += __shfl_xor_sync(0xffffffffu, ps0, 2);
        ps1 += __shfl_xor_sync(0xffffffffu, ps1, 1);
        ps1 += __shfl_xor_sync(0xffffffffu, ps1, 2);
        l0 = l0 * corr0 + ps0;
        l1 = l1 * corr1 + ps1;

        #pragma unroll
        for (int nt = 0; nt < 8; nt++) {
            o[nt][0] *= corr0; o[nt][1] *= corr0;
            o[nt][2] *= corr1; o[nt][3] *= corr1;
        }

        // ---- O += P V (P exact fp16 pair, V fp16) -----------------------------
        #pragma unroll
        for (int u = 0; u < 4; u++) {
            uint32_t aph[4], apl[4];
            {
                const float p00 = s[2*u][0],   p01 = s[2*u][1];
                const float p02 = s[2*u][2],   p03 = s[2*u][3];
                const float p10 = s[2*u+1][0], p11 = s[2*u+1][1];
                const float p12 = s[2*u+1][2], p13 = s[2*u+1][3];
                aph[0] = pack_hf2(p00, p01);
                aph[1] = pack_hf2(p02, p03);
                aph[2] = pack_hf2(p10, p11);
                aph[3] = pack_hf2(p12, p13);
                apl[0] = pack_hf2(p00 - hf_round(p00), p01 - hf_round(p01));
                apl[1] = pack_hf2(p02 - hf_round(p02), p03 - hf_round(p03));
                apl[2] = pack_hf2(p10 - hf_round(p10), p11 - hf_round(p11));
                apl[3] = pack_hf2(p12 - hf_round(p12), p13 - hf_round(p13));
            }
            uint32_t vh[8][2];
            #pragma unroll
            for (int pr = 0; pr < 4; pr++) {     // paired x4 trans: 2 n-tiles per ld
                uint32_t tmp[4];
                const uint32_t voff =
                    (uint32_t)((u * 16 + (lane & 15)) * ATPITCH + (2 * pr + (lane >> 4)) * 16);
                ldsm_x4t(sVh + voff, tmp);
                vh[2*pr  ][0] = tmp[0]; vh[2*pr  ][1] = tmp[1];
                vh[2*pr+1][0] = tmp[2]; vh[2*pr+1][1] = tmp[3];
            }
            #pragma unroll
            for (int nt = 0; nt < 8; nt++) {
                mma_f16(o[nt], aph, vh[nt]);
                mma_f16(o[nt], apl, vh[nt]);
            }
        }

        if (it + 2 < NT) {
            __syncthreads();          // stage (it&1) fully consumed
            issue_kv(it & 1, it + 2); // lands during compute(it+1)
        }
    }

    // ---- epilogue: normalize, split fp16 hi/lo, write [B,S,D] ----------------
    const float inv0 = 1.0f / l0, inv1 = 1.0f / l1;
    const int b = bh >> 4, h = bh & 15;
    const size_t base0 = ((size_t)b * Sq + r) * Dm + h * Dk;
    const size_t base1 = ((size_t)b * Sq + r + 8) * Dm + h * Dk;
    #pragma unroll
    for (int nt = 0; nt < 8; nt++) {
        const int col = nt * 8 + dc;
        const float v0 = o[nt][0] * inv0, v1 = o[nt][1] * inv0;
        const float v2 = o[nt][2] * inv1, v3 = o[nt][3] * inv1;
        *reinterpret_cast<uint32_t*>(Ohi + base0 + col) = pack_hf2(v0, v1);
        *reinterpret_cast<uint32_t*>(Olo + base0 + col) =
            pack_hf2(v0 - hf_round(v0), v1 - hf_round(v1));
        *reinterpret_cast<uint32_t*>(Ohi + base1 + col) = pack_hf2(v2, v3);
        *reinterpret_cast<uint32_t*>(Olo + base1 + col) =
            pack_hf2(v2 - hf_round(v2), v3 - hf_round(v3));
    }
}

// ---------------- launch -----------------------------------------------------
extern "C" void kernel_launch(void* const* d_in, const int* in_sizes, int n_in,
                              void* d_out, int out_size)
{
    const float* x   = (const float*)d_in[0];
    const float* Wq  = (const float*)d_in[1];
    const float* Wk  = (const float*)d_in[2];
    const float* Wv  = (const float*)d_in[3];
    const float* Wo  = (const float*)d_in[4];
    const int*   pos = (const int*)d_in[5];
    float* out = (float*)d_out;

    __half *xhi, *xlo, *wqhi, *wkhi, *wvhi, *wohi;
    __half *qhi, *qlo, *khi, *vhi, *ohi, *olo;
    cudaGetSymbolAddress((void**)&xhi,  g_xhi);  cudaGetSymbolAddress((void**)&xlo,  g_xlo);
    cudaGetSymbolAddress((void**)&wqhi, g_wqhi);
    cudaGetSymbolAddress((void**)&wkhi, g_wkhi);
    cudaGetSymbolAddress((void**)&wvhi, g_wvhi);
    cudaGetSymbolAddress((void**)&wohi, g_wohi);
    cudaGetSymbolAddress((void**)&qhi,  g_Qhi);  cudaGetSymbolAddress((void**)&qlo,  g_Qlo);
    cudaGetSymbolAddress((void**)&khi,  g_Khi);
    cudaGetSymbolAddress((void**)&vhi,  g_Vhi);
    cudaGetSymbolAddress((void**)&ohi,  g_Ohi);  cudaGetSymbolAddress((void**)&olo,  g_Olo);

    cudaFuncSetAttribute(qkv_gemm_kernel,
                         cudaFuncAttributeMaxDynamicSharedMemorySize, GEMM_SMEM);
    cudaFuncSetAttribute(wo_gemm_kernel,
                         cudaFuncAttributeMaxDynamicSharedMemorySize, GEMM_SMEM);
    cudaFuncSetAttribute(attn_mma_kernel,
                         cudaFuncAttributeMaxDynamicSharedMemorySize, ATT_SMEM);

    // 1) one fused split pass (x hi/lo fp16 + 4 weights fp16 hi)
    const int ntot4 = NX4 + 4 * NW4;   // 2097152
    split_all_kernel<<<ntot4 / 256, 256>>>(x, Wq, Wk, Wv, Wo,
                                           xhi, xlo, wqhi, wkhi, wvhi, wohi);

    // 2) fused QKV projection (+RoPE on Q,K)
    dim3 qkvgrid(3 * (Dm / BN), Mrows / BM);   // (24, 32)
    qkv_gemm_kernel<<<qkvgrid, 256, GEMM_SMEM>>>(xhi, xlo, wqhi, wkhi, wvhi,
                                                 qhi, qlo, khi, vhi, pos);

    // 3) causal flash attention
    dim3 agrid(Sq / 128, Bsz * Hn);            // (16, 32)
    attn_mma_kernel<<<agrid, 256, ATT_SMEM>>>(qhi, qlo, khi, vhi, ohi, olo);

    // 4) output projection
    dim3 wogrid(Dm / BN, Mrows / BM);          // (8, 32)
    wo_gemm_kernel<<<wogrid, 256, GEMM_SMEM>>>(ohi, olo, wohi, out);
}

// round 10
// speedup vs baseline: 4.1330x; 1.0702x over previous
#include <cuda_runtime.h>
#include <cuda_bf16.h>
#include <cuda_fp16.h>
#include <math.h>
#include <stdint.h>

// Problem constants (fixed by this dataset instance)
#define Bsz 2
#define Sq  2048
#define Dm  1024
#define Hn  16
#define Dk  64
#define Mrows (Bsz*Sq)   // 4096

// ---------------- scratch ----------------------------------------------------
__device__ __half g_xhi[Mrows*Dm], g_xlo[Mrows*Dm];        // x: fp16 hi/lo
__device__ __half g_wqhi[Dm*Dm];                            // weights: fp16 hi only
__device__ __half g_wkhi[Dm*Dm];
__device__ __half g_wvhi[Dm*Dm];
__device__ __half g_wohi[Dm*Dm];
__device__ __half g_Qhi[Mrows*Dm], g_Qlo[Mrows*Dm];        // [B,H,S,Dk] fp16 hi/lo
__device__ __half g_Khi[Mrows*Dm];                          // K: fp16 hi only
__device__ __half g_Vhi[Mrows*Dm];                          // V: fp16 hi only
__device__ __half g_Ohi[Mrows*Dm], g_Olo[Mrows*Dm];        // [B,S,D] fp16 hi/lo

// ================= small PTX wrappers (portable, compute_103-safe) ===========
__device__ __forceinline__ uint32_t smem_u32(const void* p) {
    uint32_t a;
    asm("{ .reg .u64 t; cvta.to.shared.u64 t, %1; cvt.u32.u64 %0, t; }"
        : "=r"(a) : "l"(p));
    return a;
}
__device__ __forceinline__ void ldsm_x4(uint32_t addr, uint32_t r[4]) {
    asm volatile("ldmatrix.sync.aligned.m8n8.x4.shared.b16 {%0,%1,%2,%3}, [%4];"
                 : "=r"(r[0]), "=r"(r[1]), "=r"(r[2]), "=r"(r[3]) : "r"(addr));
}
__device__ __forceinline__ void ldsm_x2(uint32_t addr, uint32_t r[2]) {
    asm volatile("ldmatrix.sync.aligned.m8n8.x2.shared.b16 {%0,%1}, [%2];"
                 : "=r"(r[0]), "=r"(r[1]) : "r"(addr));
}
__device__ __forceinline__ void ldsm_x2t(uint32_t addr, uint32_t r[2]) {
    asm volatile("ldmatrix.sync.aligned.m8n8.x2.trans.shared.b16 {%0,%1}, [%2];"
                 : "=r"(r[0]), "=r"(r[1]) : "r"(addr));
}
__device__ __forceinline__ void mma_f16(float c[4], const uint32_t a[4],
                                        const uint32_t b[2]) {
    asm volatile(
        "mma.sync.aligned.m16n8k16.row.col.f32.f16.f16.f32 "
        "{%0,%1,%2,%3}, {%4,%5,%6,%7}, {%8,%9}, {%0,%1,%2,%3};"
        : "+f"(c[0]), "+f"(c[1]), "+f"(c[2]), "+f"(c[3])
        : "r"(a[0]), "r"(a[1]), "r"(a[2]), "r"(a[3]), "r"(b[0]), "r"(b[1]));
}
__device__ __forceinline__ void cp16(uint32_t smem_addr, const void* gptr) {
    asm volatile("cp.async.cg.shared.global [%0], [%1], 16;"
                 :: "r"(smem_addr), "l"(gptr) : "memory");
}
#define CP_COMMIT() asm volatile("cp.async.commit_group;" ::: "memory")
#define CP_WAIT(n)  asm volatile("cp.async.wait_group %0;" :: "n"(n) : "memory")

__device__ __forceinline__ float hf_round(float x) {
    return __half2float(__float2half_rn(x));
}
__device__ __forceinline__ uint32_t pack_hf2(float x, float y) {
    __half2 t = __floats2half2_rn(x, y);
    return *reinterpret_cast<uint32_t*>(&t);
}

// ================= fused split pass ==========================================
// x -> fp16 hi/lo ; weights -> fp16 hi only
#define NX4 (Mrows*Dm/4)    // 1048576
#define NW4 (Dm*Dm/4)       // 262144
__global__ void __launch_bounds__(256)
split_all_kernel(const float* __restrict__ x,  const float* __restrict__ Wq,
                 const float* __restrict__ Wk, const float* __restrict__ Wv,
                 const float* __restrict__ Wo,
                 __half* __restrict__ xhi,  __half* __restrict__ xlo,
                 __half* __restrict__ wqhi, __half* __restrict__ wkhi,
                 __half* __restrict__ wvhi, __half* __restrict__ wohi)
{
    int i = blockIdx.x * 256 + threadIdx.x;
    if (i < NX4) {
        float4 v = reinterpret_cast<const float4*>(x)[i];
        uint2 h = make_uint2(pack_hf2(v.x, v.y), pack_hf2(v.z, v.w));
        uint2 l = make_uint2(pack_hf2(v.x - hf_round(v.x), v.y - hf_round(v.y)),
                             pack_hf2(v.z - hf_round(v.z), v.w - hf_round(v.w)));
        reinterpret_cast<uint2*>(xhi)[i] = h;
        reinterpret_cast<uint2*>(xlo)[i] = l;
    } else {
        int t = (i - NX4) >> 18;            // which weight (NW4 = 2^18)
        int j = (i - NX4) & (NW4 - 1);
        const float* src; __half* hi;
        if      (t == 0) { src = Wq; hi = wqhi; }
        else if (t == 1) { src = Wk; hi = wkhi; }
        else if (t == 2) { src = Wv; hi = wvhi; }
        else             { src = Wo; hi = wohi; }
        float4 v = reinterpret_cast<const float4*>(src)[j];
        reinterpret_cast<uint2*>(hi)[j] =
            make_uint2(pack_hf2(v.x, v.y), pack_hf2(v.z, v.w));
    }
}

// ================= shared GEMM machinery (fp16 2-term) ========================
// C = A*B^T with A = Ahi+Alo (fp16 pair), B = Bhi (fp16).  D = Ahi*Bhi + Alo*Bhi
#define BM 128
#define BN 128
#define BK 32
#define KT_ITERS (Dm/BK)              // 32
#define TPITCH 80
#define TILE_BYTES (128*TPITCH)        // 10240
#define STAGE_BYTES (3*TILE_BYTES)     // Ahi|Alo|Bhi = 30720
#define NSTAGE 3
#define GEMM_SMEM (NSTAGE*STAGE_BYTES) // 92160  (2 CTAs/SM fit)

struct GemmCore {
    uint32_t sbase;
    int lane, warp_m, warp_n, m0, n0;
    const __half *Ahi, *Alo, *Bhi;
    int r0a, c0, r1a;

    __device__ __forceinline__ void issue_stage(int stage, int kt) {
        const int kc = kt * BK;
        const uint32_t sb = sbase + stage * STAGE_BYTES;
        const __half* gsrc[3] = {Ahi, Alo, Bhi};
        #pragma unroll
        for (int t = 0; t < 3; t++) {
            const int row0 = (t < 2) ? m0 : n0;
            const __half* g = gsrc[t];
            cp16(sb + t * TILE_BYTES + (uint32_t)(r0a * TPITCH + c0 * 16),
                 g + (size_t)(row0 + r0a) * Dm + kc + c0 * 8);
            cp16(sb + t * TILE_BYTES + (uint32_t)(r1a * TPITCH + c0 * 16),
                 g + (size_t)(row0 + r1a) * Dm + kc + c0 * 8);
        }
        CP_COMMIT();
    }

    __device__ __forceinline__ void mainloop(float acc[4][4][4]) {
        issue_stage(0, 0);
        issue_stage(1, 1);
        for (int kt = 0; kt < KT_ITERS; kt++) {
            if (kt + 1 < KT_ITERS) { CP_WAIT(1); } else { CP_WAIT(0); }
            __syncthreads();
            if (kt + 2 < KT_ITERS) issue_stage((kt + 2) % NSTAGE, kt + 2);

            const uint32_t sb = sbase + (kt % NSTAGE) * STAGE_BYTES;
            const uint32_t sAhi = sb;
            const uint32_t sAlo = sb + TILE_BYTES;
            const uint32_t sBhi = sb + 2 * TILE_BYTES;

            #pragma unroll
            for (int ks = 0; ks < 2; ks++) {
                const int chunk = ks * 2;
                uint32_t bhi[4][2];
                #pragma unroll
                for (int nt = 0; nt < 4; nt++) {      // direct x2 loads (no unpack MOVs)
                    const int brow = warp_n * 32 + nt * 8 + (lane & 7);
                    const uint32_t boff = (uint32_t)(brow * TPITCH + (chunk + ((lane >> 3) & 1)) * 16);
                    ldsm_x2(sBhi + boff, bhi[nt]);
                }
                #pragma unroll
                for (int mt = 0; mt < 4; mt++) {
                    uint32_t ahi[4], alo[4];
                    const int arow = warp_m * 64 + mt * 16 + (lane & 15);
                    const uint32_t aoff = (uint32_t)(arow * TPITCH + (chunk + (lane >> 4)) * 16);
                    ldsm_x4(sAhi + aoff, ahi);
                    ldsm_x4(sAlo + aoff, alo);
                    #pragma unroll
                    for (int nt = 0; nt < 4; nt++) {
                        mma_f16(acc[mt][nt], ahi, bhi[nt]);
                        mma_f16(acc[mt][nt], alo, bhi[nt]);
                    }
                }
            }
        }
    }
};

// ---- fused QKV GEMM: one launch computes Q, K, V projections -----------------
__global__ void __launch_bounds__(256, 2)
qkv_gemm_kernel(const __half* __restrict__ xhi, const __half* __restrict__ xlo,
                const __half* __restrict__ wqhi, const __half* __restrict__ wkhi,
                const __half* __restrict__ wvhi,
                __half* __restrict__ qhi, __half* __restrict__ qlo,
                __half* __restrict__ khi, __half* __restrict__ vhi,
                const int* __restrict__ pos)
{
    extern __shared__ char sm[];
    const int tid  = threadIdx.x;
    const int wsel = blockIdx.x >> 3;

    GemmCore gc;
    gc.sbase = smem_u32(sm);
    gc.lane = tid & 31;
    gc.warp_m = (tid >> 5) & 1; gc.warp_n = tid >> 6;
    gc.n0 = (blockIdx.x & 7) * BN;
    gc.m0 = blockIdx.y * BM;
    gc.Ahi = xhi; gc.Alo = xlo;
    gc.r0a = tid >> 2; gc.c0 = tid & 3; gc.r1a = (tid + 256) >> 2;

    __half *Chi, *Clo;
    bool rope, storelo;
    if (wsel == 0)      { gc.Bhi = wqhi; Chi = qhi; Clo = qlo; rope = true;  storelo = true;  }
    else if (wsel == 1) { gc.Bhi = wkhi; Chi = khi; Clo = qlo; rope = true;  storelo = false; }
    else                { gc.Bhi = wvhi; Chi = vhi; Clo = qlo; rope = false; storelo = false; }

    float acc[4][4][4];
    #pragma unroll
    for (int i = 0; i < 4; i++)
        #pragma unroll
        for (int j = 0; j < 4; j++)
            #pragma unroll
            for (int v = 0; v < 4; v++) acc[i][j][v] = 0.f;

    gc.mainloop(acc);

    // epilogue: fused RoPE + fp16 store to [B,H,S,Dk] (hi always, lo for Q only)
    const int lane = gc.lane;
    #pragma unroll
    for (int mt = 0; mt < 4; mt++) {
        #pragma unroll
        for (int half = 0; half < 2; half++) {
            const int row = gc.m0 + gc.warp_m * 64 + mt * 16 + (lane >> 2) + half * 8;
            const int b = row >> 11;
            const int s = row & (Sq - 1);
            float p = rope ? (float)pos[row] : 0.f;
            #pragma unroll
            for (int nt = 0; nt < 4; nt++) {
                const int col = gc.n0 + gc.warp_n * 32 + nt * 8 + (lane & 3) * 2;  // even
                float e = acc[mt][nt][half * 2];
                float o = acc[mt][nt][half * 2 + 1];
                if (rope) {
                    const int dk = col & (Dk - 1);
                    const float inv = exp2f((float)dk * (-13.287712379549449f / 64.0f));
                    float sn, cs;
                    sincosf(p * inv, &sn, &cs);
                    const float re = e * cs - o * sn;
                    const float ro = e * sn + o * cs;
                    e = re; o = ro;
                }
                const int h  = col >> 6;
                const int dk = col & (Dk - 1);
                const size_t idx = ((size_t)(b * Hn + h) * Sq + s) * Dk + dk;
                *reinterpret_cast<uint32_t*>(Chi + idx) = pack_hf2(e, o);
                if (storelo)
                    *reinterpret_cast<uint32_t*>(Clo + idx) =
                        pack_hf2(e - hf_round(e), o - hf_round(o));
            }
        }
    }
}

// ---- output projection GEMM: fp32 out ----------------------------------------
__global__ void __launch_bounds__(256, 2)
wo_gemm_kernel(const __half* __restrict__ Ahi, const __half* __restrict__ Alo,
               const __half* __restrict__ Bhi, float* __restrict__ C)
{
    extern __shared__ char sm[];
    const int tid = threadIdx.x;

    GemmCore gc;
    gc.sbase = smem_u32(sm);
    gc.lane = tid & 31;
    gc.warp_m = (tid >> 5) & 1; gc.warp_n = tid >> 6;
    gc.n0 = blockIdx.x * BN;
    gc.m0 = blockIdx.y * BM;
    gc.Ahi = Ahi; gc.Alo = Alo; gc.Bhi = Bhi;
    gc.r0a = tid >> 2; gc.c0 = tid & 3; gc.r1a = (tid + 256) >> 2;

    float acc[4][4][4];
    #pragma unroll
    for (int i = 0; i < 4; i++)
        #pragma unroll
        for (int j = 0; j < 4; j++)
            #pragma unroll
            for (int v = 0; v < 4; v++) acc[i][j][v] = 0.f;

    gc.mainloop(acc);

    const int lane = gc.lane;
    #pragma unroll
    for (int mt = 0; mt < 4; mt++) {
        #pragma unroll
        for (int half = 0; half < 2; half++) {
            const int row = gc.m0 + gc.warp_m * 64 + mt * 16 + (lane >> 2) + half * 8;
            #pragma unroll
            for (int nt = 0; nt < 4; nt++) {
                const int col = gc.n0 + gc.warp_n * 32 + nt * 8 + (lane & 3) * 2;
                float* dst = C + (size_t)row * Dm + col;
                *reinterpret_cast<float2*>(dst) =
                    make_float2(acc[mt][nt][half * 2], acc[mt][nt][half * 2 + 1]);
            }
        }
    }
}

// ================= tensor-core causal flash attention (fp16 2-term) ===========
// S = (Qhi+Qlo)*Khi   (K fp16-rounded);  O += (Phi+Plo)*Vhi  (V fp16-rounded)
#define ATPITCH 144
#define AT_TILE (64*ATPITCH)          // 9216
#define AT_STAGE (2*AT_TILE)          // Khi|Vhi = 18432
#define ATT_SMEM (2*AT_STAGE)         // 36864  (2 stages; 2 CTAs/SM easily)

__global__ void __launch_bounds__(256, 2)
attn_mma_kernel(const __half* __restrict__ Qhi, const __half* __restrict__ Qlo,
                const __half* __restrict__ Khi, const __half* __restrict__ Vhi,
                __half* __restrict__ Ohi, __half* __restrict__ Olo)
{
    extern __shared__ char sm[];
    const uint32_t sbase = smem_u32(sm);

    const int tid  = threadIdx.x;
    const int lane = tid & 31;
    const int w    = tid >> 5;
    const int bh   = blockIdx.y;
    const int qt   = (int)gridDim.x - 1 - (int)blockIdx.x;   // big tiles first
    const int q0   = qt * 128;
    const int NT   = 2 * qt + 2;                             // key tiles (64 each)

    const size_t kvbase = (size_t)bh * Sq;

    // --- Q fragments (direct gmem gather, once) ------------------------------
    const int r  = q0 + w * 16 + (lane >> 2);
    const int dc = 2 * (lane & 3);
    uint32_t qh[4][4], ql[4][4];
    #pragma unroll
    for (int c = 0; c < 4; c++) {
        const int d = c * 16 + dc;
        const size_t i00 = (kvbase + r) * Dk + d;
        const size_t i10 = (kvbase + r + 8) * Dk + d;
        qh[c][0] = *reinterpret_cast<const uint32_t*>(Qhi + i00);
        qh[c][1] = *reinterpret_cast<const uint32_t*>(Qhi + i10);
        qh[c][2] = *reinterpret_cast<const uint32_t*>(Qhi + i00 + 8);
        qh[c][3] = *reinterpret_cast<const uint32_t*>(Qhi + i10 + 8);
        ql[c][0] = *reinterpret_cast<const uint32_t*>(Qlo + i00);
        ql[c][1] = *reinterpret_cast<const uint32_t*>(Qlo + i10);
        ql[c][2] = *reinterpret_cast<const uint32_t*>(Qlo + i00 + 8);
        ql[c][3] = *reinterpret_cast<const uint32_t*>(Qlo + i10 + 8);
    }

    const __half* gkv[2] = {Khi, Vhi};
    auto issue_kv = [&](int stage, int it) {
        const int k0 = it * 64;
        const uint32_t sb = sbase + stage * AT_STAGE;
        #pragma unroll
        for (int i = 0; i < 4; i++) {
            const int c = tid + i * 256;          // 0..1023
            const int t = c >> 9;                 // tile 0..1
            const int rr = (c >> 3) & 63;         // row 0..63
            const int cl = c & 7;                 // 16B chunk 0..7
            cp16(sb + t * AT_TILE + (uint32_t)(rr * ATPITCH + cl * 16),
                 gkv[t] + (kvbase + k0 + rr) * Dk + cl * 8);
        }
        CP_COMMIT();
    };

    float o[8][4];
    #pragma unroll
    for (int nt = 0; nt < 8; nt++)
        #pragma unroll
        for (int j = 0; j < 4; j++) o[nt][j] = 0.f;
    float m0 = -1e30f, m1 = -1e30f, l0 = 0.f, l1 = 0.f;

    issue_kv(0, 0);
    issue_kv(1, 1);

    const float SCL = 0.125f * 1.4426950408889634f;  // scale * log2(e)

    for (int it = 0; it < NT; it++) {
        if (it + 1 < NT) { CP_WAIT(1); } else { CP_WAIT(0); }
        __syncthreads();

        const uint32_t sb  = sbase + (it & 1) * AT_STAGE;
        const uint32_t sKh = sb;
        const uint32_t sVh = sb + AT_TILE;
        const int k0 = it * 64;

        // ---- S = Q K^T (Q exact, K fp16) -------------------------------------
        float s[8][4];
        #pragma unroll
        for (int nt = 0; nt < 8; nt++)
            #pragma unroll
            for (int j = 0; j < 4; j++) s[nt][j] = 0.f;

        #pragma unroll
        for (int c = 0; c < 4; c++) {
            #pragma unroll
            for (int nt = 0; nt < 8; nt++) {      // direct x2 loads (no unpack MOVs)
                const uint32_t boff =
                    (uint32_t)((nt * 8 + (lane & 7)) * ATPITCH + c * 32 + ((lane >> 3) & 1) * 16);
                uint32_t kh[2];
                ldsm_x2(sKh + boff, kh);
                mma_f16(s[nt], qh[c], kh);
                mma_f16(s[nt], ql[c], kh);
            }
        }

        // ---- online softmax (exp2 domain) ------------------------------------
        const bool need_mask = (k0 + 63 > q0);
        float t0 = -1e30f, t1 = -1e30f;
        #pragma unroll
        for (int nt = 0; nt < 8; nt++) {
            #pragma unroll
            for (int j = 0; j < 4; j++) {
                float t = s[nt][j] * SCL;
                if (need_mask) {
                    const int col = k0 + nt * 8 + dc + (j & 1);
                    const int row = (j < 2) ? r : r + 8;
                    if (col > row) t = -1e30f;
                }
                s[nt][j] = t;
                if (j < 2) t0 = fmaxf(t0, t); else t1 = fmaxf(t1, t);
            }
        }
        t0 = fmaxf(t0, __shfl_xor_sync(0xffffffffu, t0, 1));
        t0 = fmaxf(t0, __shfl_xor_sync(0xffffffffu, t0, 2));
        t1 = fmaxf(t1, __shfl_xor_sync(0xffffffffu, t1, 1));
        t1 = fmaxf(t1, __shfl_xor_sync(0xffffffffu, t1, 2));
        const float mn0 = fmaxf(m0, t0), mn1 = fmaxf(m1, t1);
        const float corr0 = exp2f(m0 - mn0), corr1 = exp2f(m1 - mn1);
        m0 = mn0; m1 = mn1;

        float ps0 = 0.f, ps1 = 0.f;
        #pragma unroll
        for (int nt = 0; nt < 8; nt++) {
            s[nt][0] = exp2f(s[nt][0] - m0);
            s[nt][1] = exp2f(s[nt][1] - m0);
            s[nt][2] = exp2f(s[nt][2] - m1);
            s[nt][3] = exp2f(s[nt][3] - m1);
            ps0 += s[nt][0] + s[nt][1];
            ps1 += s[nt][2] + s[nt][3];
        }
        ps0 += __shfl_xor_sync(0xffffffffu, ps0, 1);
        ps0 += __shfl_xor_sync(0xffffffffu, ps0, 2);
        ps1 += __shfl_xor_sync(0xffffffffu, ps1, 1);
        ps1 += __shfl_xor_sync(0xffffffffu, ps1, 2);
        l0 = l0 * corr0 + ps0;
        l1 = l1 * corr1 + ps1;

        #pragma unroll
        for (int nt = 0; nt < 8; nt++) {
            o[nt][0] *= corr0; o[nt][1] *= corr0;
            o[nt][2] *= corr1; o[nt][3] *= corr1;
        }

        // ---- O += P V (P exact fp16 pair, V fp16) -----------------------------
        #pragma unroll
        for (int u = 0; u < 4; u++) {
            uint32_t aph[4], apl[4];
            {
                const float p00 = s[2*u][0],   p01 = s[2*u][1];
                const float p02 = s[2*u][2],   p03 = s[2*u][3];
                const float p10 = s[2*u+1][0], p11 = s[2*u+1][1];
                const float p12 = s[2*u+1][2], p13 = s[2*u+1][3];
                aph[0] = pack_hf2(p00, p01);
                aph[1] = pack_hf2(p02, p03);
                aph[2] = pack_hf2(p10, p11);
                aph[3] = pack_hf2(p12, p13);
                apl[0] = pack_hf2(p00 - hf_round(p00), p01 - hf_round(p01));
                apl[1] = pack_hf2(p02 - hf_round(p02), p03 - hf_round(p03));
                apl[2] = pack_hf2(p10 - hf_round(p10), p11 - hf_round(p11));
                apl[3] = pack_hf2(p12 - hf_round(p12), p13 - hf_round(p13));
            }
            #pragma unroll
            for (int nt = 0; nt < 8; nt++) {      // direct x2t loads (no unpack MOVs)
                const uint32_t voff =
                    (uint32_t)((u * 16 + (lane & 15)) * ATPITCH + nt * 16);
                uint32_t vh[2];
                ldsm_x2t(sVh + voff, vh);
                mma_f16(o[nt], aph, vh);
                mma_f16(o[nt], apl, vh);
            }
        }

        if (it + 2 < NT) {
            __syncthreads();          // stage (it&1) fully consumed
            issue_kv(it & 1, it + 2); // lands during compute(it+1)
        }
    }

    // ---- epilogue: normalize, split fp16 hi/lo, write [B,S,D] ----------------
    const float inv0 = 1.0f / l0, inv1 = 1.0f / l1;
    const int b = bh >> 4, h = bh & 15;
    const size_t base0 = ((size_t)b * Sq + r) * Dm + h * Dk;
    const size_t base1 = ((size_t)b * Sq + r + 8) * Dm + h * Dk;
    #pragma unroll
    for (int nt = 0; nt < 8; nt++) {
        const int col = nt * 8 + dc;
        const float v0 = o[nt][0] * inv0, v1 = o[nt][1] * inv0;
        const float v2 = o[nt][2] * inv1, v3 = o[nt][3] * inv1;
        *reinterpret_cast<uint32_t*>(Ohi + base0 + col) = pack_hf2(v0, v1);
        *reinterpret_cast<uint32_t*>(Olo + base0 + col) =
            pack_hf2(v0 - hf_round(v0), v1 - hf_round(v1));
        *reinterpret_cast<uint32_t*>(Ohi + base1 + col) = pack_hf2(v2, v3);
        *reinterpret_cast<uint32_t*>(Olo + base1 + col) =
            pack_hf2(v2 - hf_round(v2), v3 - hf_round(v3));
    }
}

// ---------------- launch -----------------------------------------------------
extern "C" void kernel_launch(void* const* d_in, const int* in_sizes, int n_in,
                              void* d_out, int out_size)
{
    const float* x   = (const float*)d_in[0];
    const float* Wq  = (const float*)d_in[1];
    const float* Wk  = (const float*)d_in[2];
    const float* Wv  = (const float*)d_in[3];
    const float* Wo  = (const float*)d_in[4];
    const int*   pos = (const int*)d_in[5];
    float* out = (float*)d_out;

    __half *xhi, *xlo, *wqhi, *wkhi, *wvhi, *wohi;
    __half *qhi, *qlo, *khi, *vhi, *ohi, *olo;
    cudaGetSymbolAddress((void**)&xhi,  g_xhi);  cudaGetSymbolAddress((void**)&xlo,  g_xlo);
    cudaGetSymbolAddress((void**)&wqhi, g_wqhi);
    cudaGetSymbolAddress((void**)&wkhi, g_wkhi);
    cudaGetSymbolAddress((void**)&wvhi, g_wvhi);
    cudaGetSymbolAddress((void**)&wohi, g_wohi);
    cudaGetSymbolAddress((void**)&qhi,  g_Qhi);  cudaGetSymbolAddress((void**)&qlo,  g_Qlo);
    cudaGetSymbolAddress((void**)&khi,  g_Khi);
    cudaGetSymbolAddress((void**)&vhi,  g_Vhi);
    cudaGetSymbolAddress((void**)&ohi,  g_Ohi);  cudaGetSymbolAddress((void**)&olo,  g_Olo);

    cudaFuncSetAttribute(qkv_gemm_kernel,
                         cudaFuncAttributeMaxDynamicSharedMemorySize, GEMM_SMEM);
    cudaFuncSetAttribute(wo_gemm_kernel,
                         cudaFuncAttributeMaxDynamicSharedMemorySize, GEMM_SMEM);
    cudaFuncSetAttribute(attn_mma_kernel,
                         cudaFuncAttributeMaxDynamicSharedMemorySize, ATT_SMEM);

    // 1) one fused split pass (x hi/lo fp16 + 4 weights fp16 hi)
    const int ntot4 = NX4 + 4 * NW4;   // 2097152
    split_all_kernel<<<ntot4 / 256, 256>>>(x, Wq, Wk, Wv, Wo,
                                           xhi, xlo, wqhi, wkhi, wvhi, wohi);

    // 2) fused QKV projection (+RoPE on Q,K)
    dim3 qkvgrid(3 * (Dm / BN), Mrows / BM);   // (24, 32)
    qkv_gemm_kernel<<<qkvgrid, 256, GEMM_SMEM>>>(xhi, xlo, wqhi, wkhi, wvhi,
                                                 qhi, qlo, khi, vhi, pos);

    // 3) causal flash attention
    dim3 agrid(Sq / 128, Bsz * Hn);            // (16, 32)
    attn_mma_kernel<<<agrid, 256, ATT_SMEM>>>(qhi, qlo, khi, vhi, ohi, olo);

    // 4) output projection
    dim3 wogrid(Dm / BN, Mrows / BM);          // (8, 32)
    wo_gemm_kernel<<<wogrid, 256, GEMM_SMEM>>>(ohi, olo, wohi, out);
}

// round 11
// speedup vs baseline: 5.3424x; 1.2926x over previous
#include <cuda_runtime.h>
#include <cuda_fp16.h>
#include <math.h>
#include <stdint.h>

// Problem constants (fixed by this dataset instance)
#define Bsz 2
#define Sq  2048
#define Dm  1024
#define Hn  16
#define Dk  64
#define Mrows (Bsz*Sq)   // 4096

// ---------------- scratch ----------------------------------------------------
__device__ __half g_xhi[Mrows*Dm], g_xlo[Mrows*Dm];   // x: fp16 hi/lo
__device__ __half g_wqhi[Dm*Dm];                       // weights: fp16 hi only
__device__ __half g_wkhi[Dm*Dm];
__device__ __half g_wvhi[Dm*Dm];
__device__ __half g_wohi[Dm*Dm];
__device__ __half g_Qhi[Mrows*Dm];                     // [B,H,S,Dk] fp16 hi
__device__ __half g_Khi[Mrows*Dm];
__device__ __half g_Vhi[Mrows*Dm];
__device__ __half g_Ohi[Mrows*Dm];                     // [B,S,D] fp16 hi

// ================= small PTX wrappers (portable, compute_103-safe) ===========
__device__ __forceinline__ uint32_t smem_u32(const void* p) {
    uint32_t a;
    asm("{ .reg .u64 t; cvta.to.shared.u64 t, %1; cvt.u32.u64 %0, t; }"
        : "=r"(a) : "l"(p));
    return a;
}
__device__ __forceinline__ void ldsm_x4(uint32_t addr, uint32_t r[4]) {
    asm volatile("ldmatrix.sync.aligned.m8n8.x4.shared.b16 {%0,%1,%2,%3}, [%4];"
                 : "=r"(r[0]), "=r"(r[1]), "=r"(r[2]), "=r"(r[3]) : "r"(addr));
}
__device__ __forceinline__ void ldsm_x2(uint32_t addr, uint32_t r[2]) {
    asm volatile("ldmatrix.sync.aligned.m8n8.x2.shared.b16 {%0,%1}, [%2];"
                 : "=r"(r[0]), "=r"(r[1]) : "r"(addr));
}
__device__ __forceinline__ void ldsm_x2t(uint32_t addr, uint32_t r[2]) {
    asm volatile("ldmatrix.sync.aligned.m8n8.x2.trans.shared.b16 {%0,%1}, [%2];"
                 : "=r"(r[0]), "=r"(r[1]) : "r"(addr));
}
__device__ __forceinline__ void mma_f16(float c[4], const uint32_t a[4],
                                        const uint32_t b[2]) {
    asm volatile(
        "mma.sync.aligned.m16n8k16.row.col.f32.f16.f16.f32 "
        "{%0,%1,%2,%3}, {%4,%5,%6,%7}, {%8,%9}, {%0,%1,%2,%3};"
        : "+f"(c[0]), "+f"(c[1]), "+f"(c[2]), "+f"(c[3])
        : "r"(a[0]), "r"(a[1]), "r"(a[2]), "r"(a[3]), "r"(b[0]), "r"(b[1]));
}
__device__ __forceinline__ void cp16(uint32_t smem_addr, const void* gptr) {
    asm volatile("cp.async.cg.shared.global [%0], [%1], 16;"
                 :: "r"(smem_addr), "l"(gptr) : "memory");
}
#define CP_COMMIT() asm volatile("cp.async.commit_group;" ::: "memory")
#define CP_WAIT(n)  asm volatile("cp.async.wait_group %0;" :: "n"(n) : "memory")

__device__ __forceinline__ float hf_round(float x) {
    return __half2float(__float2half_rn(x));
}
__device__ __forceinline__ uint32_t pack_hf2(float x, float y) {
    __half2 t = __floats2half2_rn(x, y);
    return *reinterpret_cast<uint32_t*>(&t);
}

// ================= fused split pass ==========================================
// x -> fp16 hi/lo ; weights -> fp16 hi only
#define NX4 (Mrows*Dm/4)    // 1048576
#define NW4 (Dm*Dm/4)       // 262144
__global__ void __launch_bounds__(256)
split_all_kernel(const float* __restrict__ x,  const float* __restrict__ Wq,
                 const float* __restrict__ Wk, const float* __restrict__ Wv,
                 const float* __restrict__ Wo,
                 __half* __restrict__ xhi,  __half* __restrict__ xlo,
                 __half* __restrict__ wqhi, __half* __restrict__ wkhi,
                 __half* __restrict__ wvhi, __half* __restrict__ wohi)
{
    int i = blockIdx.x * 256 + threadIdx.x;
    if (i < NX4) {
        float4 v = reinterpret_cast<const float4*>(x)[i];
        uint2 h = make_uint2(pack_hf2(v.x, v.y), pack_hf2(v.z, v.w));
        uint2 l = make_uint2(pack_hf2(v.x - hf_round(v.x), v.y - hf_round(v.y)),
                             pack_hf2(v.z - hf_round(v.z), v.w - hf_round(v.w)));
        reinterpret_cast<uint2*>(xhi)[i] = h;
        reinterpret_cast<uint2*>(xlo)[i] = l;
    } else {
        int t = (i - NX4) >> 18;            // which weight (NW4 = 2^18)
        int j = (i - NX4) & (NW4 - 1);
        const float* src; __half* hi;
        if      (t == 0) { src = Wq; hi = wqhi; }
        else if (t == 1) { src = Wk; hi = wkhi; }
        else if (t == 2) { src = Wv; hi = wvhi; }
        else             { src = Wo; hi = wohi; }
        float4 v = reinterpret_cast<const float4*>(src)[j];
        reinterpret_cast<uint2*>(hi)[j] =
            make_uint2(pack_hf2(v.x, v.y), pack_hf2(v.z, v.w));
    }
}

// ================= shared GEMM machinery ======================================
// TWO_TERM: C = (Ahi+Alo)*Bhi^T (2 MMA/frag). else: C = Ahi*Bhi^T (1 MMA/frag).
#define BM 128
#define BN 128
#define BK 32
#define KT_ITERS (Dm/BK)              // 32
#define TPITCH 80
#define TILE_BYTES (128*TPITCH)        // 10240
#define NSTAGE 3
#define GEMM_SMEM_2T (NSTAGE*3*TILE_BYTES) // 92160 (2 CTAs/SM)
#define GEMM_SMEM_1T (NSTAGE*2*TILE_BYTES) // 61440 (2 CTAs/SM)

template<bool TWO_TERM>
struct GemmCore {
    static constexpr int TA = TWO_TERM ? 2 : 1;          // A tiles per stage
    static constexpr int STAGE_BYTES = (TA + 1) * TILE_BYTES;

    uint32_t sbase;
    int lane, warp_m, warp_n, m0, n0;
    const __half *Ahi, *Alo, *Bhi;
    int r0a, c0, r1a;

    __device__ __forceinline__ void issue_stage(int stage, int kt) {
        const int kc = kt * BK;
        const uint32_t sb = sbase + stage * STAGE_BYTES;
        const __half* gsrc[3] = {Ahi, TWO_TERM ? Alo : Bhi, Bhi};
        #pragma unroll
        for (int t = 0; t < TA + 1; t++) {
            const int row0 = (t < TA) ? m0 : n0;
            const __half* g = gsrc[TWO_TERM ? t : (t == 0 ? 0 : 2)];
            cp16(sb + t * TILE_BYTES + (uint32_t)(r0a * TPITCH + c0 * 16),
                 g + (size_t)(row0 + r0a) * Dm + kc + c0 * 8);
            cp16(sb + t * TILE_BYTES + (uint32_t)(r1a * TPITCH + c0 * 16),
                 g + (size_t)(row0 + r1a) * Dm + kc + c0 * 8);
        }
        CP_COMMIT();
    }

    __device__ __forceinline__ void mainloop(float acc[4][4][4]) {
        issue_stage(0, 0);
        issue_stage(1, 1);
        for (int kt = 0; kt < KT_ITERS; kt++) {
            if (kt + 1 < KT_ITERS) { CP_WAIT(1); } else { CP_WAIT(0); }
            __syncthreads();
            if (kt + 2 < KT_ITERS) issue_stage((kt + 2) % NSTAGE, kt + 2);

            const uint32_t sb = sbase + (kt % NSTAGE) * STAGE_BYTES;
            const uint32_t sAhi = sb;
            const uint32_t sAlo = sb + TILE_BYTES;           // valid iff TWO_TERM
            const uint32_t sBhi = sb + TA * TILE_BYTES;

            #pragma unroll
            for (int ks = 0; ks < 2; ks++) {
                const int chunk = ks * 2;
                uint32_t bhi[4][2];
                #pragma unroll
                for (int nt = 0; nt < 4; nt++) {      // direct x2 loads
                    const int brow = warp_n * 32 + nt * 8 + (lane & 7);
                    const uint32_t boff = (uint32_t)(brow * TPITCH + (chunk + ((lane >> 3) & 1)) * 16);
                    ldsm_x2(sBhi + boff, bhi[nt]);
                }
                #pragma unroll
                for (int mt = 0; mt < 4; mt++) {
                    uint32_t ahi[4];
                    const int arow = warp_m * 64 + mt * 16 + (lane & 15);
                    const uint32_t aoff = (uint32_t)(arow * TPITCH + (chunk + (lane >> 4)) * 16);
                    ldsm_x4(sAhi + aoff, ahi);
                    if (TWO_TERM) {
                        uint32_t alo[4];
                        ldsm_x4(sAlo + aoff, alo);
                        #pragma unroll
                        for (int nt = 0; nt < 4; nt++) {
                            mma_f16(acc[mt][nt], ahi, bhi[nt]);
                            mma_f16(acc[mt][nt], alo, bhi[nt]);
                        }
                    } else {
                        #pragma unroll
                        for (int nt = 0; nt < 4; nt++)
                            mma_f16(acc[mt][nt], ahi, bhi[nt]);
                    }
                }
            }
        }
    }
};

// ---- fused QKV GEMM: one launch computes Q, K, V projections -----------------
__global__ void __launch_bounds__(256, 2)
qkv_gemm_kernel(const __half* __restrict__ xhi, const __half* __restrict__ xlo,
                const __half* __restrict__ wqhi, const __half* __restrict__ wkhi,
                const __half* __restrict__ wvhi,
                __half* __restrict__ qhi, __half* __restrict__ khi,
                __half* __restrict__ vhi, const int* __restrict__ pos)
{
    extern __shared__ char sm[];
    const int tid  = threadIdx.x;
    const int wsel = blockIdx.x >> 3;

    GemmCore<true> gc;
    gc.sbase = smem_u32(sm);
    gc.lane = tid & 31;
    gc.warp_m = (tid >> 5) & 1; gc.warp_n = tid >> 6;
    gc.n0 = (blockIdx.x & 7) * BN;
    gc.m0 = blockIdx.y * BM;
    gc.Ahi = xhi; gc.Alo = xlo;
    gc.r0a = tid >> 2; gc.c0 = tid & 3; gc.r1a = (tid + 256) >> 2;

    __half* Chi;
    bool rope;
    if (wsel == 0)      { gc.Bhi = wqhi; Chi = qhi; rope = true;  }
    else if (wsel == 1) { gc.Bhi = wkhi; Chi = khi; rope = true;  }
    else                { gc.Bhi = wvhi; Chi = vhi; rope = false; }

    float acc[4][4][4];
    #pragma unroll
    for (int i = 0; i < 4; i++)
        #pragma unroll
        for (int j = 0; j < 4; j++)
            #pragma unroll
            for (int v = 0; v < 4; v++) acc[i][j][v] = 0.f;

    gc.mainloop(acc);

    // epilogue: fused RoPE + fp16 hi store to [B,H,S,Dk]
    const int lane = gc.lane;
    #pragma unroll
    for (int mt = 0; mt < 4; mt++) {
        #pragma unroll
        for (int half = 0; half < 2; half++) {
            const int row = gc.m0 + gc.warp_m * 64 + mt * 16 + (lane >> 2) + half * 8;
            const int b = row >> 11;
            const int s = row & (Sq - 1);
            float p = rope ? (float)pos[row] : 0.f;
            #pragma unroll
            for (int nt = 0; nt < 4; nt++) {
                const int col = gc.n0 + gc.warp_n * 32 + nt * 8 + (lane & 3) * 2;  // even
                float e = acc[mt][nt][half * 2];
                float o = acc[mt][nt][half * 2 + 1];
                if (rope) {
                    const int dk = col & (Dk - 1);
                    const float inv = exp2f((float)dk * (-13.287712379549449f / 64.0f));
                    float sn, cs;
                    sincosf(p * inv, &sn, &cs);
                    const float re = e * cs - o * sn;
                    const float ro = e * sn + o * cs;
                    e = re; o = ro;
                }
                const int h  = col >> 6;
                const int dk = col & (Dk - 1);
                const size_t idx = ((size_t)(b * Hn + h) * Sq + s) * Dk + dk;
                *reinterpret_cast<uint32_t*>(Chi + idx) = pack_hf2(e, o);
            }
        }
    }
}

// ---- output projection GEMM: single-term, fp32 out ----------------------------
__global__ void __launch_bounds__(256, 2)
wo_gemm_kernel(const __half* __restrict__ Ahi, const __half* __restrict__ Bhi,
               float* __restrict__ C)
{
    extern __shared__ char sm[];
    const int tid = threadIdx.x;

    GemmCore<false> gc;
    gc.sbase = smem_u32(sm);
    gc.lane = tid & 31;
    gc.warp_m = (tid >> 5) & 1; gc.warp_n = tid >> 6;
    gc.n0 = blockIdx.x * BN;
    gc.m0 = blockIdx.y * BM;
    gc.Ahi = Ahi; gc.Alo = nullptr; gc.Bhi = Bhi;
    gc.r0a = tid >> 2; gc.c0 = tid & 3; gc.r1a = (tid + 256) >> 2;

    float acc[4][4][4];
    #pragma unroll
    for (int i = 0; i < 4; i++)
        #pragma unroll
        for (int j = 0; j < 4; j++)
            #pragma unroll
            for (int v = 0; v < 4; v++) acc[i][j][v] = 0.f;

    gc.mainloop(acc);

    const int lane = gc.lane;
    #pragma unroll
    for (int mt = 0; mt < 4; mt++) {
        #pragma unroll
        for (int half = 0; half < 2; half++) {
            const int row = gc.m0 + gc.warp_m * 64 + mt * 16 + (lane >> 2) + half * 8;
            #pragma unroll
            for (int nt = 0; nt < 4; nt++) {
                const int col = gc.n0 + gc.warp_n * 32 + nt * 8 + (lane & 3) * 2;
                float* dst = C + (size_t)row * Dm + col;
                *reinterpret_cast<float2*>(dst) =
                    make_float2(acc[mt][nt][half * 2], acc[mt][nt][half * 2 + 1]);
            }
        }
    }
}

// ================= tensor-core causal flash attention (pure fp16) =============
// S = Qhi*Khi ; O += Phi*Vhi  (single-term; error terms calibrated ~2e-4 each)
#define ATPITCH 144
#define AT_TILE (64*ATPITCH)          // 9216
#define AT_STAGE (2*AT_TILE)          // Khi|Vhi = 18432
#define AT_NSTAGE 3
#define ATT_SMEM (AT_NSTAGE*AT_STAGE) // 55296  (2 CTAs/SM)

__global__ void __launch_bounds__(256, 2)
attn_mma_kernel(const __half* __restrict__ Qhi,
                const __half* __restrict__ Khi, const __half* __restrict__ Vhi,
                __half* __restrict__ Ohi)
{
    extern __shared__ char sm[];
    const uint32_t sbase = smem_u32(sm);

    const int tid  = threadIdx.x;
    const int lane = tid & 31;
    const int w    = tid >> 5;
    const int bh   = blockIdx.y;
    const int qt   = (int)gridDim.x - 1 - (int)blockIdx.x;   // big tiles first
    const int q0   = qt * 128;
    const int NT   = 2 * qt + 2;                             // key tiles (64 each)

    const size_t kvbase = (size_t)bh * Sq;

    // --- Q fragments (direct gmem gather, once) ------------------------------
    const int r  = q0 + w * 16 + (lane >> 2);
    const int dc = 2 * (lane & 3);
    uint32_t qh[4][4];
    #pragma unroll
    for (int c = 0; c < 4; c++) {
        const int d = c * 16 + dc;
        const size_t i00 = (kvbase + r) * Dk + d;
        const size_t i10 = (kvbase + r + 8) * Dk + d;
        qh[c][0] = *reinterpret_cast<const uint32_t*>(Qhi + i00);
        qh[c][1] = *reinterpret_cast<const uint32_t*>(Qhi + i10);
        qh[c][2] = *reinterpret_cast<const uint32_t*>(Qhi + i00 + 8);
        qh[c][3] = *reinterpret_cast<const uint32_t*>(Qhi + i10 + 8);
    }

    const __half* gkv[2] = {Khi, Vhi};
    auto issue_kv = [&](int stage, int it) {
        const int k0 = it * 64;
        const uint32_t sb = sbase + stage * AT_STAGE;
        #pragma unroll
        for (int i = 0; i < 4; i++) {
            const int c = tid + i * 256;          // 0..1023
            const int t = c >> 9;                 // tile 0..1
            const int rr = (c >> 3) & 63;         // row 0..63
            const int cl = c & 7;                 // 16B chunk 0..7
            cp16(sb + t * AT_TILE + (uint32_t)(rr * ATPITCH + cl * 16),
                 gkv[t] + (kvbase + k0 + rr) * Dk + cl * 8);
        }
        CP_COMMIT();
    };

    float o[8][4];
    #pragma unroll
    for (int nt = 0; nt < 8; nt++)
        #pragma unroll
        for (int j = 0; j < 4; j++) o[nt][j] = 0.f;
    float m0 = -1e30f, m1 = -1e30f, l0 = 0.f, l1 = 0.f;

    issue_kv(0, 0);
    issue_kv(1, 1);

    const float SCL = 0.125f * 1.4426950408889634f;  // scale * log2(e)

    for (int it = 0; it < NT; it++) {
        if (it + 1 < NT) { CP_WAIT(1); } else { CP_WAIT(0); }
        __syncthreads();
        if (it + 2 < NT) issue_kv((it + 2) % AT_NSTAGE, it + 2);  // single-sync pipeline

        const uint32_t sb  = sbase + (it % AT_NSTAGE) * AT_STAGE;
        const uint32_t sKh = sb;
        const uint32_t sVh = sb + AT_TILE;
        const int k0 = it * 64;

        // ---- S = Q K^T -------------------------------------------------------
        float s[8][4];
        #pragma unroll
        for (int nt = 0; nt < 8; nt++)
            #pragma unroll
            for (int j = 0; j < 4; j++) s[nt][j] = 0.f;

        #pragma unroll
        for (int c = 0; c < 4; c++) {
            #pragma unroll
            for (int nt = 0; nt < 8; nt++) {
                const uint32_t boff =
                    (uint32_t)((nt * 8 + (lane & 7)) * ATPITCH + c * 32 + ((lane >> 3) & 1) * 16);
                uint32_t kh[2];
                ldsm_x2(sKh + boff, kh);
                mma_f16(s[nt], qh[c], kh);
            }
        }

        // ---- online softmax (exp2 domain) ------------------------------------
        const bool need_mask = (k0 + 63 > q0);
        float t0 = -1e30f, t1 = -1e30f;
        #pragma unroll
        for (int nt = 0; nt < 8; nt++) {
            #pragma unroll
            for (int j = 0; j < 4; j++) {
                float t = s[nt][j] * SCL;
                if (need_mask) {
                    const int col = k0 + nt * 8 + dc + (j & 1);
                    const int row = (j < 2) ? r : r + 8;
                    if (col > row) t = -1e30f;
                }
                s[nt][j] = t;
                if (j < 2) t0 = fmaxf(t0, t); else t1 = fmaxf(t1, t);
            }
        }
        t0 = fmaxf(t0, __shfl_xor_sync(0xffffffffu, t0, 1));
        t0 = fmaxf(t0, __shfl_xor_sync(0xffffffffu, t0, 2));
        t1 = fmaxf(t1, __shfl_xor_sync(0xffffffffu, t1, 1));
        t1 = fmaxf(t1, __shfl_xor_sync(0xffffffffu, t1, 2));
        const float mn0 = fmaxf(m0, t0), mn1 = fmaxf(m1, t1);
        const float corr0 = exp2f(m0 - mn0), corr1 = exp2f(m1 - mn1);
        m0 = mn0; m1 = mn1;

        float ps0 = 0.f, ps1 = 0.f;
        #pragma unroll
        for (int nt = 0; nt < 8; nt++) {
            s[nt][0] = exp2f(s[nt][0] - m0);
            s[nt][1] = exp2f(s[nt][1] - m0);
            s[nt][2] = exp2f(s[nt][2] - m1);
            s[nt][3] = exp2f(s[nt][3] - m1);
            ps0 += s[nt][0] + s[nt][1];
            ps1 += s[nt][2] + s[nt][3];
        }
        ps0 += __shfl_xor_sync(0xffffffffu, ps0, 1);
        ps0 += __shfl_xor_sync(0xffffffffu, ps0, 2);
        ps1 += __shfl_xor_sync(0xffffffffu, ps1, 1);
        ps1 += __shfl_xor_sync(0xffffffffu, ps1, 2);
        l0 = l0 * corr0 + ps0;
        l1 = l1 * corr1 + ps1;

        #pragma unroll
        for (int nt = 0; nt < 8; nt++) {
            o[nt][0] *= corr0; o[nt][1] *= corr0;
            o[nt][2] *= corr1; o[nt][3] *= corr1;
        }

        // ---- O += P V ----------------------------------------------------------
        #pragma unroll
        for (int u = 0; u < 4; u++) {
            uint32_t aph[4];
            aph[0] = pack_hf2(s[2*u][0],   s[2*u][1]);
            aph[1] = pack_hf2(s[2*u][2],   s[2*u][3]);
            aph[2] = pack_hf2(s[2*u+1][0], s[2*u+1][1]);
            aph[3] = pack_hf2(s[2*u+1][2], s[2*u+1][3]);
            #pragma unroll
            for (int nt = 0; nt < 8; nt++) {
                const uint32_t voff =
                    (uint32_t)((u * 16 + (lane & 15)) * ATPITCH + nt * 16);
                uint32_t vh[2];
                ldsm_x2t(sVh + voff, vh);
                mma_f16(o[nt], aph, vh);
            }
        }
    }

    // ---- epilogue: normalize, fp16 hi store, write [B,S,D] -------------------
    const float inv0 = 1.0f / l0, inv1 = 1.0f / l1;
    const int b = bh >> 4, h = bh & 15;
    const size_t base0 = ((size_t)b * Sq + r) * Dm + h * Dk;
    const size_t base1 = ((size_t)b * Sq + r + 8) * Dm + h * Dk;
    #pragma unroll
    for (int nt = 0; nt < 8; nt++) {
        const int col = nt * 8 + dc;
        *reinterpret_cast<uint32_t*>(Ohi + base0 + col) =
            pack_hf2(o[nt][0] * inv0, o[nt][1] * inv0);
        *reinterpret_cast<uint32_t*>(Ohi + base1 + col) =
            pack_hf2(o[nt][2] * inv1, o[nt][3] * inv1);
    }
}

// ---------------- launch -----------------------------------------------------
extern "C" void kernel_launch(void* const* d_in, const int* in_sizes, int n_in,
                              void* d_out, int out_size)
{
    const float* x   = (const float*)d_in[0];
    const float* Wq  = (const float*)d_in[1];
    const float* Wk  = (const float*)d_in[2];
    const float* Wv  = (const float*)d_in[3];
    const float* Wo  = (const float*)d_in[4];
    const int*   pos = (const int*)d_in[5];
    float* out = (float*)d_out;

    __half *xhi, *xlo, *wqhi, *wkhi, *wvhi, *wohi;
    __half *qhi, *khi, *vhi, *ohi;
    cudaGetSymbolAddress((void**)&xhi,  g_xhi);  cudaGetSymbolAddress((void**)&xlo,  g_xlo);
    cudaGetSymbolAddress((void**)&wqhi, g_wqhi);
    cudaGetSymbolAddress((void**)&wkhi, g_wkhi);
    cudaGetSymbolAddress((void**)&wvhi, g_wvhi);
    cudaGetSymbolAddress((void**)&wohi, g_wohi);
    cudaGetSymbolAddress((void**)&qhi,  g_Qhi);
    cudaGetSymbolAddress((void**)&khi,  g_Khi);
    cudaGetSymbolAddress((void**)&vhi,  g_Vhi);
    cudaGetSymbolAddress((void**)&ohi,  g_Ohi);

    cudaFuncSetAttribute(qkv_gemm_kernel,
                         cudaFuncAttributeMaxDynamicSharedMemorySize, GEMM_SMEM_2T);
    cudaFuncSetAttribute(wo_gemm_kernel,
                         cudaFuncAttributeMaxDynamicSharedMemorySize, GEMM_SMEM_1T);
    cudaFuncSetAttribute(attn_mma_kernel,
                         cudaFuncAttributeMaxDynamicSharedMemorySize, ATT_SMEM);

    // 1) one fused split pass (x hi/lo fp16 + 4 weights fp16 hi)
    const int ntot4 = NX4 + 4 * NW4;   // 2097152
    split_all_kernel<<<ntot4 / 256, 256>>>(x, Wq, Wk, Wv, Wo,
                                           xhi, xlo, wqhi, wkhi, wvhi, wohi);

    // 2) fused QKV projection (+RoPE on Q,K)
    dim3 qkvgrid(3 * (Dm / BN), Mrows / BM);   // (24, 32)
    qkv_gemm_kernel<<<qkvgrid, 256, GEMM_SMEM_2T>>>(xhi, xlo, wqhi, wkhi, wvhi,
                                                    qhi, khi, vhi, pos);

    // 3) causal flash attention
    dim3 agrid(Sq / 128, Bsz * Hn);            // (16, 32)
    attn_mma_kernel<<<agrid, 256, ATT_SMEM>>>(qhi, khi, vhi, ohi);

    // 4) output projection (single-term)
    dim3 wogrid(Dm / BN, Mrows / BM);          // (8, 32)
    wo_gemm_kernel<<<wogrid, 256, GEMM_SMEM_1T>>>(ohi, wohi, out);
}

// round 12
// speedup vs baseline: 6.9406x; 1.2991x over previous
#include <cuda_runtime.h>
#include <cuda_fp16.h>
#include <math.h>
#include <stdint.h>

// Problem constants (fixed by this dataset instance)
#define Bsz 2
#define Sq  2048
#define Dm  1024
#define Hn  16
#define Dk  64
#define Mrows (Bsz*Sq)   // 4096

// ---------------- scratch ----------------------------------------------------
__device__ __half g_xhi[Mrows*Dm];                     // x: fp16 hi only
__device__ __half g_wqhi[Dm*Dm];                       // weights: fp16 hi only
__device__ __half g_wkhi[Dm*Dm];
__device__ __half g_wvhi[Dm*Dm];
__device__ __half g_wohi[Dm*Dm];
__device__ __half g_Qhi[Mrows*Dm];                     // [B,H,S,Dk] fp16 hi
__device__ __half g_Khi[Mrows*Dm];
__device__ __half g_Vhi[Mrows*Dm];
__device__ __half g_Ohi[Mrows*Dm];                     // [B,S,D] fp16 hi

// ================= small PTX wrappers (portable, compute_103-safe) ===========
__device__ __forceinline__ uint32_t smem_u32(const void* p) {
    uint32_t a;
    asm("{ .reg .u64 t; cvta.to.shared.u64 t, %1; cvt.u32.u64 %0, t; }"
        : "=r"(a) : "l"(p));
    return a;
}
__device__ __forceinline__ void ldsm_x4(uint32_t addr, uint32_t r[4]) {
    asm volatile("ldmatrix.sync.aligned.m8n8.x4.shared.b16 {%0,%1,%2,%3}, [%4];"
                 : "=r"(r[0]), "=r"(r[1]), "=r"(r[2]), "=r"(r[3]) : "r"(addr));
}
__device__ __forceinline__ void ldsm_x2(uint32_t addr, uint32_t r[2]) {
    asm volatile("ldmatrix.sync.aligned.m8n8.x2.shared.b16 {%0,%1}, [%2];"
                 : "=r"(r[0]), "=r"(r[1]) : "r"(addr));
}
__device__ __forceinline__ void ldsm_x2t(uint32_t addr, uint32_t r[2]) {
    asm volatile("ldmatrix.sync.aligned.m8n8.x2.trans.shared.b16 {%0,%1}, [%2];"
                 : "=r"(r[0]), "=r"(r[1]) : "r"(addr));
}
__device__ __forceinline__ void mma_f16(float c[4], const uint32_t a[4],
                                        const uint32_t b[2]) {
    asm volatile(
        "mma.sync.aligned.m16n8k16.row.col.f32.f16.f16.f32 "
        "{%0,%1,%2,%3}, {%4,%5,%6,%7}, {%8,%9}, {%0,%1,%2,%3};"
        : "+f"(c[0]), "+f"(c[1]), "+f"(c[2]), "+f"(c[3])
        : "r"(a[0]), "r"(a[1]), "r"(a[2]), "r"(a[3]), "r"(b[0]), "r"(b[1]));
}
__device__ __forceinline__ void cp16(uint32_t smem_addr, const void* gptr) {
    asm volatile("cp.async.cg.shared.global [%0], [%1], 16;"
                 :: "r"(smem_addr), "l"(gptr) : "memory");
}
#define CP_COMMIT() asm volatile("cp.async.commit_group;" ::: "memory")
#define CP_WAIT(n)  asm volatile("cp.async.wait_group %0;" :: "n"(n) : "memory")

__device__ __forceinline__ uint32_t pack_hf2(float x, float y) {
    __half2 t = __floats2half2_rn(x, y);
    return *reinterpret_cast<uint32_t*>(&t);
}

// ================= fused split pass ==========================================
// all five tensors -> fp16 hi only
#define NX4 (Mrows*Dm/4)    // 1048576
#define NW4 (Dm*Dm/4)       // 262144
__global__ void __launch_bounds__(256)
split_all_kernel(const float* __restrict__ x,  const float* __restrict__ Wq,
                 const float* __restrict__ Wk, const float* __restrict__ Wv,
                 const float* __restrict__ Wo,
                 __half* __restrict__ xhi,
                 __half* __restrict__ wqhi, __half* __restrict__ wkhi,
                 __half* __restrict__ wvhi, __half* __restrict__ wohi)
{
    int i = blockIdx.x * 256 + threadIdx.x;
    const float* src; __half* hi; int j;
    if (i < NX4) { src = x; hi = xhi; j = i; }
    else {
        int t = (i - NX4) >> 18;            // which weight (NW4 = 2^18)
        j = (i - NX4) & (NW4 - 1);
        if      (t == 0) { src = Wq; hi = wqhi; }
        else if (t == 1) { src = Wk; hi = wkhi; }
        else if (t == 2) { src = Wv; hi = wvhi; }
        else             { src = Wo; hi = wohi; }
    }
    float4 v = reinterpret_cast<const float4*>(src)[j];
    reinterpret_cast<uint2*>(hi)[j] =
        make_uint2(pack_hf2(v.x, v.y), pack_hf2(v.z, v.w));
}

// ================= shared GEMM machinery (single-term fp16) ===================
// C = Ahi * Bhi^T, fp32 accumulate.
#define BM 128
#define BN 128
#define BK 32
#define KT_ITERS (Dm/BK)              // 32
#define TPITCH 80
#define TILE_BYTES (128*TPITCH)        // 10240
#define STAGE_BYTES (2*TILE_BYTES)     // Ahi|Bhi = 20480
#define NSTAGE 3
#define GEMM_SMEM (NSTAGE*STAGE_BYTES) // 61440  (2 CTAs/SM easily)

struct GemmCore {
    uint32_t sbase;
    int lane, warp_m, warp_n, m0, n0;
    const __half *Ahi, *Bhi;
    int r0a, c0, r1a;

    __device__ __forceinline__ void issue_stage(int stage, int kt) {
        const int kc = kt * BK;
        const uint32_t sb = sbase + stage * STAGE_BYTES;
        cp16(sb + (uint32_t)(r0a * TPITCH + c0 * 16),
             Ahi + (size_t)(m0 + r0a) * Dm + kc + c0 * 8);
        cp16(sb + (uint32_t)(r1a * TPITCH + c0 * 16),
             Ahi + (size_t)(m0 + r1a) * Dm + kc + c0 * 8);
        cp16(sb + TILE_BYTES + (uint32_t)(r0a * TPITCH + c0 * 16),
             Bhi + (size_t)(n0 + r0a) * Dm + kc + c0 * 8);
        cp16(sb + TILE_BYTES + (uint32_t)(r1a * TPITCH + c0 * 16),
             Bhi + (size_t)(n0 + r1a) * Dm + kc + c0 * 8);
        CP_COMMIT();
    }

    __device__ __forceinline__ void mainloop(float acc[4][4][4]) {
        issue_stage(0, 0);
        issue_stage(1, 1);
        for (int kt = 0; kt < KT_ITERS; kt++) {
            if (kt + 1 < KT_ITERS) { CP_WAIT(1); } else { CP_WAIT(0); }
            __syncthreads();
            if (kt + 2 < KT_ITERS) issue_stage((kt + 2) % NSTAGE, kt + 2);

            const uint32_t sb = sbase + (kt % NSTAGE) * STAGE_BYTES;
            const uint32_t sAhi = sb;
            const uint32_t sBhi = sb + TILE_BYTES;

            #pragma unroll
            for (int ks = 0; ks < 2; ks++) {
                const int chunk = ks * 2;
                uint32_t bhi[4][2];
                #pragma unroll
                for (int nt = 0; nt < 4; nt++) {      // direct x2 loads
                    const int brow = warp_n * 32 + nt * 8 + (lane & 7);
                    const uint32_t boff = (uint32_t)(brow * TPITCH + (chunk + ((lane >> 3) & 1)) * 16);
                    ldsm_x2(sBhi + boff, bhi[nt]);
                }
                #pragma unroll
                for (int mt = 0; mt < 4; mt++) {
                    uint32_t ahi[4];
                    const int arow = warp_m * 64 + mt * 16 + (lane & 15);
                    const uint32_t aoff = (uint32_t)(arow * TPITCH + (chunk + (lane >> 4)) * 16);
                    ldsm_x4(sAhi + aoff, ahi);
                    #pragma unroll
                    for (int nt = 0; nt < 4; nt++)
                        mma_f16(acc[mt][nt], ahi, bhi[nt]);
                }
            }
        }
    }
};

// ---- fused QKV GEMM: one launch computes Q, K, V projections -----------------
__global__ void __launch_bounds__(256, 2)
qkv_gemm_kernel(const __half* __restrict__ xhi,
                const __half* __restrict__ wqhi, const __half* __restrict__ wkhi,
                const __half* __restrict__ wvhi,
                __half* __restrict__ qhi, __half* __restrict__ khi,
                __half* __restrict__ vhi, const int* __restrict__ pos)
{
    extern __shared__ char sm[];
    const int tid  = threadIdx.x;
    const int wsel = blockIdx.x >> 3;

    GemmCore gc;
    gc.sbase = smem_u32(sm);
    gc.lane = tid & 31;
    gc.warp_m = (tid >> 5) & 1; gc.warp_n = tid >> 6;
    gc.n0 = (blockIdx.x & 7) * BN;
    gc.m0 = blockIdx.y * BM;
    gc.Ahi = xhi;
    gc.r0a = tid >> 2; gc.c0 = tid & 3; gc.r1a = (tid + 256) >> 2;

    __half* Chi;
    bool rope;
    if (wsel == 0)      { gc.Bhi = wqhi; Chi = qhi; rope = true;  }
    else if (wsel == 1) { gc.Bhi = wkhi; Chi = khi; rope = true;  }
    else                { gc.Bhi = wvhi; Chi = vhi; rope = false; }

    float acc[4][4][4];
    #pragma unroll
    for (int i = 0; i < 4; i++)
        #pragma unroll
        for (int j = 0; j < 4; j++)
            #pragma unroll
            for (int v = 0; v < 4; v++) acc[i][j][v] = 0.f;

    gc.mainloop(acc);

    // epilogue: fused RoPE + fp16 hi store to [B,H,S,Dk]
    const int lane = gc.lane;
    #pragma unroll
    for (int mt = 0; mt < 4; mt++) {
        #pragma unroll
        for (int half = 0; half < 2; half++) {
            const int row = gc.m0 + gc.warp_m * 64 + mt * 16 + (lane >> 2) + half * 8;
            const int b = row >> 11;
            const int s = row & (Sq - 1);
            float p = rope ? (float)pos[row] : 0.f;
            #pragma unroll
            for (int nt = 0; nt < 4; nt++) {
                const int col = gc.n0 + gc.warp_n * 32 + nt * 8 + (lane & 3) * 2;  // even
                float e = acc[mt][nt][half * 2];
                float o = acc[mt][nt][half * 2 + 1];
                if (rope) {
                    const int dk = col & (Dk - 1);
                    const float inv = exp2f((float)dk * (-13.287712379549449f / 64.0f));
                    float sn, cs;
                    sincosf(p * inv, &sn, &cs);
                    const float re = e * cs - o * sn;
                    const float ro = e * sn + o * cs;
                    e = re; o = ro;
                }
                const int h  = col >> 6;
                const int dk = col & (Dk - 1);
                const size_t idx = ((size_t)(b * Hn + h) * Sq + s) * Dk + dk;
                *reinterpret_cast<uint32_t*>(Chi + idx) = pack_hf2(e, o);
            }
        }
    }
}

// ---- output projection GEMM: single-term, fp32 out ----------------------------
__global__ void __launch_bounds__(256, 2)
wo_gemm_kernel(const __half* __restrict__ Ahi, const __half* __restrict__ Bhi,
               float* __restrict__ C)
{
    extern __shared__ char sm[];
    const int tid = threadIdx.x;

    GemmCore gc;
    gc.sbase = smem_u32(sm);
    gc.lane = tid & 31;
    gc.warp_m = (tid >> 5) & 1; gc.warp_n = tid >> 6;
    gc.n0 = blockIdx.x * BN;
    gc.m0 = blockIdx.y * BM;
    gc.Ahi = Ahi; gc.Bhi = Bhi;
    gc.r0a = tid >> 2; gc.c0 = tid & 3; gc.r1a = (tid + 256) >> 2;

    float acc[4][4][4];
    #pragma unroll
    for (int i = 0; i < 4; i++)
        #pragma unroll
        for (int j = 0; j < 4; j++)
            #pragma unroll
            for (int v = 0; v < 4; v++) acc[i][j][v] = 0.f;

    gc.mainloop(acc);

    const int lane = gc.lane;
    #pragma unroll
    for (int mt = 0; mt < 4; mt++) {
        #pragma unroll
        for (int half = 0; half < 2; half++) {
            const int row = gc.m0 + gc.warp_m * 64 + mt * 16 + (lane >> 2) + half * 8;
            #pragma unroll
            for (int nt = 0; nt < 4; nt++) {
                const int col = gc.n0 + gc.warp_n * 32 + nt * 8 + (lane & 3) * 2;
                float* dst = C + (size_t)row * Dm + col;
                *reinterpret_cast<float2*>(dst) =
                    make_float2(acc[mt][nt][half * 2], acc[mt][nt][half * 2 + 1]);
            }
        }
    }
}

// ================= tensor-core causal flash attention (pure fp16) =============
#define ATPITCH 144
#define AT_TILE (64*ATPITCH)          // 9216
#define AT_STAGE (2*AT_TILE)          // Khi|Vhi = 18432
#define AT_NSTAGE 3
#define ATT_SMEM (AT_NSTAGE*AT_STAGE) // 55296  (2 CTAs/SM)

__global__ void __launch_bounds__(256, 2)
attn_mma_kernel(const __half* __restrict__ Qhi,
                const __half* __restrict__ Khi, const __half* __restrict__ Vhi,
                __half* __restrict__ Ohi)
{
    extern __shared__ char sm[];
    const uint32_t sbase = smem_u32(sm);

    const int tid  = threadIdx.x;
    const int lane = tid & 31;
    const int w    = tid >> 5;
    const int bh   = blockIdx.y;
    const int qt   = (int)gridDim.x - 1 - (int)blockIdx.x;   // big tiles first
    const int q0   = qt * 128;
    const int NT   = 2 * qt + 2;                             // key tiles (64 each)

    const size_t kvbase = (size_t)bh * Sq;

    // --- Q fragments (direct gmem gather, once) ------------------------------
    const int r  = q0 + w * 16 + (lane >> 2);
    const int dc = 2 * (lane & 3);
    uint32_t qh[4][4];
    #pragma unroll
    for (int c = 0; c < 4; c++) {
        const int d = c * 16 + dc;
        const size_t i00 = (kvbase + r) * Dk + d;
        const size_t i10 = (kvbase + r + 8) * Dk + d;
        qh[c][0] = *reinterpret_cast<const uint32_t*>(Qhi + i00);
        qh[c][1] = *reinterpret_cast<const uint32_t*>(Qhi + i10);
        qh[c][2] = *reinterpret_cast<const uint32_t*>(Qhi + i00 + 8);
        qh[c][3] = *reinterpret_cast<const uint32_t*>(Qhi + i10 + 8);
    }

    const __half* gkv[2] = {Khi, Vhi};
    auto issue_kv = [&](int stage, int it) {
        const int k0 = it * 64;
        const uint32_t sb = sbase + stage * AT_STAGE;
        #pragma unroll
        for (int i = 0; i < 4; i++) {
            const int c = tid + i * 256;          // 0..1023
            const int t = c >> 9;                 // tile 0..1
            const int rr = (c >> 3) & 63;         // row 0..63
            const int cl = c & 7;                 // 16B chunk 0..7
            cp16(sb + t * AT_TILE + (uint32_t)(rr * ATPITCH + cl * 16),
                 gkv[t] + (kvbase + k0 + rr) * Dk + cl * 8);
        }
        CP_COMMIT();
    };

    float o[8][4];
    #pragma unroll
    for (int nt = 0; nt < 8; nt++)
        #pragma unroll
        for (int j = 0; j < 4; j++) o[nt][j] = 0.f;
    float m0 = -1e30f, m1 = -1e30f, l0 = 0.f, l1 = 0.f;

    issue_kv(0, 0);
    issue_kv(1, 1);

    const float SCL = 0.125f * 1.4426950408889634f;  // scale * log2(e)

    for (int it = 0; it < NT; it++) {
        if (it + 1 < NT) { CP_WAIT(1); } else { CP_WAIT(0); }
        __syncthreads();
        if (it + 2 < NT) issue_kv((it + 2) % AT_NSTAGE, it + 2);  // single-sync pipeline

        const uint32_t sb  = sbase + (it % AT_NSTAGE) * AT_STAGE;
        const uint32_t sKh = sb;
        const uint32_t sVh = sb + AT_TILE;
        const int k0 = it * 64;

        // ---- S = Q K^T -------------------------------------------------------
        float s[8][4];
        #pragma unroll
        for (int nt = 0; nt < 8; nt++)
            #pragma unroll
            for (int j = 0; j < 4; j++) s[nt][j] = 0.f;

        #pragma unroll
        for (int c = 0; c < 4; c++) {
            #pragma unroll
            for (int nt = 0; nt < 8; nt++) {
                const uint32_t boff =
                    (uint32_t)((nt * 8 + (lane & 7)) * ATPITCH + c * 32 + ((lane >> 3) & 1) * 16);
                uint32_t kh[2];
                ldsm_x2(sKh + boff, kh);
                mma_f16(s[nt], qh[c], kh);
            }
        }

        // ---- online softmax (exp2 domain) ------------------------------------
        const bool need_mask = (k0 + 63 > q0);
        float t0 = -1e30f, t1 = -1e30f;
        #pragma unroll
        for (int nt = 0; nt < 8; nt++) {
            #pragma unroll
            for (int j = 0; j < 4; j++) {
                float t = s[nt][j] * SCL;
                if (need_mask) {
                    const int col = k0 + nt * 8 + dc + (j & 1);
                    const int row = (j < 2) ? r : r + 8;
                    if (col > row) t = -1e30f;
                }
                s[nt][j] = t;
                if (j < 2) t0 = fmaxf(t0, t); else t1 = fmaxf(t1, t);
            }
        }
        t0 = fmaxf(t0, __shfl_xor_sync(0xffffffffu, t0, 1));
        t0 = fmaxf(t0, __shfl_xor_sync(0xffffffffu, t0, 2));
        t1 = fmaxf(t1, __shfl_xor_sync(0xffffffffu, t1, 1));
        t1 = fmaxf(t1, __shfl_xor_sync(0xffffffffu, t1, 2));
        const float mn0 = fmaxf(m0, t0), mn1 = fmaxf(m1, t1);
        const float corr0 = exp2f(m0 - mn0), corr1 = exp2f(m1 - mn1);
        m0 = mn0; m1 = mn1;

        float ps0 = 0.f, ps1 = 0.f;
        #pragma unroll
        for (int nt = 0; nt < 8; nt++) {
            s[nt][0] = exp2f(s[nt][0] - m0);
            s[nt][1] = exp2f(s[nt][1] - m0);
            s[nt][2] = exp2f(s[nt][2] - m1);
            s[nt][3] = exp2f(s[nt][3] - m1);
            ps0 += s[nt][0] + s[nt][1];
            ps1 += s[nt][2] + s[nt][3];
        }
        ps0 += __shfl_xor_sync(0xffffffffu, ps0, 1);
        ps0 += __shfl_xor_sync(0xffffffffu, ps0, 2);
        ps1 += __shfl_xor_sync(0xffffffffu, ps1, 1);
        ps1 += __shfl_xor_sync(0xffffffffu, ps1, 2);
        l0 = l0 * corr0 + ps0;
        l1 = l1 * corr1 + ps1;

        #pragma unroll
        for (int nt = 0; nt < 8; nt++) {
            o[nt][0] *= corr0; o[nt][1] *= corr0;
            o[nt][2] *= corr1; o[nt][3] *= corr1;
        }

        // ---- O += P V ----------------------------------------------------------
        #pragma unroll
        for (int u = 0; u < 4; u++) {
            uint32_t aph[4];
            aph[0] = pack_hf2(s[2*u][0],   s[2*u][1]);
            aph[1] = pack_hf2(s[2*u][2],   s[2*u][3]);
            aph[2] = pack_hf2(s[2*u+1][0], s[2*u+1][1]);
            aph[3] = pack_hf2(s[2*u+1][2], s[2*u+1][3]);
            #pragma unroll
            for (int nt = 0; nt < 8; nt++) {
                const uint32_t voff =
                    (uint32_t)((u * 16 + (lane & 15)) * ATPITCH + nt * 16);
                uint32_t vh[2];
                ldsm_x2t(sVh + voff, vh);
                mma_f16(o[nt], aph, vh);
            }
        }
    }

    // ---- epilogue: normalize, fp16 hi store, write [B,S,D] -------------------
    const float inv0 = 1.0f / l0, inv1 = 1.0f / l1;
    const int b = bh >> 4, h = bh & 15;
    const size_t base0 = ((size_t)b * Sq + r) * Dm + h * Dk;
    const size_t base1 = ((size_t)b * Sq + r + 8) * Dm + h * Dk;
    #pragma unroll
    for (int nt = 0; nt < 8; nt++) {
        const int col = nt * 8 + dc;
        *reinterpret_cast<uint32_t*>(Ohi + base0 + col) =
            pack_hf2(o[nt][0] * inv0, o[nt][1] * inv0);
        *reinterpret_cast<uint32_t*>(Ohi + base1 + col) =
            pack_hf2(o[nt][2] * inv1, o[nt][3] * inv1);
    }
}

// ---------------- launch -----------------------------------------------------
extern "C" void kernel_launch(void* const* d_in, const int* in_sizes, int n_in,
                              void* d_out, int out_size)
{
    const float* x   = (const float*)d_in[0];
    const float* Wq  = (const float*)d_in[1];
    const float* Wk  = (const float*)d_in[2];
    const float* Wv  = (const float*)d_in[3];
    const float* Wo  = (const float*)d_in[4];
    const int*   pos = (const int*)d_in[5];
    float* out = (float*)d_out;

    __half *xhi, *wqhi, *wkhi, *wvhi, *wohi;
    __half *qhi, *khi, *vhi, *ohi;
    cudaGetSymbolAddress((void**)&xhi,  g_xhi);
    cudaGetSymbolAddress((void**)&wqhi, g_wqhi);
    cudaGetSymbolAddress((void**)&wkhi, g_wkhi);
    cudaGetSymbolAddress((void**)&wvhi, g_wvhi);
    cudaGetSymbolAddress((void**)&wohi, g_wohi);
    cudaGetSymbolAddress((void**)&qhi,  g_Qhi);
    cudaGetSymbolAddress((void**)&khi,  g_Khi);
    cudaGetSymbolAddress((void**)&vhi,  g_Vhi);
    cudaGetSymbolAddress((void**)&ohi,  g_Ohi);

    cudaFuncSetAttribute(qkv_gemm_kernel,
                         cudaFuncAttributeMaxDynamicSharedMemorySize, GEMM_SMEM);
    cudaFuncSetAttribute(wo_gemm_kernel,
                         cudaFuncAttributeMaxDynamicSharedMemorySize, GEMM_SMEM);
    cudaFuncSetAttribute(attn_mma_kernel,
                         cudaFuncAttributeMaxDynamicSharedMemorySize, ATT_SMEM);

    // 1) one fused split pass (all tensors -> fp16 hi)
    const int ntot4 = NX4 + 4 * NW4;   // 2097152
    split_all_kernel<<<ntot4 / 256, 256>>>(x, Wq, Wk, Wv, Wo,
                                           xhi, wqhi, wkhi, wvhi, wohi);

    // 2) fused QKV projection (+RoPE on Q,K), single-term
    dim3 qkvgrid(3 * (Dm / BN), Mrows / BM);   // (24, 32)
    qkv_gemm_kernel<<<qkvgrid, 256, GEMM_SMEM>>>(xhi, wqhi, wkhi, wvhi,
                                                 qhi, khi, vhi, pos);

    // 3) causal flash attention
    dim3 agrid(Sq / 128, Bsz * Hn);            // (16, 32)
    attn_mma_kernel<<<agrid, 256, ATT_SMEM>>>(qhi, khi, vhi, ohi);

    // 4) output projection (single-term)
    dim3 wogrid(Dm / BN, Mrows / BM);          // (8, 32)
    wo_gemm_kernel<<<wogrid, 256, GEMM_SMEM>>>(ohi, wohi, out);
}

// round 13
// speedup vs baseline: 6.9836x; 1.0062x over previous
#include <cuda_runtime.h>
#include <cuda_fp16.h>
#include <math.h>
#include <stdint.h>

// Problem constants (fixed by this dataset instance)
#define Bsz 2
#define Sq  2048
#define Dm  1024
#define Hn  16
#define Dk  64
#define Mrows (Bsz*Sq)   // 4096

// ---------------- scratch ----------------------------------------------------
__device__ __half g_xhi[Mrows*Dm];                     // x: fp16 hi only
__device__ __half g_wqhi[Dm*Dm];                       // weights: fp16 hi only
__device__ __half g_wkhi[Dm*Dm];
__device__ __half g_wvhi[Dm*Dm];
__device__ __half g_wohi[Dm*Dm];
__device__ __half g_Qhi[Mrows*Dm];                     // [B,H,S,Dk] fp16 hi
__device__ __half g_Khi[Mrows*Dm];
__device__ __half g_Vhi[Mrows*Dm];
__device__ __half g_Ohi[Mrows*Dm];                     // [B,S,D] fp16 hi
__device__ float2 g_rope[Mrows*(Dk/2)];                // [row, dk/2] = {cos, sin}

// ================= small PTX wrappers (portable, compute_103-safe) ===========
__device__ __forceinline__ uint32_t smem_u32(const void* p) {
    uint32_t a;
    asm("{ .reg .u64 t; cvta.to.shared.u64 t, %1; cvt.u32.u64 %0, t; }"
        : "=r"(a) : "l"(p));
    return a;
}
__device__ __forceinline__ void ldsm_x4(uint32_t addr, uint32_t r[4]) {
    asm volatile("ldmatrix.sync.aligned.m8n8.x4.shared.b16 {%0,%1,%2,%3}, [%4];"
                 : "=r"(r[0]), "=r"(r[1]), "=r"(r[2]), "=r"(r[3]) : "r"(addr));
}
__device__ __forceinline__ void ldsm_x2(uint32_t addr, uint32_t r[2]) {
    asm volatile("ldmatrix.sync.aligned.m8n8.x2.shared.b16 {%0,%1}, [%2];"
                 : "=r"(r[0]), "=r"(r[1]) : "r"(addr));
}
__device__ __forceinline__ void ldsm_x2t(uint32_t addr, uint32_t r[2]) {
    asm volatile("ldmatrix.sync.aligned.m8n8.x2.trans.shared.b16 {%0,%1}, [%2];"
                 : "=r"(r[0]), "=r"(r[1]) : "r"(addr));
}
__device__ __forceinline__ void mma_f16(float c[4], const uint32_t a[4],
                                        const uint32_t b[2]) {
    asm volatile(
        "mma.sync.aligned.m16n8k16.row.col.f32.f16.f16.f32 "
        "{%0,%1,%2,%3}, {%4,%5,%6,%7}, {%8,%9}, {%0,%1,%2,%3};"
        : "+f"(c[0]), "+f"(c[1]), "+f"(c[2]), "+f"(c[3])
        : "r"(a[0]), "r"(a[1]), "r"(a[2]), "r"(a[3]), "r"(b[0]), "r"(b[1]));
}
__device__ __forceinline__ void cp16(uint32_t smem_addr, const void* gptr) {
    asm volatile("cp.async.cg.shared.global [%0], [%1], 16;"
                 :: "r"(smem_addr), "l"(gptr) : "memory");
}
#define CP_COMMIT() asm volatile("cp.async.commit_group;" ::: "memory")
#define CP_WAIT(n)  asm volatile("cp.async.wait_group %0;" :: "n"(n) : "memory")

__device__ __forceinline__ uint32_t pack_hf2(float x, float y) {
    __half2 t = __floats2half2_rn(x, y);
    return *reinterpret_cast<uint32_t*>(&t);
}

// ================= fused split pass + RoPE table ==============================
// CTAs [0, SPLIT_CTAS): convert x + 4 weights to fp16 (4 float4 per thread, MLP=4)
// CTAs [SPLIT_CTAS, SPLIT_CTAS+ROPE_CTAS): fill cos/sin table per (row, dk/2)
#define NX4 (Mrows*Dm/4)    // 1048576
#define NW4 (Dm*Dm/4)       // 262144
#define NTOT4 (NX4 + 4*NW4) // 2097152
#define SPLIT_STRIDE (NTOT4/4)          // 524288 threads
#define SPLIT_CTAS (SPLIT_STRIDE/256)   // 2048
#define ROPE_N (Mrows*(Dk/2))           // 131072
#define ROPE_CTAS (ROPE_N/256)          // 512

__global__ void __launch_bounds__(256)
split_all_kernel(const float* __restrict__ x,  const float* __restrict__ Wq,
                 const float* __restrict__ Wk, const float* __restrict__ Wv,
                 const float* __restrict__ Wo, const int* __restrict__ pos,
                 __half* __restrict__ xhi,
                 __half* __restrict__ wqhi, __half* __restrict__ wkhi,
                 __half* __restrict__ wvhi, __half* __restrict__ wohi,
                 float2* __restrict__ ropeTab)
{
    const int bid = blockIdx.x;
    if (bid < SPLIT_CTAS) {
        #pragma unroll
        for (int k = 0; k < 4; k++) {
            int i = bid * 256 + threadIdx.x + k * SPLIT_STRIDE;
            const float* src; __half* hi; int j;
            if (i < NX4) { src = x; hi = xhi; j = i; }
            else {
                int t = (i - NX4) >> 18;            // which weight (NW4 = 2^18)
                j = (i - NX4) & (NW4 - 1);
                if      (t == 0) { src = Wq; hi = wqhi; }
                else if (t == 1) { src = Wk; hi = wkhi; }
                else if (t == 2) { src = Wv; hi = wvhi; }
                else             { src = Wo; hi = wohi; }
            }
            float4 v = reinterpret_cast<const float4*>(src)[j];
            reinterpret_cast<uint2*>(hi)[j] =
                make_uint2(pack_hf2(v.x, v.y), pack_hf2(v.z, v.w));
        }
    } else {
        // RoPE table: gid -> (row m, dk-half)
        const int gid = (bid - SPLIT_CTAS) * 256 + threadIdx.x;   // 0..131071
        const int m   = gid >> 5;
        const int dkh = gid & 31;
        const float p = (float)pos[m];
        const float inv = exp2f((float)(2 * dkh) * (-13.287712379549449f / 64.0f));
        float sn, cs;
        sincosf(p * inv, &sn, &cs);
        ropeTab[gid] = make_float2(cs, sn);
    }
}

// ================= shared GEMM machinery (single-term fp16) ===================
// C = Ahi * Bhi^T, fp32 accumulate.
#define BM 128
#define BN 128
#define BK 32
#define KT_ITERS (Dm/BK)              // 32
#define TPITCH 80
#define TILE_BYTES (128*TPITCH)        // 10240
#define STAGE_BYTES (2*TILE_BYTES)     // Ahi|Bhi = 20480
#define NSTAGE 4
#define GEMM_SMEM (NSTAGE*STAGE_BYTES) // 81920  (2 CTAs/SM)

struct GemmCore {
    uint32_t sbase;
    int lane, warp_m, warp_n, m0, n0;
    const __half *Ahi, *Bhi;
    int r0a, c0, r1a;

    __device__ __forceinline__ void issue_stage(int stage, int kt) {
        const int kc = kt * BK;
        const uint32_t sb = sbase + stage * STAGE_BYTES;
        cp16(sb + (uint32_t)(r0a * TPITCH + c0 * 16),
             Ahi + (size_t)(m0 + r0a) * Dm + kc + c0 * 8);
        cp16(sb + (uint32_t)(r1a * TPITCH + c0 * 16),
             Ahi + (size_t)(m0 + r1a) * Dm + kc + c0 * 8);
        cp16(sb + TILE_BYTES + (uint32_t)(r0a * TPITCH + c0 * 16),
             Bhi + (size_t)(n0 + r0a) * Dm + kc + c0 * 8);
        cp16(sb + TILE_BYTES + (uint32_t)(r1a * TPITCH + c0 * 16),
             Bhi + (size_t)(n0 + r1a) * Dm + kc + c0 * 8);
        CP_COMMIT();
    }

    __device__ __forceinline__ void mainloop(float acc[4][4][4]) {
        issue_stage(0, 0);
        issue_stage(1, 1);
        issue_stage(2, 2);
        for (int kt = 0; kt < KT_ITERS; kt++) {
            if (kt + 2 < KT_ITERS)      { CP_WAIT(2); }
            else if (kt + 1 < KT_ITERS) { CP_WAIT(1); }
            else                        { CP_WAIT(0); }
            __syncthreads();
            if (kt + 3 < KT_ITERS) issue_stage((kt + 3) & 3, kt + 3);

            const uint32_t sb = sbase + (kt & 3) * STAGE_BYTES;
            const uint32_t sAhi = sb;
            const uint32_t sBhi = sb + TILE_BYTES;

            #pragma unroll
            for (int ks = 0; ks < 2; ks++) {
                const int chunk = ks * 2;
                uint32_t bhi[4][2];
                #pragma unroll
                for (int nt = 0; nt < 4; nt++) {      // direct x2 loads
                    const int brow = warp_n * 32 + nt * 8 + (lane & 7);
                    const uint32_t boff = (uint32_t)(brow * TPITCH + (chunk + ((lane >> 3) & 1)) * 16);
                    ldsm_x2(sBhi + boff, bhi[nt]);
                }
                #pragma unroll
                for (int mt = 0; mt < 4; mt++) {
                    uint32_t ahi[4];
                    const int arow = warp_m * 64 + mt * 16 + (lane & 15);
                    const uint32_t aoff = (uint32_t)(arow * TPITCH + (chunk + (lane >> 4)) * 16);
                    ldsm_x4(sAhi + aoff, ahi);
                    #pragma unroll
                    for (int nt = 0; nt < 4; nt++)
                        mma_f16(acc[mt][nt], ahi, bhi[nt]);
                }
            }
        }
    }
};

// ---- fused QKV GEMM: one launch computes Q, K, V projections -----------------
__global__ void __launch_bounds__(256, 2)
qkv_gemm_kernel(const __half* __restrict__ xhi,
                const __half* __restrict__ wqhi, const __half* __restrict__ wkhi,
                const __half* __restrict__ wvhi,
                __half* __restrict__ qhi, __half* __restrict__ khi,
                __half* __restrict__ vhi, const float2* __restrict__ ropeTab)
{
    extern __shared__ char sm[];
    const int tid  = threadIdx.x;
    const int wsel = blockIdx.x >> 3;

    GemmCore gc;
    gc.sbase = smem_u32(sm);
    gc.lane = tid & 31;
    gc.warp_m = (tid >> 5) & 1; gc.warp_n = tid >> 6;
    gc.n0 = (blockIdx.x & 7) * BN;
    gc.m0 = blockIdx.y * BM;
    gc.Ahi = xhi;
    gc.r0a = tid >> 2; gc.c0 = tid & 3; gc.r1a = (tid + 256) >> 2;

    __half* Chi;
    bool rope;
    if (wsel == 0)      { gc.Bhi = wqhi; Chi = qhi; rope = true;  }
    else if (wsel == 1) { gc.Bhi = wkhi; Chi = khi; rope = true;  }
    else                { gc.Bhi = wvhi; Chi = vhi; rope = false; }

    float acc[4][4][4];
    #pragma unroll
    for (int i = 0; i < 4; i++)
        #pragma unroll
        for (int j = 0; j < 4; j++)
            #pragma unroll
            for (int v = 0; v < 4; v++) acc[i][j][v] = 0.f;

    gc.mainloop(acc);

    // epilogue: fused RoPE (table lookup) + fp16 hi store to [B,H,S,Dk]
    const int lane = gc.lane;
    #pragma unroll
    for (int mt = 0; mt < 4; mt++) {
        #pragma unroll
        for (int half = 0; half < 2; half++) {
            const int row = gc.m0 + gc.warp_m * 64 + mt * 16 + (lane >> 2) + half * 8;
            const int b = row >> 11;
            const int s = row & (Sq - 1);
            #pragma unroll
            for (int nt = 0; nt < 4; nt++) {
                const int col = gc.n0 + gc.warp_n * 32 + nt * 8 + (lane & 3) * 2;  // even
                float e = acc[mt][nt][half * 2];
                float o = acc[mt][nt][half * 2 + 1];
                if (rope) {
                    const int dkh = (col & (Dk - 1)) >> 1;
                    const float2 cssn = ropeTab[row * (Dk / 2) + dkh];
                    const float re = e * cssn.x - o * cssn.y;
                    const float ro = e * cssn.y + o * cssn.x;
                    e = re; o = ro;
                }
                const int h  = col >> 6;
                const int dk = col & (Dk - 1);
                const size_t idx = ((size_t)(b * Hn + h) * Sq + s) * Dk + dk;
                *reinterpret_cast<uint32_t*>(Chi + idx) = pack_hf2(e, o);
            }
        }
    }
}

// ---- output projection GEMM: single-term, fp32 out ----------------------------
__global__ void __launch_bounds__(256, 2)
wo_gemm_kernel(const __half* __restrict__ Ahi, const __half* __restrict__ Bhi,
               float* __restrict__ C)
{
    extern __shared__ char sm[];
    const int tid = threadIdx.x;

    GemmCore gc;
    gc.sbase = smem_u32(sm);
    gc.lane = tid & 31;
    gc.warp_m = (tid >> 5) & 1; gc.warp_n = tid >> 6;
    gc.n0 = blockIdx.x * BN;
    gc.m0 = blockIdx.y * BM;
    gc.Ahi = Ahi; gc.Bhi = Bhi;
    gc.r0a = tid >> 2; gc.c0 = tid & 3; gc.r1a = (tid + 256) >> 2;

    float acc[4][4][4];
    #pragma unroll
    for (int i = 0; i < 4; i++)
        #pragma unroll
        for (int j = 0; j < 4; j++)
            #pragma unroll
            for (int v = 0; v < 4; v++) acc[i][j][v] = 0.f;

    gc.mainloop(acc);

    const int lane = gc.lane;
    #pragma unroll
    for (int mt = 0; mt < 4; mt++) {
        #pragma unroll
        for (int half = 0; half < 2; half++) {
            const int row = gc.m0 + gc.warp_m * 64 + mt * 16 + (lane >> 2) + half * 8;
            #pragma unroll
            for (int nt = 0; nt < 4; nt++) {
                const int col = gc.n0 + gc.warp_n * 32 + nt * 8 + (lane & 3) * 2;
                float* dst = C + (size_t)row * Dm + col;
                *reinterpret_cast<float2*>(dst) =
                    make_float2(acc[mt][nt][half * 2], acc[mt][nt][half * 2 + 1]);
            }
        }
    }
}

// ================= tensor-core causal flash attention (pure fp16) =============
#define ATPITCH 144
#define AT_TILE (64*ATPITCH)          // 9216
#define AT_STAGE (2*AT_TILE)          // Khi|Vhi = 18432
#define AT_NSTAGE 3
#define ATT_SMEM (AT_NSTAGE*AT_STAGE) // 55296  (2 CTAs/SM)

__global__ void __launch_bounds__(256, 2)
attn_mma_kernel(const __half* __restrict__ Qhi,
                const __half* __restrict__ Khi, const __half* __restrict__ Vhi,
                __half* __restrict__ Ohi)
{
    extern __shared__ char sm[];
    const uint32_t sbase = smem_u32(sm);

    const int tid  = threadIdx.x;
    const int lane = tid & 31;
    const int w    = tid >> 5;
    const int bh   = blockIdx.y;
    const int qt   = (int)gridDim.x - 1 - (int)blockIdx.x;   // big tiles first
    const int q0   = qt * 128;
    const int NT   = 2 * qt + 2;                             // key tiles (64 each)

    const size_t kvbase = (size_t)bh * Sq;

    // --- Q fragments (direct gmem gather, once) ------------------------------
    const int r  = q0 + w * 16 + (lane >> 2);
    const int dc = 2 * (lane & 3);
    uint32_t qh[4][4];
    #pragma unroll
    for (int c = 0; c < 4; c++) {
        const int d = c * 16 + dc;
        const size_t i00 = (kvbase + r) * Dk + d;
        const size_t i10 = (kvbase + r + 8) * Dk + d;
        qh[c][0] = *reinterpret_cast<const uint32_t*>(Qhi + i00);
        qh[c][1] = *reinterpret_cast<const uint32_t*>(Qhi + i10);
        qh[c][2] = *reinterpret_cast<const uint32_t*>(Qhi + i00 + 8);
        qh[c][3] = *reinterpret_cast<const uint32_t*>(Qhi + i10 + 8);
    }

    const __half* gkv[2] = {Khi, Vhi};
    auto issue_kv = [&](int stage, int it) {
        const int k0 = it * 64;
        const uint32_t sb = sbase + stage * AT_STAGE;
        #pragma unroll
        for (int i = 0; i < 4; i++) {
            const int c = tid + i * 256;          // 0..1023
            const int t = c >> 9;                 // tile 0..1
            const int rr = (c >> 3) & 63;         // row 0..63
            const int cl = c & 7;                 // 16B chunk 0..7
            cp16(sb + t * AT_TILE + (uint32_t)(rr * ATPITCH + cl * 16),
                 gkv[t] + (kvbase + k0 + rr) * Dk + cl * 8);
        }
        CP_COMMIT();
    };

    float o[8][4];
    #pragma unroll
    for (int nt = 0; nt < 8; nt++)
        #pragma unroll
        for (int j = 0; j < 4; j++) o[nt][j] = 0.f;
    float m0 = -1e30f, m1 = -1e30f, l0 = 0.f, l1 = 0.f;

    issue_kv(0, 0);
    issue_kv(1, 1);

    const float SCL = 0.125f * 1.4426950408889634f;  // scale * log2(e)

    for (int it = 0; it < NT; it++) {
        if (it + 1 < NT) { CP_WAIT(1); } else { CP_WAIT(0); }
        __syncthreads();
        if (it + 2 < NT) issue_kv((it + 2) % AT_NSTAGE, it + 2);  // single-sync pipeline

        const uint32_t sb  = sbase + (it % AT_NSTAGE) * AT_STAGE;
        const uint32_t sKh = sb;
        const uint32_t sVh = sb + AT_TILE;
        const int k0 = it * 64;

        // ---- S = Q K^T -------------------------------------------------------
        float s[8][4];
        #pragma unroll
        for (int nt = 0; nt < 8; nt++)
            #pragma unroll
            for (int j = 0; j < 4; j++) s[nt][j] = 0.f;

        #pragma unroll
        for (int c = 0; c < 4; c++) {
            #pragma unroll
            for (int nt = 0; nt < 8; nt++) {
                const uint32_t boff =
                    (uint32_t)((nt * 8 + (lane & 7)) * ATPITCH + c * 32 + ((lane >> 3) & 1) * 16);
                uint32_t kh[2];
                ldsm_x2(sKh + boff, kh);
                mma_f16(s[nt], qh[c], kh);
            }
        }

        // ---- online softmax (exp2 domain) ------------------------------------
        const bool need_mask = (k0 + 63 > q0);
        float t0 = -1e30f, t1 = -1e30f;
        #pragma unroll
        for (int nt = 0; nt < 8; nt++) {
            #pragma unroll
            for (int j = 0; j < 4; j++) {
                float t = s[nt][j] * SCL;
                if (need_mask) {
                    const int col = k0 + nt * 8 + dc + (j & 1);
                    const int row = (j < 2) ? r : r + 8;
                    if (col > row) t = -1e30f;
                }
                s[nt][j] = t;
                if (j < 2) t0 = fmaxf(t0, t); else t1 = fmaxf(t1, t);
            }
        }
        t0 = fmaxf(t0, __shfl_xor_sync(0xffffffffu, t0, 1));
        t0 = fmaxf(t0, __shfl_xor_sync(0xffffffffu, t0, 2));
        t1 = fmaxf(t1, __shfl_xor_sync(0xffffffffu, t1, 1));
        t1 = fmaxf(t1, __shfl_xor_sync(0xffffffffu, t1, 2));
        const float mn0 = fmaxf(m0, t0), mn1 = fmaxf(m1, t1);
        const float corr0 = exp2f(m0 - mn0), corr1 = exp2f(m1 - mn1);
        m0 = mn0; m1 = mn1;

        float ps0 = 0.f, ps1 = 0.f;
        #pragma unroll
        for (int nt = 0; nt < 8; nt++) {
            s[nt][0] = exp2f(s[nt][0] - m0);
            s[nt][1] = exp2f(s[nt][1] - m0);
            s[nt][2] = exp2f(s[nt][2] - m1);
            s[nt][3] = exp2f(s[nt][3] - m1);
            ps0 += s[nt][0] + s[nt][1];
            ps1 += s[nt][2] + s[nt][3];
        }
        ps0 += __shfl_xor_sync(0xffffffffu, ps0, 1);
        ps0 += __shfl_xor_sync(0xffffffffu, ps0, 2);
        ps1 += __shfl_xor_sync(0xffffffffu, ps1, 1);
        ps1 += __shfl_xor_sync(0xffffffffu, ps1, 2);
        l0 = l0 * corr0 + ps0;
        l1 = l1 * corr1 + ps1;

        #pragma unroll
        for (int nt = 0; nt < 8; nt++) {
            o[nt][0] *= corr0; o[nt][1] *= corr0;
            o[nt][2] *= corr1; o[nt][3] *= corr1;
        }

        // ---- O += P V ----------------------------------------------------------
        #pragma unroll
        for (int u = 0; u < 4; u++) {
            uint32_t aph[4];
            aph[0] = pack_hf2(s[2*u][0],   s[2*u][1]);
            aph[1] = pack_hf2(s[2*u][2],   s[2*u][3]);
            aph[2] = pack_hf2(s[2*u+1][0], s[2*u+1][1]);
            aph[3] = pack_hf2(s[2*u+1][2], s[2*u+1][3]);
            #pragma unroll
            for (int nt = 0; nt < 8; nt++) {
                const uint32_t voff =
                    (uint32_t)((u * 16 + (lane & 15)) * ATPITCH + nt * 16);
                uint32_t vh[2];
                ldsm_x2t(sVh + voff, vh);
                mma_f16(o[nt], aph, vh);
            }
        }
    }

    // ---- epilogue: normalize, fp16 hi store, write [B,S,D] -------------------
    const float inv0 = 1.0f / l0, inv1 = 1.0f / l1;
    const int b = bh >> 4, h = bh & 15;
    const size_t base0 = ((size_t)b * Sq + r) * Dm + h * Dk;
    const size_t base1 = ((size_t)b * Sq + r + 8) * Dm + h * Dk;
    #pragma unroll
    for (int nt = 0; nt < 8; nt++) {
        const int col = nt * 8 + dc;
        *reinterpret_cast<uint32_t*>(Ohi + base0 + col) =
            pack_hf2(o[nt][0] * inv0, o[nt][1] * inv0);
        *reinterpret_cast<uint32_t*>(Ohi + base1 + col) =
            pack_hf2(o[nt][2] * inv1, o[nt][3] * inv1);
    }
}

// ---------------- launch -----------------------------------------------------
extern "C" void kernel_launch(void* const* d_in, const int* in_sizes, int n_in,
                              void* d_out, int out_size)
{
    const float* x   = (const float*)d_in[0];
    const float* Wq  = (const float*)d_in[1];
    const float* Wk  = (const float*)d_in[2];
    const float* Wv  = (const float*)d_in[3];
    const float* Wo  = (const float*)d_in[4];
    const int*   pos = (const int*)d_in[5];
    float* out = (float*)d_out;

    __half *xhi, *wqhi, *wkhi, *wvhi, *wohi;
    __half *qhi, *khi, *vhi, *ohi;
    float2* ropeTab;
    cudaGetSymbolAddress((void**)&xhi,  g_xhi);
    cudaGetSymbolAddress((void**)&wqhi, g_wqhi);
    cudaGetSymbolAddress((void**)&wkhi, g_wkhi);
    cudaGetSymbolAddress((void**)&wvhi, g_wvhi);
    cudaGetSymbolAddress((void**)&wohi, g_wohi);
    cudaGetSymbolAddress((void**)&qhi,  g_Qhi);
    cudaGetSymbolAddress((void**)&khi,  g_Khi);
    cudaGetSymbolAddress((void**)&vhi,  g_Vhi);
    cudaGetSymbolAddress((void**)&ohi,  g_Ohi);
    cudaGetSymbolAddress((void**)&ropeTab, g_rope);

    cudaFuncSetAttribute(qkv_gemm_kernel,
                         cudaFuncAttributeMaxDynamicSharedMemorySize, GEMM_SMEM);
    cudaFuncSetAttribute(wo_gemm_kernel,
                         cudaFuncAttributeMaxDynamicSharedMemorySize, GEMM_SMEM);
    cudaFuncSetAttribute(attn_mma_kernel,
                         cudaFuncAttributeMaxDynamicSharedMemorySize, ATT_SMEM);

    // 1) fused split pass (fp16 conversion, MLP=4) + RoPE cos/sin table
    split_all_kernel<<<SPLIT_CTAS + ROPE_CTAS, 256>>>(x, Wq, Wk, Wv, Wo, pos,
                                                      xhi, wqhi, wkhi, wvhi, wohi,
                                                      ropeTab);

    // 2) fused QKV projection (+RoPE table on Q,K), single-term
    dim3 qkvgrid(3 * (Dm / BN), Mrows / BM);   // (24, 32)
    qkv_gemm_kernel<<<qkvgrid, 256, GEMM_SMEM>>>(xhi, wqhi, wkhi, wvhi,
                                                 qhi, khi, vhi, ropeTab);

    // 3) causal flash attention
    dim3 agrid(Sq / 128, Bsz * Hn);            // (16, 32)
    attn_mma_kernel<<<agrid, 256, ATT_SMEM>>>(qhi, khi, vhi, ohi);

    // 4) output projection (single-term)
    dim3 wogrid(Dm / BN, Mrows / BM);          // (8, 32)
    wo_gemm_kernel<<<wogrid, 256, GEMM_SMEM>>>(ohi, wohi, out);
}